// round 1
// baseline (speedup 1.0000x reference)
#include <cuda_runtime.h>

#define BB 4
#define CC 256
#define CI 128
#define NN 4096
#define BN_EPS 1e-5f

// ---------------- scratch (no allocations allowed) ----------------
__device__ float g_TH[BB * NN * CI];   // theta proj  [b][n][d]
__device__ float g_PH[BB * NN * CI];   // phi  proj   [b][m][d]  (keys)
__device__ float g_G [BB * NN * CI];   // g    proj   [b][m][d]  (values)
__device__ float g_Y [BB * NN * CI];   // attention out [b][n][d]
__device__ float g_WY[BB * CC * NN];   // W conv out   [b][o][n]
__device__ float g_mean[CC];
__device__ float g_rstd[CC];

// ---------------- kernel 1: fused 3-way channel projections ----------------
// out[b][n][o] = sum_c w[o][c] * x[b][c*NN + n] + bias[o]
// tile: 64 n x 128 o, 256 threads, per-thread 4x8, K-chunk 32
__global__ void __launch_bounds__(256) proj_kernel(
    const float* __restrict__ x,
    const float* __restrict__ gw, const float* __restrict__ gb,
    const float* __restrict__ tw, const float* __restrict__ tb,
    const float* __restrict__ pw, const float* __restrict__ pb)
{
    __shared__ float xs[32 * 64];    // [cc][nl]
    __shared__ float ws[32 * 129];   // [cc][o], padded

    const int b  = blockIdx.y;
    const int n0 = blockIdx.x * 64;
    const int which = blockIdx.z;

    const float* w; const float* bias; float* out;
    if (which == 0)      { w = gw; bias = gb; out = g_G;  }
    else if (which == 1) { w = tw; bias = tb; out = g_TH; }
    else                 { w = pw; bias = pb; out = g_PH; }
    out += (size_t)b * NN * CI;
    const float* xb = x + (size_t)b * CC * NN;

    const int tid = threadIdx.x;
    const int tx = tid & 15, ty = tid >> 4;

    float acc[4][8];
#pragma unroll
    for (int i = 0; i < 4; i++)
#pragma unroll
        for (int j = 0; j < 8; j++) acc[i][j] = 0.f;

    for (int c0 = 0; c0 < CC; c0 += 32) {
        __syncthreads();
#pragma unroll
        for (int r = 0; r < 8; r++) {               // 2048 elems of x
            int idx = tid + r * 256;
            int cc = idx >> 6, nl = idx & 63;
            xs[cc * 64 + nl] = xb[(c0 + cc) * NN + n0 + nl];
        }
#pragma unroll
        for (int r = 0; r < 16; r++) {              // 4096 elems of w (transposed)
            int idx = tid + r * 256;
            int o = idx >> 5, cc = idx & 31;
            ws[cc * 129 + o] = w[o * CC + c0 + cc];
        }
        __syncthreads();
#pragma unroll 8
        for (int cc = 0; cc < 32; cc++) {
            float a[4], bv[8];
#pragma unroll
            for (int i = 0; i < 4; i++) a[i] = xs[cc * 64 + ty + 16 * i];
#pragma unroll
            for (int j = 0; j < 8; j++) bv[j] = ws[cc * 129 + tx + 16 * j];
#pragma unroll
            for (int i = 0; i < 4; i++)
#pragma unroll
                for (int j = 0; j < 8; j++) acc[i][j] += a[i] * bv[j];
        }
    }

#pragma unroll
    for (int j = 0; j < 8; j++) {
        float bs = bias[tx + 16 * j];
#pragma unroll
        for (int i = 0; i < 4; i++)
            out[(size_t)(n0 + ty + 16 * i) * CI + tx + 16 * j] = acc[i][j] + bs;
    }
}

// ---------------- kernel 2: fused flash attention ----------------
// per block: 64 query rows, full d=128, loop key tiles of 64
#define SQ_OFF 0
#define SK_OFF (128 * 65)
#define SG_OFF (SK_OFF + 128 * 65)
#define SS_OFF (SG_OFF + 64 * 128)
#define SM_OFF (SS_OFF + 64 * 65)
#define SL_OFF (SM_OFF + 64)
#define SC_OFF (SL_OFF + 64)
#define ATTN_SMEM_FLOATS (SC_OFF + 64)
#define ATTN_SMEM_BYTES (ATTN_SMEM_FLOATS * 4)

extern __shared__ float sm_attn[];

__global__ void __launch_bounds__(256) attn_kernel()
{
    float* sQ = sm_attn + SQ_OFF;   // [d][i] stride 65
    float* sK = sm_attn + SK_OFF;   // [d][j] stride 65
    float* sG = sm_attn + SG_OFF;   // [j][d] stride 128
    float* sS = sm_attn + SS_OFF;   // [i][j] stride 65
    float* sM = sm_attn + SM_OFF;
    float* sL = sm_attn + SL_OFF;
    float* sC = sm_attn + SC_OFF;

    const int b  = blockIdx.y;
    const int n0 = blockIdx.x * 64;
    const float* Q = g_TH + (size_t)b * NN * CI;
    const float* K = g_PH + (size_t)b * NN * CI;
    const float* G = g_G  + (size_t)b * NN * CI;

    const int tid = threadIdx.x;
    const int tx = tid & 15, ty = tid >> 4;

    // load Q tile transposed (coalesced LDG, conflict-free STS via stride 65)
#pragma unroll
    for (int r = 0; r < 32; r++) {
        int idx = tid + r * 256;
        int i = idx >> 7, d = idx & 127;
        sQ[d * 65 + i] = Q[(size_t)(n0 + i) * CI + d];
    }
    if (tid < 64) { sM[tid] = -1e30f; sL[tid] = 0.f; }

    float acc[4][8];
#pragma unroll
    for (int i = 0; i < 4; i++)
#pragma unroll
        for (int j = 0; j < 8; j++) acc[i][j] = 0.f;

    for (int k0 = 0; k0 < NN; k0 += 64) {
        // load K (transposed) + G (direct) tiles
#pragma unroll
        for (int r = 0; r < 32; r++) {
            int idx = tid + r * 256;
            int j = idx >> 7, d = idx & 127;
            float kv = K[(size_t)(k0 + j) * CI + d];
            float gv = G[(size_t)(k0 + j) * CI + d];
            sK[d * 65 + j] = kv;
            sG[j * 128 + d] = gv;
        }
        __syncthreads();

        // phase 1: S = Q @ K^T  (per thread 4x4)
        float s[4][4];
#pragma unroll
        for (int i = 0; i < 4; i++)
#pragma unroll
            for (int j = 0; j < 4; j++) s[i][j] = 0.f;

#pragma unroll 8
        for (int k = 0; k < 128; k++) {
            float a[4], bv[4];
#pragma unroll
            for (int i = 0; i < 4; i++) a[i] = sQ[k * 65 + ty + 16 * i];
#pragma unroll
            for (int j = 0; j < 4; j++) bv[j] = sK[k * 65 + tx + 16 * j];
#pragma unroll
            for (int i = 0; i < 4; i++)
#pragma unroll
                for (int j = 0; j < 4; j++) s[i][j] += a[i] * bv[j];
        }

        // online softmax (rows i = ty + 16*ii live in one 16-lane half-warp group)
#pragma unroll
        for (int ii = 0; ii < 4; ii++) {
            const int i = ty + 16 * ii;
            float m = fmaxf(fmaxf(s[ii][0], s[ii][1]), fmaxf(s[ii][2], s[ii][3]));
#pragma unroll
            for (int off = 8; off >= 1; off >>= 1)
                m = fmaxf(m, __shfl_xor_sync(0xffffffffu, m, off));
            float mo = sM[i];
            float mn = fmaxf(mo, m);
            float sum = 0.f;
#pragma unroll
            for (int jj = 0; jj < 4; jj++) {
                float p = __expf(s[ii][jj] - mn);
                s[ii][jj] = p;
                sum += p;
            }
#pragma unroll
            for (int off = 8; off >= 1; off >>= 1)
                sum += __shfl_xor_sync(0xffffffffu, sum, off);
            float corr = __expf(mo - mn);
            if (tx == 0) {
                sM[i] = mn;
                sC[i] = corr;
                sL[i] = sL[i] * corr + sum;
            }
#pragma unroll
            for (int jj = 0; jj < 4; jj++)
                sS[i * 65 + tx + 16 * jj] = s[ii][jj];
        }
        __syncthreads();

        // phase 3: acc = acc*corr + P @ G  (per thread 4x8)
#pragma unroll
        for (int ii = 0; ii < 4; ii++) {
            float c = sC[ty + 16 * ii];
#pragma unroll
            for (int id = 0; id < 8; id++) acc[ii][id] *= c;
        }
#pragma unroll 4
        for (int j = 0; j < 64; j++) {
            float p[4], gv[8];
#pragma unroll
            for (int ii = 0; ii < 4; ii++) p[ii] = sS[(ty + 16 * ii) * 65 + j];
#pragma unroll
            for (int id = 0; id < 8; id++) gv[id] = sG[j * 128 + tx + 16 * id];
#pragma unroll
            for (int ii = 0; ii < 4; ii++)
#pragma unroll
                for (int id = 0; id < 8; id++) acc[ii][id] += p[ii] * gv[id];
        }
        __syncthreads();
    }

    // finalize: divide by l, write y
#pragma unroll
    for (int ii = 0; ii < 4; ii++) {
        float inv = 1.0f / sL[ty + 16 * ii];
#pragma unroll
        for (int id = 0; id < 8; id++)
            g_Y[(size_t)b * NN * CI + (size_t)(n0 + ty + 16 * ii) * CI + tx + 16 * id]
                = acc[ii][id] * inv;
    }
}

// ---------------- kernel 3: wy[b][o][n] = sum_d Ww[o][d]*y[b][n][d] + Wb[o] ----------------
__global__ void __launch_bounds__(256) wgemm_kernel(
    const float* __restrict__ Ww, const float* __restrict__ Wb)
{
    __shared__ float ws[32 * 65];   // [dd][ol]
    __shared__ float ys[32 * 65];   // [dd][nl]

    const int b  = blockIdx.z;
    const int o0 = blockIdx.y * 64;
    const int n0 = blockIdx.x * 64;
    const float* Y = g_Y + (size_t)b * NN * CI;

    const int tid = threadIdx.x;
    const int tx = tid & 15, ty = tid >> 4;

    float acc[4][4];
#pragma unroll
    for (int i = 0; i < 4; i++)
#pragma unroll
        for (int j = 0; j < 4; j++) acc[i][j] = 0.f;

    for (int d0 = 0; d0 < CI; d0 += 32) {
        __syncthreads();
#pragma unroll
        for (int r = 0; r < 8; r++) {
            int idx = tid + r * 256;
            int ol = idx >> 5, dd = idx & 31;
            ws[dd * 65 + ol] = Ww[(o0 + ol) * CI + d0 + dd];
        }
#pragma unroll
        for (int r = 0; r < 8; r++) {
            int idx = tid + r * 256;
            int nl = idx >> 5, dd = idx & 31;
            ys[dd * 65 + nl] = Y[(size_t)(n0 + nl) * CI + d0 + dd];
        }
        __syncthreads();
#pragma unroll 8
        for (int dd = 0; dd < 32; dd++) {
            float a[4], bv[4];
#pragma unroll
            for (int io = 0; io < 4; io++) a[io] = ws[dd * 65 + ty + 16 * io];
#pragma unroll
            for (int in = 0; in < 4; in++) bv[in] = ys[dd * 65 + tx + 16 * in];
#pragma unroll
            for (int io = 0; io < 4; io++)
#pragma unroll
                for (int in = 0; in < 4; in++) acc[io][in] += a[io] * bv[in];
        }
    }

#pragma unroll
    for (int io = 0; io < 4; io++) {
        int o = o0 + ty + 16 * io;
        float wb = Wb[o];
#pragma unroll
        for (int in = 0; in < 4; in++)
            g_WY[(size_t)b * CC * NN + (size_t)o * NN + n0 + tx + 16 * in]
                = acc[io][in] + wb;
    }
}

// ---------------- kernel 4: deterministic BN stats per channel ----------------
__global__ void __launch_bounds__(256) stats_kernel()
{
    const int o = blockIdx.x;
    const int tid = threadIdx.x;
    float s = 0.f, sq = 0.f;
    const float* p = g_WY + (size_t)o * NN;
    for (int b = 0; b < BB; b++) {
        const float* pb = p + (size_t)b * CC * NN;
        for (int n = tid; n < NN; n += 256) {
            float v = pb[n];
            s += v;
            sq += v * v;
        }
    }
    __shared__ float rs[256], rq[256];
    rs[tid] = s; rq[tid] = sq;
    __syncthreads();
    for (int w = 128; w > 0; w >>= 1) {
        if (tid < w) { rs[tid] += rs[tid + w]; rq[tid] += rq[tid + w]; }
        __syncthreads();
    }
    if (tid == 0) {
        const float invn = 1.0f / (float)(BB * NN);
        float mean = rs[0] * invn;
        float var  = rq[0] * invn - mean * mean;
        g_mean[o] = mean;
        g_rstd[o] = rsqrtf(var + BN_EPS);
    }
}

// ---------------- kernel 5: BN apply + scale + residual ----------------
__global__ void __launch_bounds__(256) apply_kernel(
    const float* __restrict__ x,
    const float* __restrict__ gamma, const float* __restrict__ beta,
    const float* __restrict__ scale, float* __restrict__ out)
{
    const int idx = blockIdx.x * blockDim.x + threadIdx.x;   // float4 index
    const int c = (idx >> 10) & 255;                          // NN/4 = 1024 per (b,c)
    const float s  = scale[0];
    const float m  = g_mean[c];
    const float r  = g_rstd[c];
    const float ga = gamma[c];
    const float be = beta[c];

    float4 wv = ((const float4*)g_WY)[idx];
    float4 xv = ((const float4*)x)[idx];
    float4 ov;
    ov.x = s * ((wv.x - m) * r * ga + be) + xv.x;
    ov.y = s * ((wv.y - m) * r * ga + be) + xv.y;
    ov.z = s * ((wv.z - m) * r * ga + be) + xv.z;
    ov.w = s * ((wv.w - m) * r * ga + be) + xv.w;
    ((float4*)out)[idx] = ov;
}

// ---------------- launcher ----------------
extern "C" void kernel_launch(void* const* d_in, const int* in_sizes, int n_in,
                              void* d_out, int out_size)
{
    const float* x     = (const float*)d_in[0];
    const float* gw    = (const float*)d_in[1];
    const float* gb    = (const float*)d_in[2];
    const float* tw    = (const float*)d_in[3];
    const float* tb    = (const float*)d_in[4];
    const float* pw    = (const float*)d_in[5];
    const float* pb    = (const float*)d_in[6];
    const float* Ww    = (const float*)d_in[7];
    const float* Wb    = (const float*)d_in[8];
    const float* gamma = (const float*)d_in[9];
    const float* beta  = (const float*)d_in[10];
    const float* scale = (const float*)d_in[11];
    float* out = (float*)d_out;

    cudaFuncSetAttribute(attn_kernel,
                         cudaFuncAttributeMaxDynamicSharedMemorySize,
                         ATTN_SMEM_BYTES);

    proj_kernel<<<dim3(NN / 64, BB, 3), 256>>>(x, gw, gb, tw, tb, pw, pb);
    attn_kernel<<<dim3(NN / 64, BB), 256, ATTN_SMEM_BYTES>>>();
    wgemm_kernel<<<dim3(NN / 64, CC / 64, BB), 256>>>(Ww, Wb);
    stats_kernel<<<CC, 256>>>();
    apply_kernel<<<(BB * CC * NN / 4) / 256, 256>>>(x, gamma, beta, scale, out);
}

// round 2
// speedup vs baseline: 1.0000x; 1.0000x over previous
#include <cuda_runtime.h>

#define BB 4
#define CC 256
#define CI 128
#define NN 4096
#define BN_EPS 1e-5f

// ---------------- scratch (no allocations allowed) ----------------
__device__ float g_TH[BB * NN * CI];   // theta proj  [b][n][d]
__device__ float g_PH[BB * NN * CI];   // phi  proj   [b][m][d]  (keys)
__device__ float g_G [BB * NN * CI];   // g    proj   [b][m][d]  (values)
__device__ float g_Y [BB * NN * CI];   // attention out [b][n][d]
__device__ float g_WY[BB * CC * NN];   // W conv out   [b][o][n]
__device__ float g_mean[CC];
__device__ float g_rstd[CC];

// ---------------- kernel 1: fused 3-way channel projections ----------------
// out[b][n][o] = sum_c w[o][c] * x[b][c*NN + n] + bias[o]
// tile: 64 n x 128 o, 256 threads, per-thread 4x8, K-chunk 32
__global__ void __launch_bounds__(256) proj_kernel(
    const float* __restrict__ x,
    const float* __restrict__ gw, const float* __restrict__ gb,
    const float* __restrict__ tw, const float* __restrict__ tb,
    const float* __restrict__ pw, const float* __restrict__ pb)
{
    __shared__ float xs[32 * 64];    // [cc][nl]
    __shared__ float ws[32 * 129];   // [cc][o], padded

    const int b  = blockIdx.y;
    const int n0 = blockIdx.x * 64;
    const int which = blockIdx.z;

    const float* w; const float* bias; float* out;
    if (which == 0)      { w = gw; bias = gb; out = g_G;  }
    else if (which == 1) { w = tw; bias = tb; out = g_TH; }
    else                 { w = pw; bias = pb; out = g_PH; }
    out += (size_t)b * NN * CI;
    const float* xb = x + (size_t)b * CC * NN;

    const int tid = threadIdx.x;
    const int tx = tid & 15, ty = tid >> 4;

    float acc[4][8];
#pragma unroll
    for (int i = 0; i < 4; i++)
#pragma unroll
        for (int j = 0; j < 8; j++) acc[i][j] = 0.f;

    for (int c0 = 0; c0 < CC; c0 += 32) {
        __syncthreads();
#pragma unroll
        for (int r = 0; r < 8; r++) {               // 2048 elems of x
            int idx = tid + r * 256;
            int cc = idx >> 6, nl = idx & 63;
            xs[cc * 64 + nl] = xb[(c0 + cc) * NN + n0 + nl];
        }
#pragma unroll
        for (int r = 0; r < 16; r++) {              // 4096 elems of w (transposed)
            int idx = tid + r * 256;
            int o = idx >> 5, cc = idx & 31;
            ws[cc * 129 + o] = w[o * CC + c0 + cc];
        }
        __syncthreads();
#pragma unroll 8
        for (int cc = 0; cc < 32; cc++) {
            float a[4], bv[8];
#pragma unroll
            for (int i = 0; i < 4; i++) a[i] = xs[cc * 64 + ty + 16 * i];
#pragma unroll
            for (int j = 0; j < 8; j++) bv[j] = ws[cc * 129 + tx + 16 * j];
#pragma unroll
            for (int i = 0; i < 4; i++)
#pragma unroll
                for (int j = 0; j < 8; j++) acc[i][j] += a[i] * bv[j];
        }
    }

#pragma unroll
    for (int j = 0; j < 8; j++) {
        float bs = bias[tx + 16 * j];
#pragma unroll
        for (int i = 0; i < 4; i++)
            out[(size_t)(n0 + ty + 16 * i) * CI + tx + 16 * j] = acc[i][j] + bs;
    }
}

// ---------------- kernel 2: fused flash attention ----------------
// per block: 64 query rows, full d=128, loop key tiles of 64
#define SQ_OFF 0
#define SK_OFF (128 * 65)
#define SG_OFF (SK_OFF + 128 * 65)
#define SS_OFF (SG_OFF + 64 * 128)
#define SM_OFF (SS_OFF + 64 * 65)
#define SL_OFF (SM_OFF + 64)
#define SC_OFF (SL_OFF + 64)
#define ATTN_SMEM_FLOATS (SC_OFF + 64)
#define ATTN_SMEM_BYTES (ATTN_SMEM_FLOATS * 4)

extern __shared__ float sm_attn[];

__global__ void __launch_bounds__(256) attn_kernel()
{
    float* sQ = sm_attn + SQ_OFF;   // [d][i] stride 65
    float* sK = sm_attn + SK_OFF;   // [d][j] stride 65
    float* sG = sm_attn + SG_OFF;   // [j][d] stride 128
    float* sS = sm_attn + SS_OFF;   // [i][j] stride 65
    float* sM = sm_attn + SM_OFF;
    float* sL = sm_attn + SL_OFF;
    float* sC = sm_attn + SC_OFF;

    const int b  = blockIdx.y;
    const int n0 = blockIdx.x * 64;
    const float* Q = g_TH + (size_t)b * NN * CI;
    const float* K = g_PH + (size_t)b * NN * CI;
    const float* G = g_G  + (size_t)b * NN * CI;

    const int tid = threadIdx.x;
    const int tx = tid & 15, ty = tid >> 4;

    // load Q tile transposed (coalesced LDG, conflict-free STS via stride 65)
#pragma unroll
    for (int r = 0; r < 32; r++) {
        int idx = tid + r * 256;
        int i = idx >> 7, d = idx & 127;
        sQ[d * 65 + i] = Q[(size_t)(n0 + i) * CI + d];
    }
    if (tid < 64) { sM[tid] = -1e30f; sL[tid] = 0.f; }

    float acc[4][8];
#pragma unroll
    for (int i = 0; i < 4; i++)
#pragma unroll
        for (int j = 0; j < 8; j++) acc[i][j] = 0.f;

    for (int k0 = 0; k0 < NN; k0 += 64) {
        // load K (transposed) + G (direct) tiles
#pragma unroll
        for (int r = 0; r < 32; r++) {
            int idx = tid + r * 256;
            int j = idx >> 7, d = idx & 127;
            float kv = K[(size_t)(k0 + j) * CI + d];
            float gv = G[(size_t)(k0 + j) * CI + d];
            sK[d * 65 + j] = kv;
            sG[j * 128 + d] = gv;
        }
        __syncthreads();

        // phase 1: S = Q @ K^T  (per thread 4x4)
        float s[4][4];
#pragma unroll
        for (int i = 0; i < 4; i++)
#pragma unroll
            for (int j = 0; j < 4; j++) s[i][j] = 0.f;

#pragma unroll 8
        for (int k = 0; k < 128; k++) {
            float a[4], bv[4];
#pragma unroll
            for (int i = 0; i < 4; i++) a[i] = sQ[k * 65 + ty + 16 * i];
#pragma unroll
            for (int j = 0; j < 4; j++) bv[j] = sK[k * 65 + tx + 16 * j];
#pragma unroll
            for (int i = 0; i < 4; i++)
#pragma unroll
                for (int j = 0; j < 4; j++) s[i][j] += a[i] * bv[j];
        }

        // online softmax (rows i = ty + 16*ii live in one 16-lane half-warp group)
#pragma unroll
        for (int ii = 0; ii < 4; ii++) {
            const int i = ty + 16 * ii;
            float m = fmaxf(fmaxf(s[ii][0], s[ii][1]), fmaxf(s[ii][2], s[ii][3]));
#pragma unroll
            for (int off = 8; off >= 1; off >>= 1)
                m = fmaxf(m, __shfl_xor_sync(0xffffffffu, m, off));
            float mo = sM[i];
            float mn = fmaxf(mo, m);
            float sum = 0.f;
#pragma unroll
            for (int jj = 0; jj < 4; jj++) {
                float p = __expf(s[ii][jj] - mn);
                s[ii][jj] = p;
                sum += p;
            }
#pragma unroll
            for (int off = 8; off >= 1; off >>= 1)
                sum += __shfl_xor_sync(0xffffffffu, sum, off);
            float corr = __expf(mo - mn);
            if (tx == 0) {
                sM[i] = mn;
                sC[i] = corr;
                sL[i] = sL[i] * corr + sum;
            }
#pragma unroll
            for (int jj = 0; jj < 4; jj++)
                sS[i * 65 + tx + 16 * jj] = s[ii][jj];
        }
        __syncthreads();

        // phase 3: acc = acc*corr + P @ G  (per thread 4x8)
#pragma unroll
        for (int ii = 0; ii < 4; ii++) {
            float c = sC[ty + 16 * ii];
#pragma unroll
            for (int id = 0; id < 8; id++) acc[ii][id] *= c;
        }
#pragma unroll 4
        for (int j = 0; j < 64; j++) {
            float p[4], gv[8];
#pragma unroll
            for (int ii = 0; ii < 4; ii++) p[ii] = sS[(ty + 16 * ii) * 65 + j];
#pragma unroll
            for (int id = 0; id < 8; id++) gv[id] = sG[j * 128 + tx + 16 * id];
#pragma unroll
            for (int ii = 0; ii < 4; ii++)
#pragma unroll
                for (int id = 0; id < 8; id++) acc[ii][id] += p[ii] * gv[id];
        }
        __syncthreads();
    }

    // finalize: divide by l, write y
#pragma unroll
    for (int ii = 0; ii < 4; ii++) {
        float inv = 1.0f / sL[ty + 16 * ii];
#pragma unroll
        for (int id = 0; id < 8; id++)
            g_Y[(size_t)b * NN * CI + (size_t)(n0 + ty + 16 * ii) * CI + tx + 16 * id]
                = acc[ii][id] * inv;
    }
}

// ---------------- kernel 3: wy[b][o][n] = sum_d Ww[o][d]*y[b][n][d] + Wb[o] ----------------
__global__ void __launch_bounds__(256) wgemm_kernel(
    const float* __restrict__ Ww, const float* __restrict__ Wb)
{
    __shared__ float ws[32 * 65];   // [dd][ol]
    __shared__ float ys[32 * 65];   // [dd][nl]

    const int b  = blockIdx.z;
    const int o0 = blockIdx.y * 64;
    const int n0 = blockIdx.x * 64;
    const float* Y = g_Y + (size_t)b * NN * CI;

    const int tid = threadIdx.x;
    const int tx = tid & 15, ty = tid >> 4;

    float acc[4][4];
#pragma unroll
    for (int i = 0; i < 4; i++)
#pragma unroll
        for (int j = 0; j < 4; j++) acc[i][j] = 0.f;

    for (int d0 = 0; d0 < CI; d0 += 32) {
        __syncthreads();
#pragma unroll
        for (int r = 0; r < 8; r++) {
            int idx = tid + r * 256;
            int ol = idx >> 5, dd = idx & 31;
            ws[dd * 65 + ol] = Ww[(o0 + ol) * CI + d0 + dd];
        }
#pragma unroll
        for (int r = 0; r < 8; r++) {
            int idx = tid + r * 256;
            int nl = idx >> 5, dd = idx & 31;
            ys[dd * 65 + nl] = Y[(size_t)(n0 + nl) * CI + d0 + dd];
        }
        __syncthreads();
#pragma unroll 8
        for (int dd = 0; dd < 32; dd++) {
            float a[4], bv[4];
#pragma unroll
            for (int io = 0; io < 4; io++) a[io] = ws[dd * 65 + ty + 16 * io];
#pragma unroll
            for (int in = 0; in < 4; in++) bv[in] = ys[dd * 65 + tx + 16 * in];
#pragma unroll
            for (int io = 0; io < 4; io++)
#pragma unroll
                for (int in = 0; in < 4; in++) acc[io][in] += a[io] * bv[in];
        }
    }

#pragma unroll
    for (int io = 0; io < 4; io++) {
        int o = o0 + ty + 16 * io;
        float wb = Wb[o];
#pragma unroll
        for (int in = 0; in < 4; in++)
            g_WY[(size_t)b * CC * NN + (size_t)o * NN + n0 + tx + 16 * in]
                = acc[io][in] + wb;
    }
}

// ---------------- kernel 4: deterministic BN stats per channel ----------------
__global__ void __launch_bounds__(256) stats_kernel()
{
    const int o = blockIdx.x;
    const int tid = threadIdx.x;
    float s = 0.f, sq = 0.f;
    const float* p = g_WY + (size_t)o * NN;
    for (int b = 0; b < BB; b++) {
        const float* pb = p + (size_t)b * CC * NN;
        for (int n = tid; n < NN; n += 256) {
            float v = pb[n];
            s += v;
            sq += v * v;
        }
    }
    __shared__ float rs[256], rq[256];
    rs[tid] = s; rq[tid] = sq;
    __syncthreads();
    for (int w = 128; w > 0; w >>= 1) {
        if (tid < w) { rs[tid] += rs[tid + w]; rq[tid] += rq[tid + w]; }
        __syncthreads();
    }
    if (tid == 0) {
        const float invn = 1.0f / (float)(BB * NN);
        float mean = rs[0] * invn;
        float var  = rq[0] * invn - mean * mean;
        g_mean[o] = mean;
        g_rstd[o] = rsqrtf(var + BN_EPS);
    }
}

// ---------------- kernel 5: BN apply + scale + residual ----------------
__global__ void __launch_bounds__(256) apply_kernel(
    const float* __restrict__ x,
    const float* __restrict__ gamma, const float* __restrict__ beta,
    const float* __restrict__ scale, float* __restrict__ out)
{
    const int idx = blockIdx.x * blockDim.x + threadIdx.x;   // float4 index
    const int c = (idx >> 10) & 255;                          // NN/4 = 1024 per (b,c)
    const float s  = scale[0];
    const float m  = g_mean[c];
    const float r  = g_rstd[c];
    const float ga = gamma[c];
    const float be = beta[c];

    float4 wv = ((const float4*)g_WY)[idx];
    float4 xv = ((const float4*)x)[idx];
    float4 ov;
    ov.x = s * ((wv.x - m) * r * ga + be) + xv.x;
    ov.y = s * ((wv.y - m) * r * ga + be) + xv.y;
    ov.z = s * ((wv.z - m) * r * ga + be) + xv.z;
    ov.w = s * ((wv.w - m) * r * ga + be) + xv.w;
    ((float4*)out)[idx] = ov;
}

// ---------------- launcher ----------------
extern "C" void kernel_launch(void* const* d_in, const int* in_sizes, int n_in,
                              void* d_out, int out_size)
{
    const float* x     = (const float*)d_in[0];
    const float* gw    = (const float*)d_in[1];
    const float* gb    = (const float*)d_in[2];
    const float* tw    = (const float*)d_in[3];
    const float* tb    = (const float*)d_in[4];
    const float* pw    = (const float*)d_in[5];
    const float* pb    = (const float*)d_in[6];
    const float* Ww    = (const float*)d_in[7];
    const float* Wb    = (const float*)d_in[8];
    const float* gamma = (const float*)d_in[9];
    const float* beta  = (const float*)d_in[10];
    const float* scale = (const float*)d_in[11];
    float* out = (float*)d_out;

    cudaFuncSetAttribute(attn_kernel,
                         cudaFuncAttributeMaxDynamicSharedMemorySize,
                         ATTN_SMEM_BYTES);

    proj_kernel<<<dim3(NN / 64, BB, 3), 256>>>(x, gw, gb, tw, tb, pw, pb);
    attn_kernel<<<dim3(NN / 64, BB), 256, ATTN_SMEM_BYTES>>>();
    wgemm_kernel<<<dim3(NN / 64, CC / 64, BB), 256>>>(Ww, Wb);
    stats_kernel<<<CC, 256>>>();
    apply_kernel<<<(BB * CC * NN / 4) / 256, 256>>>(x, gamma, beta, scale, out);
}

// round 4
// speedup vs baseline: 3.4952x; 3.4951x over previous
#include <cuda_runtime.h>

#define BB 4
#define CC 256
#define CI 128
#define NN 4096
#define BN_EPS 1e-5f

typedef unsigned int uint;
typedef unsigned short ushort;

// ---------------- scratch (no allocations allowed) ----------------
__device__ ushort g_Qh[BB * NN * CI];   // theta hi  [b][n][d]
__device__ ushort g_Ql[BB * NN * CI];   // theta lo
__device__ ushort g_Kh[BB * NN * CI];   // phi hi    [b][m][d]
__device__ ushort g_Kl[BB * NN * CI];   // phi lo
__device__ ushort g_Gth[BB * CI * NN];  // g^T hi    [b][d][m]
__device__ ushort g_Gtl[BB * CI * NN];  // g^T lo
__device__ float g_Y [BB * NN * CI];    // attention out [b][n][d]
__device__ float g_WY[BB * CC * NN];    // W conv out   [b][o][n]
__device__ float g_mean[CC];
__device__ float g_rstd[CC];

// ---------------- helpers ----------------
__device__ __forceinline__ ushort bf16rn(float v) {
    uint u = __float_as_uint(v);
    return (ushort)((u + 0x7FFFu + ((u >> 16) & 1u)) >> 16);
}
__device__ __forceinline__ uint smem_u32(const void* p) {
    uint a;
    asm("{ .reg .u64 t; cvta.to.shared.u64 t, %1; cvt.u32.u64 %0, t; }" : "=r"(a) : "l"(p));
    return a;
}
__device__ __forceinline__ void cpa16(uint s, const void* g) {
    asm volatile("cp.async.cg.shared.global [%0], [%1], 16;" :: "r"(s), "l"(g) : "memory");
}
#define CP_COMMIT() asm volatile("cp.async.commit_group;" ::: "memory")
#define CP_WAIT1()  asm volatile("cp.async.wait_group 1;" ::: "memory")

// pack2(lo, hi): bf16x2 with lo in low half
__device__ __forceinline__ uint pack2(float lo, float hi) {
    uint r;
    asm("cvt.rn.bf16x2.f32 %0, %1, %2;" : "=r"(r) : "f"(hi), "f"(lo));
    return r;
}
__device__ __forceinline__ void mma_bf(float& d0, float& d1, float& d2, float& d3,
                                       uint a0, uint a1, uint a2, uint a3,
                                       uint b0, uint b1) {
    asm volatile("mma.sync.aligned.m16n8k16.row.col.f32.bf16.bf16.f32 "
        "{%0,%1,%2,%3},{%4,%5,%6,%7},{%8,%9},{%0,%1,%2,%3};"
        : "+f"(d0), "+f"(d1), "+f"(d2), "+f"(d3)
        : "r"(a0), "r"(a1), "r"(a2), "r"(a3), "r"(b0), "r"(b1));
}

// ---------------- kernel 1: fused 3-way projections -> bf16 hi/lo ----------------
__global__ void __launch_bounds__(256) proj_kernel(
    const float* __restrict__ x,
    const float* __restrict__ gw, const float* __restrict__ gb,
    const float* __restrict__ tw, const float* __restrict__ tb,
    const float* __restrict__ pw, const float* __restrict__ pb)
{
    __shared__ uint pool[6176];                  // xs(2048) + ws(4128); reused as stage
    float* xs = (float*)pool;                    // [cc][nl] 32x64
    float* ws = (float*)pool + 2048;             // [cc][o]  32x129

    const int b  = blockIdx.y;
    const int n0 = blockIdx.x * 64;
    const int which = blockIdx.z;                // 0=g->Gt, 1=theta->Q, 2=phi->K

    const float* w; const float* bias;
    if (which == 0)      { w = gw; bias = gb; }
    else if (which == 1) { w = tw; bias = tb; }
    else                 { w = pw; bias = pb; }
    const float* xb = x + (size_t)b * CC * NN;

    const int tid = threadIdx.x;
    const int tx = tid & 15, ty = tid >> 4;

    float acc[4][8];
#pragma unroll
    for (int i = 0; i < 4; i++)
#pragma unroll
        for (int j = 0; j < 8; j++) acc[i][j] = 0.f;

    for (int c0 = 0; c0 < CC; c0 += 32) {
        __syncthreads();
#pragma unroll
        for (int r = 0; r < 8; r++) {
            int idx = tid + r * 256;
            int cc = idx >> 6, nl = idx & 63;
            xs[cc * 64 + nl] = xb[(c0 + cc) * NN + n0 + nl];
        }
#pragma unroll
        for (int r = 0; r < 16; r++) {
            int idx = tid + r * 256;
            int o = idx >> 5, cc = idx & 31;
            ws[cc * 129 + o] = w[o * CC + c0 + cc];
        }
        __syncthreads();
#pragma unroll 8
        for (int cc = 0; cc < 32; cc++) {
            float a[4], bv[8];
#pragma unroll
            for (int i = 0; i < 4; i++) a[i] = xs[cc * 64 + ty + 16 * i];
#pragma unroll
            for (int j = 0; j < 8; j++) bv[j] = ws[cc * 129 + tx + 16 * j];
#pragma unroll
            for (int i = 0; i < 4; i++)
#pragma unroll
                for (int j = 0; j < 8; j++) acc[i][j] += a[i] * bv[j];
        }
    }
#pragma unroll
    for (int j = 0; j < 8; j++) {
        float bs = bias[tx + 16 * j];
#pragma unroll
        for (int i = 0; i < 4; i++) acc[i][j] += bs;
    }

    // stage hi / lo, write out coalesced
    ushort* st = (ushort*)pool;
    for (int sel = 0; sel < 2; sel++) {
        __syncthreads();
#pragma unroll
        for (int i = 0; i < 4; i++) {
#pragma unroll
            for (int j = 0; j < 8; j++) {
                float v = acc[i][j];
                ushort hs = bf16rn(v);
                ushort bits = sel ? bf16rn(v - __uint_as_float(((uint)hs) << 16)) : hs;
                int nl = ty + 16 * i, o = tx + 16 * j;
                if (which == 0) st[o * 66 + nl] = bits;    // [o][n] stride 66
                else            st[nl * 130 + o] = bits;   // [n][o] stride 130
            }
        }
        __syncthreads();
        if (which == 0) {
            ushort* gdst = sel ? g_Gtl : g_Gth;
            int row = tid >> 1, half = tid & 1;
            uint* dst = (uint*)gdst + (size_t)(b * CI + row) * (NN / 2) + (n0 >> 1) + half * 16;
            const uint* src = pool + row * 33 + half * 16;
#pragma unroll
            for (int c = 0; c < 16; c++) dst[c] = src[c];
        } else {
            ushort* base = (which == 1) ? (sel ? g_Ql : g_Qh) : (sel ? g_Kl : g_Kh);
            uint* dst = (uint*)base + (size_t)(b * NN + n0) * (CI / 2);
#pragma unroll
            for (int it = 0; it < 16; it++) {
                int u = tid + it * 256;
                int nl = u >> 6, c = u & 63;
                dst[nl * 64 + c] = pool[nl * 65 + c];
            }
        }
    }
}

// ---------------- kernel 2: mma.sync flash attention ----------------
// smem byte offsets (Q 128x136us, K 64x136us x2x2, G 128x72us x2x2)
#define SQH 0
#define SQL 34816
#define SKH(s) (69632 + (s) * 17408)
#define SKL(s) (104448 + (s) * 17408)
#define SGH(s) (139264 + (s) * 18432)
#define SGL(s) (176128 + (s) * 18432)
#define ATTN_SMEM 212992

extern __shared__ char sm_a[];

__global__ void __launch_bounds__(256, 1) attn_kernel()
{
    const int b  = blockIdx.y;
    const int qt = blockIdx.x;                 // 0..31 (128 rows each)
    const int tid = threadIdx.x;
    const int lane = tid & 31, warp = tid >> 5;
    const uint sb = smem_u32(sm_a);

    const size_t qbase = (size_t)(b * NN + qt * 128) * CI;
    const char* Qh_g = (const char*)(g_Qh + qbase);
    const char* Ql_g = (const char*)(g_Ql + qbase);

    // ---- prologue: Q + stage0 in group0, stage1 in group1 ----
#pragma unroll
    for (int it = 0; it < 8; it++) {
        int u = tid + it * 256;
        int row = u >> 4, ch = u & 15;
        cpa16(sb + SQH + row * 272 + ch * 16, Qh_g + row * 256 + ch * 16);
        cpa16(sb + SQL + row * 272 + ch * 16, Ql_g + row * 256 + ch * 16);
    }
    {
        const char* kh = (const char*)(g_Kh + (size_t)(b * NN) * CI);
        const char* kl = (const char*)(g_Kl + (size_t)(b * NN) * CI);
        const char* gh = (const char*)(g_Gth + (size_t)(b * CI) * NN);
        const char* gl = (const char*)(g_Gtl + (size_t)(b * CI) * NN);
#pragma unroll
        for (int s = 0; s < 2; s++) {
            const char* khs = kh + (size_t)s * 64 * 256;
            const char* kls = kl + (size_t)s * 64 * 256;
#pragma unroll
            for (int it = 0; it < 4; it++) {
                int u = tid + it * 256;
                int row = u >> 4, ch = u & 15;
                cpa16(sb + SKH(s) + row * 272 + ch * 16, khs + row * 256 + ch * 16);
                cpa16(sb + SKL(s) + row * 272 + ch * 16, kls + row * 256 + ch * 16);
            }
#pragma unroll
            for (int it = 0; it < 4; it++) {
                int u = tid + it * 256;
                int row = u >> 3, ch = u & 7;
                cpa16(sb + SGH(s) + row * 144 + ch * 16, gh + (size_t)row * NN * 2 + s * 128 + ch * 16);
                cpa16(sb + SGL(s) + row * 144 + ch * 16, gl + (size_t)row * NN * 2 + s * 128 + ch * 16);
            }
            CP_COMMIT();
        }
    }

    const int r0 = warp * 16 + (lane >> 2);    // this thread's row (and r0+8)
    float o[16][4];
#pragma unroll
    for (int d = 0; d < 16; d++)
#pragma unroll
        for (int c = 0; c < 4; c++) o[d][c] = 0.f;
    float l0 = 0.f, l1 = 0.f;

    for (int t = 0; t < 64; t++) {
        CP_WAIT1();
        __syncthreads();
        const char* skh = sm_a + SKH(t & 1);
        const char* skl = sm_a + SKL(t & 1);
        const char* sgh = sm_a + SGH(t & 1);
        const char* sgl = sm_a + SGL(t & 1);

        // ---- S = Q K^T (hi*hi + hi*lo + lo*hi) ----
        float acc[8][4];
#pragma unroll
        for (int nt = 0; nt < 8; nt++)
#pragma unroll
            for (int c = 0; c < 4; c++) acc[nt][c] = 0.f;

#pragma unroll
        for (int kt = 0; kt < 8; kt++) {
            int kk = kt * 16 + (lane & 3) * 2;
            uint ah0 = *(const uint*)(sm_a + SQH + r0 * 272 + kk * 2);
            uint ah1 = *(const uint*)(sm_a + SQH + (r0 + 8) * 272 + kk * 2);
            uint ah2 = *(const uint*)(sm_a + SQH + r0 * 272 + kk * 2 + 16);
            uint ah3 = *(const uint*)(sm_a + SQH + (r0 + 8) * 272 + kk * 2 + 16);
            uint al0 = *(const uint*)(sm_a + SQL + r0 * 272 + kk * 2);
            uint al1 = *(const uint*)(sm_a + SQL + (r0 + 8) * 272 + kk * 2);
            uint al2 = *(const uint*)(sm_a + SQL + r0 * 272 + kk * 2 + 16);
            uint al3 = *(const uint*)(sm_a + SQL + (r0 + 8) * 272 + kk * 2 + 16);
#pragma unroll
            for (int nt = 0; nt < 8; nt++) {
                int j = nt * 8 + (lane >> 2);
                uint bh0 = *(const uint*)(skh + j * 272 + kk * 2);
                uint bh1 = *(const uint*)(skh + j * 272 + kk * 2 + 16);
                uint bl0 = *(const uint*)(skl + j * 272 + kk * 2);
                uint bl1 = *(const uint*)(skl + j * 272 + kk * 2 + 16);
                mma_bf(acc[nt][0], acc[nt][1], acc[nt][2], acc[nt][3],
                       ah0, ah1, ah2, ah3, bh0, bh1);
                mma_bf(acc[nt][0], acc[nt][1], acc[nt][2], acc[nt][3],
                       ah0, ah1, ah2, ah3, bl0, bl1);
                mma_bf(acc[nt][0], acc[nt][1], acc[nt][2], acc[nt][3],
                       al0, al1, al2, al3, bh0, bh1);
            }
        }

        // ---- softmax (no max subtraction; scores bounded) + bf16 hi/lo pack ----
        uint ph[8][2], pl[8][2];
#pragma unroll
        for (int nt = 0; nt < 8; nt++) {
            float p0 = __expf(acc[nt][0]);
            float p1 = __expf(acc[nt][1]);
            float p2 = __expf(acc[nt][2]);
            float p3 = __expf(acc[nt][3]);
            l0 += p0 + p1;
            l1 += p2 + p3;
            uint h01 = pack2(p0, p1);
            uint h23 = pack2(p2, p3);
            float e0 = p0 - __uint_as_float(h01 << 16);
            float e1 = p1 - __uint_as_float(h01 & 0xffff0000u);
            float e2 = p2 - __uint_as_float(h23 << 16);
            float e3 = p3 - __uint_as_float(h23 & 0xffff0000u);
            ph[nt][0] = h01; ph[nt][1] = h23;
            pl[nt][0] = pack2(e0, e1); pl[nt][1] = pack2(e2, e3);
        }

        // ---- O += P G  (P fragments come straight from registers) ----
#pragma unroll
        for (int kt2 = 0; kt2 < 4; kt2++) {
            uint ah0 = ph[2 * kt2][0], ah1 = ph[2 * kt2][1];
            uint ah2 = ph[2 * kt2 + 1][0], ah3 = ph[2 * kt2 + 1][1];
            uint al0 = pl[2 * kt2][0], al1 = pl[2 * kt2][1];
            uint al2 = pl[2 * kt2 + 1][0], al3 = pl[2 * kt2 + 1][1];
            int kk = kt2 * 16 + (lane & 3) * 2;
#pragma unroll
            for (int dn = 0; dn < 16; dn++) {
                int nd = dn * 8 + (lane >> 2);
                uint bh0 = *(const uint*)(sgh + nd * 144 + kk * 2);
                uint bh1 = *(const uint*)(sgh + nd * 144 + kk * 2 + 16);
                uint bl0 = *(const uint*)(sgl + nd * 144 + kk * 2);
                uint bl1 = *(const uint*)(sgl + nd * 144 + kk * 2 + 16);
                mma_bf(o[dn][0], o[dn][1], o[dn][2], o[dn][3],
                       ah0, ah1, ah2, ah3, bh0, bh1);
                mma_bf(o[dn][0], o[dn][1], o[dn][2], o[dn][3],
                       ah0, ah1, ah2, ah3, bl0, bl1);
                mma_bf(o[dn][0], o[dn][1], o[dn][2], o[dn][3],
                       al0, al1, al2, al3, bh0, bh1);
            }
        }

        __syncthreads();
        // ---- prefetch tile t+2 into buffer (t&1) ----
        if (t + 2 < 64) {
            int tt = t + 2;
            int s = t & 1;
            const char* khs = (const char*)(g_Kh + (size_t)(b * NN + tt * 64) * CI);
            const char* kls = (const char*)(g_Kl + (size_t)(b * NN + tt * 64) * CI);
            const char* gh = (const char*)(g_Gth + (size_t)(b * CI) * NN);
            const char* gl = (const char*)(g_Gtl + (size_t)(b * CI) * NN);
#pragma unroll
            for (int it = 0; it < 4; it++) {
                int u = tid + it * 256;
                int row = u >> 4, ch = u & 15;
                cpa16(sb + SKH(s) + row * 272 + ch * 16, khs + row * 256 + ch * 16);
                cpa16(sb + SKL(s) + row * 272 + ch * 16, kls + row * 256 + ch * 16);
            }
#pragma unroll
            for (int it = 0; it < 4; it++) {
                int u = tid + it * 256;
                int row = u >> 3, ch = u & 7;
                cpa16(sb + SGH(s) + row * 144 + ch * 16, gh + (size_t)row * NN * 2 + tt * 128 + ch * 16);
                cpa16(sb + SGL(s) + row * 144 + ch * 16, gl + (size_t)row * NN * 2 + tt * 128 + ch * 16);
            }
        }
        CP_COMMIT();   // always commit (possibly-empty group keeps wait counts aligned)
    }

    // ---- epilogue: reduce l over quad, scale, store ----
    l0 += __shfl_xor_sync(0xffffffffu, l0, 1);
    l0 += __shfl_xor_sync(0xffffffffu, l0, 2);
    l1 += __shfl_xor_sync(0xffffffffu, l1, 1);
    l1 += __shfl_xor_sync(0xffffffffu, l1, 2);
    float inv0 = 1.0f / l0, inv1 = 1.0f / l1;

    const size_t row0 = (size_t)(b * NN + qt * 128 + r0);
    const size_t row1 = row0 + 8;
#pragma unroll
    for (int dn = 0; dn < 16; dn++) {
        int col = dn * 8 + (lane & 3) * 2;
        float2 v0 = make_float2(o[dn][0] * inv0, o[dn][1] * inv0);
        float2 v1 = make_float2(o[dn][2] * inv1, o[dn][3] * inv1);
        *(float2*)(g_Y + row0 * CI + col) = v0;
        *(float2*)(g_Y + row1 * CI + col) = v1;
    }
}

// ---------------- kernel 3: wy[b][o][n] = sum_d Ww[o][d]*y[b][n][d] + Wb[o] ----------------
__global__ void __launch_bounds__(256) wgemm_kernel(
    const float* __restrict__ Ww, const float* __restrict__ Wb)
{
    __shared__ float ws[32 * 65];
    __shared__ float ys[32 * 65];

    const int b  = blockIdx.z;
    const int o0 = blockIdx.y * 64;
    const int n0 = blockIdx.x * 64;
    const float* Y = g_Y + (size_t)b * NN * CI;

    const int tid = threadIdx.x;
    const int tx = tid & 15, ty = tid >> 4;

    float acc[4][4];
#pragma unroll
    for (int i = 0; i < 4; i++)
#pragma unroll
        for (int j = 0; j < 4; j++) acc[i][j] = 0.f;

    for (int d0 = 0; d0 < CI; d0 += 32) {
        __syncthreads();
#pragma unroll
        for (int r = 0; r < 8; r++) {
            int idx = tid + r * 256;
            int ol = idx >> 5, dd = idx & 31;
            ws[dd * 65 + ol] = Ww[(o0 + ol) * CI + d0 + dd];
        }
#pragma unroll
        for (int r = 0; r < 8; r++) {
            int idx = tid + r * 256;
            int nl = idx >> 5, dd = idx & 31;
            ys[dd * 65 + nl] = Y[(size_t)(n0 + nl) * CI + d0 + dd];
        }
        __syncthreads();
#pragma unroll 8
        for (int dd = 0; dd < 32; dd++) {
            float a[4], bv[4];
#pragma unroll
            for (int io = 0; io < 4; io++) a[io] = ws[dd * 65 + ty + 16 * io];
#pragma unroll
            for (int in = 0; in < 4; in++) bv[in] = ys[dd * 65 + tx + 16 * in];
#pragma unroll
            for (int io = 0; io < 4; io++)
#pragma unroll
                for (int in = 0; in < 4; in++) acc[io][in] += a[io] * bv[in];
        }
    }

#pragma unroll
    for (int io = 0; io < 4; io++) {
        int o = o0 + ty + 16 * io;
        float wb = Wb[o];
#pragma unroll
        for (int in = 0; in < 4; in++)
            g_WY[(size_t)b * CC * NN + (size_t)o * NN + n0 + tx + 16 * in]
                = acc[io][in] + wb;
    }
}

// ---------------- kernel 4: BN stats ----------------
__global__ void __launch_bounds__(256) stats_kernel()
{
    const int o = blockIdx.x;
    const int tid = threadIdx.x;
    float s = 0.f, sq = 0.f;
    const float* p = g_WY + (size_t)o * NN;
    for (int b = 0; b < BB; b++) {
        const float* pb = p + (size_t)b * CC * NN;
        for (int n = tid; n < NN; n += 256) {
            float v = pb[n];
            s += v;
            sq += v * v;
        }
    }
    __shared__ float rs[256], rq[256];
    rs[tid] = s; rq[tid] = sq;
    __syncthreads();
    for (int w = 128; w > 0; w >>= 1) {
        if (tid < w) { rs[tid] += rs[tid + w]; rq[tid] += rq[tid + w]; }
        __syncthreads();
    }
    if (tid == 0) {
        const float invn = 1.0f / (float)(BB * NN);
        float mean = rs[0] * invn;
        float var  = rq[0] * invn - mean * mean;
        g_mean[o] = mean;
        g_rstd[o] = rsqrtf(var + BN_EPS);
    }
}

// ---------------- kernel 5: BN apply + scale + residual ----------------
__global__ void __launch_bounds__(256) apply_kernel(
    const float* __restrict__ x,
    const float* __restrict__ gamma, const float* __restrict__ beta,
    const float* __restrict__ scale, float* __restrict__ out)
{
    const int idx = blockIdx.x * blockDim.x + threadIdx.x;
    const int c = (idx >> 10) & 255;
    const float s  = scale[0];
    const float m  = g_mean[c];
    const float r  = g_rstd[c];
    const float ga = gamma[c];
    const float be = beta[c];

    float4 wv = ((const float4*)g_WY)[idx];
    float4 xv = ((const float4*)x)[idx];
    float4 ov;
    ov.x = s * ((wv.x - m) * r * ga + be) + xv.x;
    ov.y = s * ((wv.y - m) * r * ga + be) + xv.y;
    ov.z = s * ((wv.z - m) * r * ga + be) + xv.z;
    ov.w = s * ((wv.w - m) * r * ga + be) + xv.w;
    ((float4*)out)[idx] = ov;
}

// ---------------- launcher ----------------
extern "C" void kernel_launch(void* const* d_in, const int* in_sizes, int n_in,
                              void* d_out, int out_size)
{
    const float* x     = (const float*)d_in[0];
    const float* gw    = (const float*)d_in[1];
    const float* gb    = (const float*)d_in[2];
    const float* tw    = (const float*)d_in[3];
    const float* tb    = (const float*)d_in[4];
    const float* pw    = (const float*)d_in[5];
    const float* pb    = (const float*)d_in[6];
    const float* Ww    = (const float*)d_in[7];
    const float* Wb    = (const float*)d_in[8];
    const float* gamma = (const float*)d_in[9];
    const float* beta  = (const float*)d_in[10];
    const float* scale = (const float*)d_in[11];
    float* out = (float*)d_out;

    cudaFuncSetAttribute(attn_kernel,
                         cudaFuncAttributeMaxDynamicSharedMemorySize,
                         ATTN_SMEM);

    proj_kernel<<<dim3(NN / 64, BB, 3), 256>>>(x, gw, gb, tw, tb, pw, pb);
    attn_kernel<<<dim3(NN / 128, BB), 256, ATTN_SMEM>>>();
    wgemm_kernel<<<dim3(NN / 64, CC / 64, BB), 256>>>(Ww, Wb);
    stats_kernel<<<CC, 256>>>();
    apply_kernel<<<(BB * CC * NN / 4) / 256, 256>>>(x, gamma, beta, scale, out);
}

// round 5
// speedup vs baseline: 3.5070x; 1.0034x over previous
#include <cuda_runtime.h>

#define BB 4
#define CC 256
#define CI 128
#define NN 4096
#define BN_EPS 1e-5f

typedef unsigned int uint;
typedef unsigned short ushort;

// ---------------- scratch (no allocations allowed) ----------------
__device__ ushort g_Qh[BB * NN * CI];   // theta hi  [b][n][d]
__device__ ushort g_Ql[BB * NN * CI];   // theta lo
__device__ ushort g_Kh[BB * NN * CI];   // phi hi    [b][m][d]
__device__ ushort g_Kl[BB * NN * CI];   // phi lo
__device__ ushort g_Gth[BB * CI * NN];  // g^T hi    [b][d][m]
__device__ ushort g_Gtl[BB * CI * NN];  // g^T lo
__device__ float g_Y [BB * NN * CI];    // attention out [b][n][d]
__device__ float g_WY[BB * CC * NN];    // W conv out   [b][o][n]
__device__ float g_mean[CC];
__device__ float g_rstd[CC];

// ---------------- helpers ----------------
__device__ __forceinline__ ushort bf16rn(float v) {
    uint u = __float_as_uint(v);
    return (ushort)((u + 0x7FFFu + ((u >> 16) & 1u)) >> 16);
}
__device__ __forceinline__ uint smem_u32(const void* p) {
    uint a;
    asm("{ .reg .u64 t; cvta.to.shared.u64 t, %1; cvt.u32.u64 %0, t; }" : "=r"(a) : "l"(p));
    return a;
}
__device__ __forceinline__ void cpa16(uint s, const void* g) {
    asm volatile("cp.async.cg.shared.global [%0], [%1], 16;" :: "r"(s), "l"(g) : "memory");
}
#define CP_COMMIT() asm volatile("cp.async.commit_group;" ::: "memory")
#define CP_WAIT1()  asm volatile("cp.async.wait_group 1;" ::: "memory")

// pack2(lo, hi): bf16x2 with lo in low half
__device__ __forceinline__ uint pack2(float lo, float hi) {
    uint r;
    asm("cvt.rn.bf16x2.f32 %0, %1, %2;" : "=r"(r) : "f"(hi), "f"(lo));
    return r;
}
__device__ __forceinline__ void mma_bf(float& d0, float& d1, float& d2, float& d3,
                                       uint a0, uint a1, uint a2, uint a3,
                                       uint b0, uint b1) {
    asm volatile("mma.sync.aligned.m16n8k16.row.col.f32.bf16.bf16.f32 "
        "{%0,%1,%2,%3},{%4,%5,%6,%7},{%8,%9},{%0,%1,%2,%3};"
        : "+f"(d0), "+f"(d1), "+f"(d2), "+f"(d3)
        : "r"(a0), "r"(a1), "r"(a2), "r"(a3), "r"(b0), "r"(b1));
}

// ---------------- kernel 1: fused 3-way projections -> bf16 hi/lo ----------------
__global__ void __launch_bounds__(256) proj_kernel(
    const float* __restrict__ x,
    const float* __restrict__ gw, const float* __restrict__ gb,
    const float* __restrict__ tw, const float* __restrict__ tb,
    const float* __restrict__ pw, const float* __restrict__ pb)
{
    __shared__ uint pool[6176];                  // xs(2048) + ws(4128); reused as stage
    float* xs = (float*)pool;                    // [cc][nl] 32x64
    float* ws = (float*)pool + 2048;             // [cc][o]  32x129

    const int b  = blockIdx.y;
    const int n0 = blockIdx.x * 64;
    const int which = blockIdx.z;                // 0=g->Gt, 1=theta->Q, 2=phi->K

    const float* w; const float* bias;
    if (which == 0)      { w = gw; bias = gb; }
    else if (which == 1) { w = tw; bias = tb; }
    else                 { w = pw; bias = pb; }
    const float* xb = x + (size_t)b * CC * NN;

    const int tid = threadIdx.x;
    const int tx = tid & 15, ty = tid >> 4;

    float acc[4][8];
#pragma unroll
    for (int i = 0; i < 4; i++)
#pragma unroll
        for (int j = 0; j < 8; j++) acc[i][j] = 0.f;

    for (int c0 = 0; c0 < CC; c0 += 32) {
        __syncthreads();
#pragma unroll
        for (int r = 0; r < 8; r++) {
            int idx = tid + r * 256;
            int cc = idx >> 6, nl = idx & 63;
            xs[cc * 64 + nl] = xb[(c0 + cc) * NN + n0 + nl];
        }
#pragma unroll
        for (int r = 0; r < 16; r++) {
            int idx = tid + r * 256;
            int o = idx >> 5, cc = idx & 31;
            ws[cc * 129 + o] = w[o * CC + c0 + cc];
        }
        __syncthreads();
#pragma unroll 8
        for (int cc = 0; cc < 32; cc++) {
            float a[4], bv[8];
#pragma unroll
            for (int i = 0; i < 4; i++) a[i] = xs[cc * 64 + ty + 16 * i];
#pragma unroll
            for (int j = 0; j < 8; j++) bv[j] = ws[cc * 129 + tx + 16 * j];
#pragma unroll
            for (int i = 0; i < 4; i++)
#pragma unroll
                for (int j = 0; j < 8; j++) acc[i][j] += a[i] * bv[j];
        }
    }
#pragma unroll
    for (int j = 0; j < 8; j++) {
        float bs = bias[tx + 16 * j];
#pragma unroll
        for (int i = 0; i < 4; i++) acc[i][j] += bs;
    }

    // stage hi / lo, write out coalesced
    ushort* st = (ushort*)pool;
    for (int sel = 0; sel < 2; sel++) {
        __syncthreads();
#pragma unroll
        for (int i = 0; i < 4; i++) {
#pragma unroll
            for (int j = 0; j < 8; j++) {
                float v = acc[i][j];
                ushort hs = bf16rn(v);
                ushort bits = sel ? bf16rn(v - __uint_as_float(((uint)hs) << 16)) : hs;
                int nl = ty + 16 * i, o = tx + 16 * j;
                if (which == 0) st[o * 66 + nl] = bits;    // [o][n] stride 66
                else            st[nl * 130 + o] = bits;   // [n][o] stride 130
            }
        }
        __syncthreads();
        if (which == 0) {
            ushort* gdst = sel ? g_Gtl : g_Gth;
            int row = tid >> 1, half = tid & 1;
            uint* dst = (uint*)gdst + (size_t)(b * CI + row) * (NN / 2) + (n0 >> 1) + half * 16;
            const uint* src = pool + row * 33 + half * 16;
#pragma unroll
            for (int c = 0; c < 16; c++) dst[c] = src[c];
        } else {
            ushort* base = (which == 1) ? (sel ? g_Ql : g_Qh) : (sel ? g_Kl : g_Kh);
            uint* dst = (uint*)base + (size_t)(b * NN + n0) * (CI / 2);
#pragma unroll
            for (int it = 0; it < 16; it++) {
                int u = tid + it * 256;
                int nl = u >> 6, c = u & 63;
                dst[nl * 64 + c] = pool[nl * 65 + c];
            }
        }
    }
}

// ---------------- kernel 2: mma.sync flash attention ----------------
// smem byte offsets (Q 128x136us, K 64x136us x2x2, G 128x72us x2x2)
#define SQH 0
#define SQL 34816
#define SKH(s) (69632 + (s) * 17408)
#define SKL(s) (104448 + (s) * 17408)
#define SGH(s) (139264 + (s) * 18432)
#define SGL(s) (176128 + (s) * 18432)
#define ATTN_SMEM 212992

extern __shared__ char sm_a[];

__global__ void __launch_bounds__(256, 1) attn_kernel()
{
    const int b  = blockIdx.y;
    const int qt = blockIdx.x;                 // 0..31 (128 rows each)
    const int tid = threadIdx.x;
    const int lane = tid & 31, warp = tid >> 5;
    const uint sb = smem_u32(sm_a);

    const size_t qbase = (size_t)(b * NN + qt * 128) * CI;
    const char* Qh_g = (const char*)(g_Qh + qbase);
    const char* Ql_g = (const char*)(g_Ql + qbase);

    // ---- prologue: Q + stage0 in group0, stage1 in group1 ----
#pragma unroll
    for (int it = 0; it < 8; it++) {
        int u = tid + it * 256;
        int row = u >> 4, ch = u & 15;
        cpa16(sb + SQH + row * 272 + ch * 16, Qh_g + row * 256 + ch * 16);
        cpa16(sb + SQL + row * 272 + ch * 16, Ql_g + row * 256 + ch * 16);
    }
    {
        const char* kh = (const char*)(g_Kh + (size_t)(b * NN) * CI);
        const char* kl = (const char*)(g_Kl + (size_t)(b * NN) * CI);
        const char* gh = (const char*)(g_Gth + (size_t)(b * CI) * NN);
        const char* gl = (const char*)(g_Gtl + (size_t)(b * CI) * NN);
#pragma unroll
        for (int s = 0; s < 2; s++) {
            const char* khs = kh + (size_t)s * 64 * 256;
            const char* kls = kl + (size_t)s * 64 * 256;
#pragma unroll
            for (int it = 0; it < 4; it++) {
                int u = tid + it * 256;
                int row = u >> 4, ch = u & 15;
                cpa16(sb + SKH(s) + row * 272 + ch * 16, khs + row * 256 + ch * 16);
                cpa16(sb + SKL(s) + row * 272 + ch * 16, kls + row * 256 + ch * 16);
            }
#pragma unroll
            for (int it = 0; it < 4; it++) {
                int u = tid + it * 256;
                int row = u >> 3, ch = u & 7;
                cpa16(sb + SGH(s) + row * 144 + ch * 16, gh + (size_t)row * NN * 2 + s * 128 + ch * 16);
                cpa16(sb + SGL(s) + row * 144 + ch * 16, gl + (size_t)row * NN * 2 + s * 128 + ch * 16);
            }
            CP_COMMIT();
        }
    }

    const int r0 = warp * 16 + (lane >> 2);    // this thread's row (and r0+8)
    float o[16][4];
#pragma unroll
    for (int d = 0; d < 16; d++)
#pragma unroll
        for (int c = 0; c < 4; c++) o[d][c] = 0.f;
    float l0 = 0.f, l1 = 0.f;

    for (int t = 0; t < 64; t++) {
        CP_WAIT1();
        __syncthreads();
        const char* skh = sm_a + SKH(t & 1);
        const char* skl = sm_a + SKL(t & 1);
        const char* sgh = sm_a + SGH(t & 1);
        const char* sgl = sm_a + SGL(t & 1);

        // ---- S = Q K^T (hi*hi + hi*lo + lo*hi) ----
        float acc[8][4];
#pragma unroll
        for (int nt = 0; nt < 8; nt++)
#pragma unroll
            for (int c = 0; c < 4; c++) acc[nt][c] = 0.f;

#pragma unroll
        for (int kt = 0; kt < 8; kt++) {
            int kk = kt * 16 + (lane & 3) * 2;
            uint ah0 = *(const uint*)(sm_a + SQH + r0 * 272 + kk * 2);
            uint ah1 = *(const uint*)(sm_a + SQH + (r0 + 8) * 272 + kk * 2);
            uint ah2 = *(const uint*)(sm_a + SQH + r0 * 272 + kk * 2 + 16);
            uint ah3 = *(const uint*)(sm_a + SQH + (r0 + 8) * 272 + kk * 2 + 16);
            uint al0 = *(const uint*)(sm_a + SQL + r0 * 272 + kk * 2);
            uint al1 = *(const uint*)(sm_a + SQL + (r0 + 8) * 272 + kk * 2);
            uint al2 = *(const uint*)(sm_a + SQL + r0 * 272 + kk * 2 + 16);
            uint al3 = *(const uint*)(sm_a + SQL + (r0 + 8) * 272 + kk * 2 + 16);
#pragma unroll
            for (int nt = 0; nt < 8; nt++) {
                int j = nt * 8 + (lane >> 2);
                uint bh0 = *(const uint*)(skh + j * 272 + kk * 2);
                uint bh1 = *(const uint*)(skh + j * 272 + kk * 2 + 16);
                uint bl0 = *(const uint*)(skl + j * 272 + kk * 2);
                uint bl1 = *(const uint*)(skl + j * 272 + kk * 2 + 16);
                mma_bf(acc[nt][0], acc[nt][1], acc[nt][2], acc[nt][3],
                       ah0, ah1, ah2, ah3, bh0, bh1);
                mma_bf(acc[nt][0], acc[nt][1], acc[nt][2], acc[nt][3],
                       ah0, ah1, ah2, ah3, bl0, bl1);
                mma_bf(acc[nt][0], acc[nt][1], acc[nt][2], acc[nt][3],
                       al0, al1, al2, al3, bh0, bh1);
            }
        }

        // ---- softmax (no max subtraction; scores bounded) + bf16 hi/lo pack ----
        uint ph[8][2], pl[8][2];
#pragma unroll
        for (int nt = 0; nt < 8; nt++) {
            float p0 = __expf(acc[nt][0]);
            float p1 = __expf(acc[nt][1]);
            float p2 = __expf(acc[nt][2]);
            float p3 = __expf(acc[nt][3]);
            l0 += p0 + p1;
            l1 += p2 + p3;
            uint h01 = pack2(p0, p1);
            uint h23 = pack2(p2, p3);
            float e0 = p0 - __uint_as_float(h01 << 16);
            float e1 = p1 - __uint_as_float(h01 & 0xffff0000u);
            float e2 = p2 - __uint_as_float(h23 << 16);
            float e3 = p3 - __uint_as_float(h23 & 0xffff0000u);
            ph[nt][0] = h01; ph[nt][1] = h23;
            pl[nt][0] = pack2(e0, e1); pl[nt][1] = pack2(e2, e3);
        }

        // ---- O += P G  (P fragments come straight from registers) ----
#pragma unroll
        for (int kt2 = 0; kt2 < 4; kt2++) {
            uint ah0 = ph[2 * kt2][0], ah1 = ph[2 * kt2][1];
            uint ah2 = ph[2 * kt2 + 1][0], ah3 = ph[2 * kt2 + 1][1];
            uint al0 = pl[2 * kt2][0], al1 = pl[2 * kt2][1];
            uint al2 = pl[2 * kt2 + 1][0], al3 = pl[2 * kt2 + 1][1];
            int kk = kt2 * 16 + (lane & 3) * 2;
#pragma unroll
            for (int dn = 0; dn < 16; dn++) {
                int nd = dn * 8 + (lane >> 2);
                uint bh0 = *(const uint*)(sgh + nd * 144 + kk * 2);
                uint bh1 = *(const uint*)(sgh + nd * 144 + kk * 2 + 16);
                uint bl0 = *(const uint*)(sgl + nd * 144 + kk * 2);
                uint bl1 = *(const uint*)(sgl + nd * 144 + kk * 2 + 16);
                mma_bf(o[dn][0], o[dn][1], o[dn][2], o[dn][3],
                       ah0, ah1, ah2, ah3, bh0, bh1);
                mma_bf(o[dn][0], o[dn][1], o[dn][2], o[dn][3],
                       ah0, ah1, ah2, ah3, bl0, bl1);
                mma_bf(o[dn][0], o[dn][1], o[dn][2], o[dn][3],
                       al0, al1, al2, al3, bh0, bh1);
            }
        }

        __syncthreads();
        // ---- prefetch tile t+2 into buffer (t&1) ----
        if (t + 2 < 64) {
            int tt = t + 2;
            int s = t & 1;
            const char* khs = (const char*)(g_Kh + (size_t)(b * NN + tt * 64) * CI);
            const char* kls = (const char*)(g_Kl + (size_t)(b * NN + tt * 64) * CI);
            const char* gh = (const char*)(g_Gth + (size_t)(b * CI) * NN);
            const char* gl = (const char*)(g_Gtl + (size_t)(b * CI) * NN);
#pragma unroll
            for (int it = 0; it < 4; it++) {
                int u = tid + it * 256;
                int row = u >> 4, ch = u & 15;
                cpa16(sb + SKH(s) + row * 272 + ch * 16, khs + row * 256 + ch * 16);
                cpa16(sb + SKL(s) + row * 272 + ch * 16, kls + row * 256 + ch * 16);
            }
#pragma unroll
            for (int it = 0; it < 4; it++) {
                int u = tid + it * 256;
                int row = u >> 3, ch = u & 7;
                cpa16(sb + SGH(s) + row * 144 + ch * 16, gh + (size_t)row * NN * 2 + tt * 128 + ch * 16);
                cpa16(sb + SGL(s) + row * 144 + ch * 16, gl + (size_t)row * NN * 2 + tt * 128 + ch * 16);
            }
        }
        CP_COMMIT();   // always commit (possibly-empty group keeps wait counts aligned)
    }

    // ---- epilogue: reduce l over quad, scale, store ----
    l0 += __shfl_xor_sync(0xffffffffu, l0, 1);
    l0 += __shfl_xor_sync(0xffffffffu, l0, 2);
    l1 += __shfl_xor_sync(0xffffffffu, l1, 1);
    l1 += __shfl_xor_sync(0xffffffffu, l1, 2);
    float inv0 = 1.0f / l0, inv1 = 1.0f / l1;

    const size_t row0 = (size_t)(b * NN + qt * 128 + r0);
    const size_t row1 = row0 + 8;
#pragma unroll
    for (int dn = 0; dn < 16; dn++) {
        int col = dn * 8 + (lane & 3) * 2;
        float2 v0 = make_float2(o[dn][0] * inv0, o[dn][1] * inv0);
        float2 v1 = make_float2(o[dn][2] * inv1, o[dn][3] * inv1);
        *(float2*)(g_Y + row0 * CI + col) = v0;
        *(float2*)(g_Y + row1 * CI + col) = v1;
    }
}

// ---------------- kernel 3: wy[b][o][n] = sum_d Ww[o][d]*y[b][n][d] + Wb[o] ----------------
__global__ void __launch_bounds__(256) wgemm_kernel(
    const float* __restrict__ Ww, const float* __restrict__ Wb)
{
    __shared__ float ws[32 * 65];
    __shared__ float ys[32 * 65];

    const int b  = blockIdx.z;
    const int o0 = blockIdx.y * 64;
    const int n0 = blockIdx.x * 64;
    const float* Y = g_Y + (size_t)b * NN * CI;

    const int tid = threadIdx.x;
    const int tx = tid & 15, ty = tid >> 4;

    float acc[4][4];
#pragma unroll
    for (int i = 0; i < 4; i++)
#pragma unroll
        for (int j = 0; j < 4; j++) acc[i][j] = 0.f;

    for (int d0 = 0; d0 < CI; d0 += 32) {
        __syncthreads();
#pragma unroll
        for (int r = 0; r < 8; r++) {
            int idx = tid + r * 256;
            int ol = idx >> 5, dd = idx & 31;
            ws[dd * 65 + ol] = Ww[(o0 + ol) * CI + d0 + dd];
        }
#pragma unroll
        for (int r = 0; r < 8; r++) {
            int idx = tid + r * 256;
            int nl = idx >> 5, dd = idx & 31;
            ys[dd * 65 + nl] = Y[(size_t)(n0 + nl) * CI + d0 + dd];
        }
        __syncthreads();
#pragma unroll 8
        for (int dd = 0; dd < 32; dd++) {
            float a[4], bv[4];
#pragma unroll
            for (int io = 0; io < 4; io++) a[io] = ws[dd * 65 + ty + 16 * io];
#pragma unroll
            for (int in = 0; in < 4; in++) bv[in] = ys[dd * 65 + tx + 16 * in];
#pragma unroll
            for (int io = 0; io < 4; io++)
#pragma unroll
                for (int in = 0; in < 4; in++) acc[io][in] += a[io] * bv[in];
        }
    }

#pragma unroll
    for (int io = 0; io < 4; io++) {
        int o = o0 + ty + 16 * io;
        float wb = Wb[o];
#pragma unroll
        for (int in = 0; in < 4; in++)
            g_WY[(size_t)b * CC * NN + (size_t)o * NN + n0 + tx + 16 * in]
                = acc[io][in] + wb;
    }
}

// ---------------- kernel 4: BN stats ----------------
__global__ void __launch_bounds__(256) stats_kernel()
{
    const int o = blockIdx.x;
    const int tid = threadIdx.x;
    float s = 0.f, sq = 0.f;
    const float* p = g_WY + (size_t)o * NN;
    for (int b = 0; b < BB; b++) {
        const float* pb = p + (size_t)b * CC * NN;
        for (int n = tid; n < NN; n += 256) {
            float v = pb[n];
            s += v;
            sq += v * v;
        }
    }
    __shared__ float rs[256], rq[256];
    rs[tid] = s; rq[tid] = sq;
    __syncthreads();
    for (int w = 128; w > 0; w >>= 1) {
        if (tid < w) { rs[tid] += rs[tid + w]; rq[tid] += rq[tid + w]; }
        __syncthreads();
    }
    if (tid == 0) {
        const float invn = 1.0f / (float)(BB * NN);
        float mean = rs[0] * invn;
        float var  = rq[0] * invn - mean * mean;
        g_mean[o] = mean;
        g_rstd[o] = rsqrtf(var + BN_EPS);
    }
}

// ---------------- kernel 5: BN apply + scale + residual ----------------
__global__ void __launch_bounds__(256) apply_kernel(
    const float* __restrict__ x,
    const float* __restrict__ gamma, const float* __restrict__ beta,
    const float* __restrict__ scale, float* __restrict__ out)
{
    const int idx = blockIdx.x * blockDim.x + threadIdx.x;
    const int c = (idx >> 10) & 255;
    const float s  = scale[0];
    const float m  = g_mean[c];
    const float r  = g_rstd[c];
    const float ga = gamma[c];
    const float be = beta[c];

    float4 wv = ((const float4*)g_WY)[idx];
    float4 xv = ((const float4*)x)[idx];
    float4 ov;
    ov.x = s * ((wv.x - m) * r * ga + be) + xv.x;
    ov.y = s * ((wv.y - m) * r * ga + be) + xv.y;
    ov.z = s * ((wv.z - m) * r * ga + be) + xv.z;
    ov.w = s * ((wv.w - m) * r * ga + be) + xv.w;
    ((float4*)out)[idx] = ov;
}

// ---------------- launcher ----------------
extern "C" void kernel_launch(void* const* d_in, const int* in_sizes, int n_in,
                              void* d_out, int out_size)
{
    const float* x     = (const float*)d_in[0];
    const float* gw    = (const float*)d_in[1];
    const float* gb    = (const float*)d_in[2];
    const float* tw    = (const float*)d_in[3];
    const float* tb    = (const float*)d_in[4];
    const float* pw    = (const float*)d_in[5];
    const float* pb    = (const float*)d_in[6];
    const float* Ww    = (const float*)d_in[7];
    const float* Wb    = (const float*)d_in[8];
    const float* gamma = (const float*)d_in[9];
    const float* beta  = (const float*)d_in[10];
    const float* scale = (const float*)d_in[11];
    float* out = (float*)d_out;

    cudaFuncSetAttribute(attn_kernel,
                         cudaFuncAttributeMaxDynamicSharedMemorySize,
                         ATTN_SMEM);

    proj_kernel<<<dim3(NN / 64, BB, 3), 256>>>(x, gw, gb, tw, tb, pw, pb);
    attn_kernel<<<dim3(NN / 128, BB), 256, ATTN_SMEM>>>();
    wgemm_kernel<<<dim3(NN / 64, CC / 64, BB), 256>>>(Ww, Wb);
    stats_kernel<<<CC, 256>>>();
    apply_kernel<<<(BB * CC * NN / 4) / 256, 256>>>(x, gamma, beta, scale, out);
}

// round 6
// speedup vs baseline: 4.2727x; 1.2184x over previous
#include <cuda_runtime.h>

#define BB 4
#define CC 256
#define CI 128
#define NN 4096
#define BN_EPS 1e-5f

typedef unsigned int uint;
typedef unsigned short ushort;

// ---------------- scratch (no allocations allowed) ----------------
__device__ ushort g_Xh[BB * NN * CC];   // x^T hi [b][n][c]
__device__ ushort g_Xl[BB * NN * CC];
__device__ ushort g_PWh[3 * CI * CC];   // proj weights hi (g, theta, phi) [which][o][c]
__device__ ushort g_PWl[3 * CI * CC];
__device__ ushort g_Wwh[CC * CI];       // W conv weight hi [o][d]
__device__ ushort g_Wwl[CC * CI];
__device__ ushort g_Qh[BB * NN * CI];   // theta hi  [b][n][d]
__device__ ushort g_Ql[BB * NN * CI];
__device__ ushort g_Kh[BB * NN * CI];   // phi hi    [b][m][d]
__device__ ushort g_Kl[BB * NN * CI];
__device__ ushort g_Gth[BB * CI * NN];  // g^T hi    [b][d][m]
__device__ ushort g_Gtl[BB * CI * NN];
__device__ ushort g_Yh[BB * NN * CI];   // attention out hi [b][n][d]
__device__ ushort g_Yl[BB * NN * CI];
__device__ float g_WY[BB * NN * CC];    // W conv out [b][n][o]
__device__ float g_psum[128 * CC];
__device__ float g_psq [128 * CC];
__device__ float g_mean[CC];
__device__ float g_rstd[CC];

// ---------------- helpers ----------------
__device__ __forceinline__ ushort bf16rn(float v) {
    uint u = __float_as_uint(v);
    return (ushort)((u + 0x7FFFu + ((u >> 16) & 1u)) >> 16);
}
__device__ __forceinline__ uint smem_u32(const void* p) {
    uint a;
    asm("{ .reg .u64 t; cvta.to.shared.u64 t, %1; cvt.u32.u64 %0, t; }" : "=r"(a) : "l"(p));
    return a;
}
__device__ __forceinline__ void cpa16(uint s, const void* g) {
    asm volatile("cp.async.cg.shared.global [%0], [%1], 16;" :: "r"(s), "l"(g) : "memory");
}
#define CP_COMMIT() asm volatile("cp.async.commit_group;" ::: "memory")
#define CP_WAIT0()  asm volatile("cp.async.wait_group 0;" ::: "memory")
#define CP_WAIT1()  asm volatile("cp.async.wait_group 1;" ::: "memory")

// pack2(lo, hi): bf16x2 with lo in low half
__device__ __forceinline__ uint pack2(float lo, float hi) {
    uint r;
    asm("cvt.rn.bf16x2.f32 %0, %1, %2;" : "=r"(r) : "f"(hi), "f"(lo));
    return r;
}
__device__ __forceinline__ void mma_bf(float& d0, float& d1, float& d2, float& d3,
                                       uint a0, uint a1, uint a2, uint a3,
                                       uint b0, uint b1) {
    asm volatile("mma.sync.aligned.m16n8k16.row.col.f32.bf16.bf16.f32 "
        "{%0,%1,%2,%3},{%4,%5,%6,%7},{%8,%9},{%0,%1,%2,%3};"
        : "+f"(d0), "+f"(d1), "+f"(d2), "+f"(d3)
        : "r"(a0), "r"(a1), "r"(a2), "r"(a3), "r"(b0), "r"(b1));
}

// ---------------- kernel 0a: transpose + split x -> bf16 hi/lo [b][n][c] ----------------
__global__ void __launch_bounds__(256) xcvt_kernel(const float* __restrict__ x)
{
    __shared__ float st[64 * 65];
    const int n0 = blockIdx.x * 64;
    const int c0 = blockIdx.y * 64;
    const int b  = blockIdx.z;
    const int tid = threadIdx.x;
#pragma unroll
    for (int r = 0; r < 16; r++) {
        int idx = tid + r * 256;
        int cc = idx >> 6, nl = idx & 63;
        st[nl * 65 + cc] = x[((size_t)(b * CC + c0 + cc)) * NN + n0 + nl];
    }
    __syncthreads();
#pragma unroll
    for (int r = 0; r < 16; r++) {
        int idx = tid + r * 256;
        int nl = idx >> 6, cc = idx & 63;
        float v = st[nl * 65 + cc];
        ushort h = bf16rn(v);
        ushort l = bf16rn(v - __uint_as_float(((uint)h) << 16));
        size_t o = ((size_t)(b * NN + n0 + nl)) * CC + c0 + cc;
        g_Xh[o] = h;
        g_Xl[o] = l;
    }
}

// ---------------- kernel 0b: split weights -> bf16 hi/lo ----------------
__global__ void __launch_bounds__(256) wcvt_kernel(
    const float* __restrict__ gw, const float* __restrict__ tw,
    const float* __restrict__ pw, const float* __restrict__ Ww)
{
    const int total = 3 * CI * CC + CC * CI;   // 131072
    for (int idx = blockIdx.x * 256 + threadIdx.x; idx < total; idx += gridDim.x * 256) {
        float v;
        if (idx < 3 * CI * CC) {
            int which = idx / (CI * CC), r = idx % (CI * CC);
            v = (which == 0 ? gw : which == 1 ? tw : pw)[r];
            ushort h = bf16rn(v);
            g_PWh[idx] = h;
            g_PWl[idx] = bf16rn(v - __uint_as_float(((uint)h) << 16));
        } else {
            int r = idx - 3 * CI * CC;
            v = Ww[r];
            ushort h = bf16rn(v);
            g_Wwh[r] = h;
            g_Wwl[r] = bf16rn(v - __uint_as_float(((uint)h) << 16));
        }
    }
}

// ---------------- kernel 1: mma projections ----------------
// CTA: 128 n-rows x 128 o, k=256 in 4 chunks of 64, double-buffered.
// chunk buffer layout (bytes): XH 0, XL 18432, WH 36864, WL 55296 ; buf stride 73728
#define PJ_XH(buf) ((buf) * 73728)
#define PJ_XL(buf) ((buf) * 73728 + 18432)
#define PJ_WH(buf) ((buf) * 73728 + 36864)
#define PJ_WL(buf) ((buf) * 73728 + 55296)
#define PROJ_SMEM (2 * 73728)

extern __shared__ char sm_p[];

__global__ void __launch_bounds__(256, 1) proj_kernel(
    const float* __restrict__ gb_, const float* __restrict__ tb_,
    const float* __restrict__ pb_)
{
    const int b  = blockIdx.y;
    const int n0 = blockIdx.x * 128;
    const int which = blockIdx.z;              // 0=g->Gt, 1=theta->Q, 2=phi->K
    const int tid = threadIdx.x;
    const int lane = tid & 31, warp = tid >> 5;
    const uint sb = smem_u32(sm_p);
    const float* bias = (which == 0) ? gb_ : (which == 1) ? tb_ : pb_;

    const char* Xh_g = (const char*)(g_Xh + (size_t)(b * NN + n0) * CC);
    const char* Xl_g = (const char*)(g_Xl + (size_t)(b * NN + n0) * CC);
    const char* Wh_g = (const char*)(g_PWh + which * CI * CC);
    const char* Wl_g = (const char*)(g_PWl + which * CI * CC);

    // chunk loader: chunk ch covers c = ch*64..+64; rows padded to 144 bytes
    auto load_chunk = [&](int ch) {
        if (ch < 4) {
            int buf = ch & 1;
            int cb = ch * 128;                 // byte offset of chunk within a 512B row
#pragma unroll
            for (int it = 0; it < 4; it++) {   // 1024 segs of 16B for Xh (128 rows x 8 segs)
                int u = tid + it * 256;
                int row = u >> 3, seg = u & 7;
                cpa16(sb + PJ_XH(buf) + row * 144 + seg * 16, Xh_g + (size_t)row * 512 + cb + seg * 16);
                cpa16(sb + PJ_XL(buf) + row * 144 + seg * 16, Xl_g + (size_t)row * 512 + cb + seg * 16);
                cpa16(sb + PJ_WH(buf) + row * 144 + seg * 16, Wh_g + (size_t)row * 512 + cb + seg * 16);
                cpa16(sb + PJ_WL(buf) + row * 144 + seg * 16, Wl_g + (size_t)row * 512 + cb + seg * 16);
            }
        }
        CP_COMMIT();
    };

    load_chunk(0);
    load_chunk(1);

    const int r0 = warp * 16 + (lane >> 2);
    float acc[16][4];
#pragma unroll
    for (int i = 0; i < 16; i++)
#pragma unroll
        for (int c = 0; c < 4; c++) acc[i][c] = 0.f;

    for (int ch = 0; ch < 4; ch++) {
        CP_WAIT1();
        __syncthreads();
        int buf = ch & 1;
        const char* axh = sm_p + PJ_XH(buf);
        const char* axl = sm_p + PJ_XL(buf);
        const char* bwh = sm_p + PJ_WH(buf);
        const char* bwl = sm_p + PJ_WL(buf);
#pragma unroll
        for (int kt = 0; kt < 4; kt++) {
            int kk2 = (kt * 16 + (lane & 3) * 2) * 2;
            uint ah0 = *(const uint*)(axh + r0 * 144 + kk2);
            uint ah1 = *(const uint*)(axh + (r0 + 8) * 144 + kk2);
            uint ah2 = *(const uint*)(axh + r0 * 144 + kk2 + 16);
            uint ah3 = *(const uint*)(axh + (r0 + 8) * 144 + kk2 + 16);
            uint al0 = *(const uint*)(axl + r0 * 144 + kk2);
            uint al1 = *(const uint*)(axl + (r0 + 8) * 144 + kk2);
            uint al2 = *(const uint*)(axl + r0 * 144 + kk2 + 16);
            uint al3 = *(const uint*)(axl + (r0 + 8) * 144 + kk2 + 16);
#pragma unroll
            for (int ot = 0; ot < 16; ot++) {
                int j = ot * 8 + (lane >> 2);
                uint bh0 = *(const uint*)(bwh + j * 144 + kk2);
                uint bh1 = *(const uint*)(bwh + j * 144 + kk2 + 16);
                uint bl0 = *(const uint*)(bwl + j * 144 + kk2);
                uint bl1 = *(const uint*)(bwl + j * 144 + kk2 + 16);
                mma_bf(acc[ot][0], acc[ot][1], acc[ot][2], acc[ot][3],
                       ah0, ah1, ah2, ah3, bh0, bh1);
                mma_bf(acc[ot][0], acc[ot][1], acc[ot][2], acc[ot][3],
                       ah0, ah1, ah2, ah3, bl0, bl1);
                mma_bf(acc[ot][0], acc[ot][1], acc[ot][2], acc[ot][3],
                       al0, al1, al2, al3, bh0, bh1);
            }
        }
        __syncthreads();
        load_chunk(ch + 2);
    }
    CP_WAIT0();

    // add bias
#pragma unroll
    for (int ot = 0; ot < 16; ot++) {
        int o = ot * 8 + (lane & 3) * 2;
        float b0 = bias[o], b1 = bias[o + 1];
        acc[ot][0] += b0; acc[ot][1] += b1;
        acc[ot][2] += b0; acc[ot][3] += b1;
    }

    if (which != 0) {
        // direct write [n][d] hi/lo
        uint* dh = (uint*)((which == 1) ? g_Qh : g_Kh) + (size_t)(b * NN + n0) * (CI / 2);
        uint* dl = (uint*)((which == 1) ? g_Ql : g_Kl) + (size_t)(b * NN + n0) * (CI / 2);
#pragma unroll
        for (int ot = 0; ot < 16; ot++) {
            uint i0 = (uint)r0 * 64 + ot * 4 + (lane & 3);
            uint i1 = i0 + 8 * 64;
            uint h0 = pack2(acc[ot][0], acc[ot][1]);
            uint h1 = pack2(acc[ot][2], acc[ot][3]);
            float e0 = acc[ot][0] - __uint_as_float(h0 << 16);
            float e1 = acc[ot][1] - __uint_as_float(h0 & 0xffff0000u);
            float e2 = acc[ot][2] - __uint_as_float(h1 << 16);
            float e3 = acc[ot][3] - __uint_as_float(h1 & 0xffff0000u);
            dh[i0] = h0; dl[i0] = pack2(e0, e1);
            dh[i1] = h1; dl[i1] = pack2(e2, e3);
        }
    } else {
        // transpose through smem: st[o][n] (stride 136 ushort), then coalesced copy
        ushort* st = (ushort*)sm_p;
        for (int sel = 0; sel < 2; sel++) {
            __syncthreads();
#pragma unroll
            for (int ot = 0; ot < 16; ot++) {
                int o = ot * 8 + (lane & 3) * 2;
#pragma unroll
                for (int c = 0; c < 4; c++) {
                    float v = acc[ot][c];
                    ushort h = bf16rn(v);
                    ushort bits = sel ? bf16rn(v - __uint_as_float(((uint)h) << 16)) : h;
                    int oo = o + (c & 1);
                    int rr = (c < 2) ? r0 : (r0 + 8);
                    st[oo * 136 + rr] = bits;
                }
            }
            __syncthreads();
            ushort* gdst = sel ? g_Gtl : g_Gth;
#pragma unroll
            for (int it = 0; it < 8; it++) {
                int u = tid + it * 256;
                int o = u >> 4, seg = u & 15;
                *(uint4*)((char*)gdst + (((size_t)(b * CI + o)) * NN + n0) * 2 + seg * 16)
                    = *(const uint4*)((const char*)st + o * 272 + seg * 16);
            }
        }
    }
}

// ---------------- kernel 2: mma.sync flash attention (unchanged core) ----------------
#define SQH 0
#define SQL 34816
#define SKH(s) (69632 + (s) * 17408)
#define SKL(s) (104448 + (s) * 17408)
#define SGH(s) (139264 + (s) * 18432)
#define SGL(s) (176128 + (s) * 18432)
#define ATTN_SMEM 212992

extern __shared__ char sm_a[];

__global__ void __launch_bounds__(256, 1) attn_kernel()
{
    const int b  = blockIdx.y;
    const int qt = blockIdx.x;
    const int tid = threadIdx.x;
    const int lane = tid & 31, warp = tid >> 5;
    const uint sb = smem_u32(sm_a);

    const size_t qbase = (size_t)(b * NN + qt * 128) * CI;
    const char* Qh_g = (const char*)(g_Qh + qbase);
    const char* Ql_g = (const char*)(g_Ql + qbase);

#pragma unroll
    for (int it = 0; it < 8; it++) {
        int u = tid + it * 256;
        int row = u >> 4, ch = u & 15;
        cpa16(sb + SQH + row * 272 + ch * 16, Qh_g + row * 256 + ch * 16);
        cpa16(sb + SQL + row * 272 + ch * 16, Ql_g + row * 256 + ch * 16);
    }
    {
        const char* kh = (const char*)(g_Kh + (size_t)(b * NN) * CI);
        const char* kl = (const char*)(g_Kl + (size_t)(b * NN) * CI);
        const char* gh = (const char*)(g_Gth + (size_t)(b * CI) * NN);
        const char* gl = (const char*)(g_Gtl + (size_t)(b * CI) * NN);
#pragma unroll
        for (int s = 0; s < 2; s++) {
            const char* khs = kh + (size_t)s * 64 * 256;
            const char* kls = kl + (size_t)s * 64 * 256;
#pragma unroll
            for (int it = 0; it < 4; it++) {
                int u = tid + it * 256;
                int row = u >> 4, ch = u & 15;
                cpa16(sb + SKH(s) + row * 272 + ch * 16, khs + row * 256 + ch * 16);
                cpa16(sb + SKL(s) + row * 272 + ch * 16, kls + row * 256 + ch * 16);
            }
#pragma unroll
            for (int it = 0; it < 4; it++) {
                int u = tid + it * 256;
                int row = u >> 3, ch = u & 7;
                cpa16(sb + SGH(s) + row * 144 + ch * 16, gh + (size_t)row * NN * 2 + s * 128 + ch * 16);
                cpa16(sb + SGL(s) + row * 144 + ch * 16, gl + (size_t)row * NN * 2 + s * 128 + ch * 16);
            }
            CP_COMMIT();
        }
    }

    const int r0 = warp * 16 + (lane >> 2);
    float o[16][4];
#pragma unroll
    for (int d = 0; d < 16; d++)
#pragma unroll
        for (int c = 0; c < 4; c++) o[d][c] = 0.f;
    float l0 = 0.f, l1 = 0.f;

    for (int t = 0; t < 64; t++) {
        CP_WAIT1();
        __syncthreads();
        const char* skh = sm_a + SKH(t & 1);
        const char* skl = sm_a + SKL(t & 1);
        const char* sgh = sm_a + SGH(t & 1);
        const char* sgl = sm_a + SGL(t & 1);

        float acc[8][4];
#pragma unroll
        for (int nt = 0; nt < 8; nt++)
#pragma unroll
            for (int c = 0; c < 4; c++) acc[nt][c] = 0.f;

#pragma unroll
        for (int kt = 0; kt < 8; kt++) {
            int kk = kt * 16 + (lane & 3) * 2;
            uint ah0 = *(const uint*)(sm_a + SQH + r0 * 272 + kk * 2);
            uint ah1 = *(const uint*)(sm_a + SQH + (r0 + 8) * 272 + kk * 2);
            uint ah2 = *(const uint*)(sm_a + SQH + r0 * 272 + kk * 2 + 16);
            uint ah3 = *(const uint*)(sm_a + SQH + (r0 + 8) * 272 + kk * 2 + 16);
            uint al0 = *(const uint*)(sm_a + SQL + r0 * 272 + kk * 2);
            uint al1 = *(const uint*)(sm_a + SQL + (r0 + 8) * 272 + kk * 2);
            uint al2 = *(const uint*)(sm_a + SQL + r0 * 272 + kk * 2 + 16);
            uint al3 = *(const uint*)(sm_a + SQL + (r0 + 8) * 272 + kk * 2 + 16);
#pragma unroll
            for (int nt = 0; nt < 8; nt++) {
                int j = nt * 8 + (lane >> 2);
                uint bh0 = *(const uint*)(skh + j * 272 + kk * 2);
                uint bh1 = *(const uint*)(skh + j * 272 + kk * 2 + 16);
                uint bl0 = *(const uint*)(skl + j * 272 + kk * 2);
                uint bl1 = *(const uint*)(skl + j * 272 + kk * 2 + 16);
                mma_bf(acc[nt][0], acc[nt][1], acc[nt][2], acc[nt][3],
                       ah0, ah1, ah2, ah3, bh0, bh1);
                mma_bf(acc[nt][0], acc[nt][1], acc[nt][2], acc[nt][3],
                       ah0, ah1, ah2, ah3, bl0, bl1);
                mma_bf(acc[nt][0], acc[nt][1], acc[nt][2], acc[nt][3],
                       al0, al1, al2, al3, bh0, bh1);
            }
        }

        uint ph[8][2], pl[8][2];
#pragma unroll
        for (int nt = 0; nt < 8; nt++) {
            float p0 = __expf(acc[nt][0]);
            float p1 = __expf(acc[nt][1]);
            float p2 = __expf(acc[nt][2]);
            float p3 = __expf(acc[nt][3]);
            l0 += p0 + p1;
            l1 += p2 + p3;
            uint h01 = pack2(p0, p1);
            uint h23 = pack2(p2, p3);
            float e0 = p0 - __uint_as_float(h01 << 16);
            float e1 = p1 - __uint_as_float(h01 & 0xffff0000u);
            float e2 = p2 - __uint_as_float(h23 << 16);
            float e3 = p3 - __uint_as_float(h23 & 0xffff0000u);
            ph[nt][0] = h01; ph[nt][1] = h23;
            pl[nt][0] = pack2(e0, e1); pl[nt][1] = pack2(e2, e3);
        }

#pragma unroll
        for (int kt2 = 0; kt2 < 4; kt2++) {
            uint ah0 = ph[2 * kt2][0], ah1 = ph[2 * kt2][1];
            uint ah2 = ph[2 * kt2 + 1][0], ah3 = ph[2 * kt2 + 1][1];
            uint al0 = pl[2 * kt2][0], al1 = pl[2 * kt2][1];
            uint al2 = pl[2 * kt2 + 1][0], al3 = pl[2 * kt2 + 1][1];
            int kk = kt2 * 16 + (lane & 3) * 2;
#pragma unroll
            for (int dn = 0; dn < 16; dn++) {
                int nd = dn * 8 + (lane >> 2);
                uint bh0 = *(const uint*)(sgh + nd * 144 + kk * 2);
                uint bh1 = *(const uint*)(sgh + nd * 144 + kk * 2 + 16);
                uint bl0 = *(const uint*)(sgl + nd * 144 + kk * 2);
                uint bl1 = *(const uint*)(sgl + nd * 144 + kk * 2 + 16);
                mma_bf(o[dn][0], o[dn][1], o[dn][2], o[dn][3],
                       ah0, ah1, ah2, ah3, bh0, bh1);
                mma_bf(o[dn][0], o[dn][1], o[dn][2], o[dn][3],
                       ah0, ah1, ah2, ah3, bl0, bl1);
                mma_bf(o[dn][0], o[dn][1], o[dn][2], o[dn][3],
                       al0, al1, al2, al3, bh0, bh1);
            }
        }

        __syncthreads();
        if (t + 2 < 64) {
            int tt = t + 2;
            int s = t & 1;
            const char* khs = (const char*)(g_Kh + (size_t)(b * NN + tt * 64) * CI);
            const char* kls = (const char*)(g_Kl + (size_t)(b * NN + tt * 64) * CI);
            const char* gh = (const char*)(g_Gth + (size_t)(b * CI) * NN);
            const char* gl = (const char*)(g_Gtl + (size_t)(b * CI) * NN);
#pragma unroll
            for (int it = 0; it < 4; it++) {
                int u = tid + it * 256;
                int row = u >> 4, ch = u & 15;
                cpa16(sb + SKH(s) + row * 272 + ch * 16, khs + row * 256 + ch * 16);
                cpa16(sb + SKL(s) + row * 272 + ch * 16, kls + row * 256 + ch * 16);
            }
#pragma unroll
            for (int it = 0; it < 4; it++) {
                int u = tid + it * 256;
                int row = u >> 3, ch = u & 7;
                cpa16(sb + SGH(s) + row * 144 + ch * 16, gh + (size_t)row * NN * 2 + tt * 128 + ch * 16);
                cpa16(sb + SGL(s) + row * 144 + ch * 16, gl + (size_t)row * NN * 2 + tt * 128 + ch * 16);
            }
        }
        CP_COMMIT();
    }

    // epilogue: reduce l over quad, scale, emit bf16 hi/lo Y
    l0 += __shfl_xor_sync(0xffffffffu, l0, 1);
    l0 += __shfl_xor_sync(0xffffffffu, l0, 2);
    l1 += __shfl_xor_sync(0xffffffffu, l1, 1);
    l1 += __shfl_xor_sync(0xffffffffu, l1, 2);
    float inv0 = 1.0f / l0, inv1 = 1.0f / l1;

    const uint row0 = (uint)(qt * 128 + r0);
    uint* yh = (uint*)g_Yh + (size_t)b * NN * (CI / 2);
    uint* yl = (uint*)g_Yl + (size_t)b * NN * (CI / 2);
#pragma unroll
    for (int dn = 0; dn < 16; dn++) {
        uint i0 = row0 * 64 + dn * 4 + (lane & 3);
        uint i1 = i0 + 8 * 64;
        float v0 = o[dn][0] * inv0, v1 = o[dn][1] * inv0;
        float v2 = o[dn][2] * inv1, v3 = o[dn][3] * inv1;
        uint h0 = pack2(v0, v1), h1 = pack2(v2, v3);
        float e0 = v0 - __uint_as_float(h0 << 16);
        float e1 = v1 - __uint_as_float(h0 & 0xffff0000u);
        float e2 = v2 - __uint_as_float(h1 << 16);
        float e3 = v3 - __uint_as_float(h1 & 0xffff0000u);
        yh[i0] = h0; yl[i0] = pack2(e0, e1);
        yh[i1] = h1; yl[i1] = pack2(e2, e3);
    }
}

// ---------------- kernel 3: mma wgemm: WY[b][n][o] = Y[n][:]·Ww[o][:] + Wb[o] ----------------
// smem: YH 0, YL 34816, WH 69632, WL 104448 (rows padded 272B)
#define WG_YH 0
#define WG_YL 34816
#define WG_WH 69632
#define WG_WL 104448
#define WG_SMEM 139264

extern __shared__ char sm_w[];

__global__ void __launch_bounds__(256, 1) wgemm_kernel(const float* __restrict__ Wb)
{
    const int b  = blockIdx.z;
    const int oh = blockIdx.y;                  // 0/1: o half
    const int n0 = blockIdx.x * 128;
    const int tid = threadIdx.x;
    const int lane = tid & 31, warp = tid >> 5;
    const uint sb = smem_u32(sm_w);

    {
        const char* yh = (const char*)(g_Yh + (size_t)(b * NN + n0) * CI);
        const char* yl = (const char*)(g_Yl + (size_t)(b * NN + n0) * CI);
        const char* wh = (const char*)(g_Wwh + (size_t)(oh * 128) * CI);
        const char* wl = (const char*)(g_Wwl + (size_t)(oh * 128) * CI);
#pragma unroll
        for (int it = 0; it < 8; it++) {
            int u = tid + it * 256;
            int row = u >> 4, ch = u & 15;
            cpa16(sb + WG_YH + row * 272 + ch * 16, yh + (size_t)row * 256 + ch * 16);
            cpa16(sb + WG_YL + row * 272 + ch * 16, yl + (size_t)row * 256 + ch * 16);
            cpa16(sb + WG_WH + row * 272 + ch * 16, wh + (size_t)row * 256 + ch * 16);
            cpa16(sb + WG_WL + row * 272 + ch * 16, wl + (size_t)row * 256 + ch * 16);
        }
    }
    CP_COMMIT();
    CP_WAIT0();
    __syncthreads();

    const int r0 = warp * 16 + (lane >> 2);
    float acc[16][4];
#pragma unroll
    for (int i = 0; i < 16; i++)
#pragma unroll
        for (int c = 0; c < 4; c++) acc[i][c] = 0.f;

#pragma unroll
    for (int kt = 0; kt < 8; kt++) {
        int kk2 = (kt * 16 + (lane & 3) * 2) * 2;
        uint ah0 = *(const uint*)(sm_w + WG_YH + r0 * 272 + kk2);
        uint ah1 = *(const uint*)(sm_w + WG_YH + (r0 + 8) * 272 + kk2);
        uint ah2 = *(const uint*)(sm_w + WG_YH + r0 * 272 + kk2 + 16);
        uint ah3 = *(const uint*)(sm_w + WG_YH + (r0 + 8) * 272 + kk2 + 16);
        uint al0 = *(const uint*)(sm_w + WG_YL + r0 * 272 + kk2);
        uint al1 = *(const uint*)(sm_w + WG_YL + (r0 + 8) * 272 + kk2);
        uint al2 = *(const uint*)(sm_w + WG_YL + r0 * 272 + kk2 + 16);
        uint al3 = *(const uint*)(sm_w + WG_YL + (r0 + 8) * 272 + kk2 + 16);
#pragma unroll
        for (int ot = 0; ot < 16; ot++) {
            int j = ot * 8 + (lane >> 2);
            uint bh0 = *(const uint*)(sm_w + WG_WH + j * 272 + kk2);
            uint bh1 = *(const uint*)(sm_w + WG_WH + j * 272 + kk2 + 16);
            uint bl0 = *(const uint*)(sm_w + WG_WL + j * 272 + kk2);
            uint bl1 = *(const uint*)(sm_w + WG_WL + j * 272 + kk2 + 16);
            mma_bf(acc[ot][0], acc[ot][1], acc[ot][2], acc[ot][3],
                   ah0, ah1, ah2, ah3, bh0, bh1);
            mma_bf(acc[ot][0], acc[ot][1], acc[ot][2], acc[ot][3],
                   ah0, ah1, ah2, ah3, bl0, bl1);
            mma_bf(acc[ot][0], acc[ot][1], acc[ot][2], acc[ot][3],
                   al0, al1, al2, al3, bh0, bh1);
        }
    }

    float* wy = g_WY + (size_t)(b * NN + n0) * CC + oh * 128;
#pragma unroll
    for (int ot = 0; ot < 16; ot++) {
        int o = ot * 8 + (lane & 3) * 2;
        float b0 = Wb[oh * 128 + o], b1 = Wb[oh * 128 + o + 1];
        *(float2*)(wy + (size_t)r0 * CC + o) = make_float2(acc[ot][0] + b0, acc[ot][1] + b1);
        *(float2*)(wy + (size_t)(r0 + 8) * CC + o) = make_float2(acc[ot][2] + b0, acc[ot][3] + b1);
    }
}

// ---------------- kernel 4a/4b: deterministic BN stats ----------------
__global__ void __launch_bounds__(256) stats1_kernel()
{
    const int blk = blockIdx.x;                // 128 blocks, 128 rows each
    const int t = threadIdx.x;                 // channel o
    float s = 0.f, q = 0.f;
    const float* base = g_WY + (size_t)blk * 128 * CC + t;
    for (int r = 0; r < 128; r++) {
        float v = base[(size_t)r * CC];
        s += v; q += v * v;
    }
    g_psum[blk * CC + t] = s;
    g_psq [blk * CC + t] = q;
}
__global__ void __launch_bounds__(256) stats2_kernel()
{
    const int t = threadIdx.x;
    float s = 0.f, q = 0.f;
    for (int p = 0; p < 128; p++) {
        s += g_psum[p * CC + t];
        q += g_psq [p * CC + t];
    }
    const float invn = 1.0f / (float)(BB * NN);
    float mean = s * invn;
    float var  = q * invn - mean * mean;
    g_mean[t] = mean;
    g_rstd[t] = rsqrtf(var + BN_EPS);
}

// ---------------- kernel 5: BN apply + scale + residual (with transpose) ----------------
__global__ void __launch_bounds__(256) apply_kernel(
    const float* __restrict__ x,
    const float* __restrict__ gamma, const float* __restrict__ beta,
    const float* __restrict__ scale, float* __restrict__ out)
{
    __shared__ float st[64 * 65];
    const int n0 = blockIdx.x * 64;
    const int c0 = blockIdx.y * 64;
    const int b  = blockIdx.z;
    const int tid = threadIdx.x;
    const float s = scale[0];

#pragma unroll
    for (int r = 0; r < 16; r++) {
        int idx = tid + r * 256;
        int nl = idx >> 6, cc = idx & 63;
        st[cc * 65 + nl] = g_WY[((size_t)(b * NN + n0 + nl)) * CC + c0 + cc];
    }
    __syncthreads();
#pragma unroll
    for (int r = 0; r < 16; r++) {
        int idx = tid + r * 256;
        int cc = idx >> 6, nl = idx & 63;
        int c = c0 + cc;
        float wv = st[cc * 65 + nl];
        float v = s * ((wv - g_mean[c]) * g_rstd[c] * gamma[c] + beta[c])
                + x[((size_t)(b * CC + c)) * NN + n0 + nl];
        out[((size_t)(b * CC + c)) * NN + n0 + nl] = v;
    }
}

// ---------------- launcher ----------------
extern "C" void kernel_launch(void* const* d_in, const int* in_sizes, int n_in,
                              void* d_out, int out_size)
{
    const float* x     = (const float*)d_in[0];
    const float* gw    = (const float*)d_in[1];
    const float* gb    = (const float*)d_in[2];
    const float* tw    = (const float*)d_in[3];
    const float* tb    = (const float*)d_in[4];
    const float* pw    = (const float*)d_in[5];
    const float* pb    = (const float*)d_in[6];
    const float* Ww    = (const float*)d_in[7];
    const float* Wb    = (const float*)d_in[8];
    const float* gamma = (const float*)d_in[9];
    const float* beta  = (const float*)d_in[10];
    const float* scale = (const float*)d_in[11];
    float* out = (float*)d_out;

    cudaFuncSetAttribute(proj_kernel,
                         cudaFuncAttributeMaxDynamicSharedMemorySize, PROJ_SMEM);
    cudaFuncSetAttribute(attn_kernel,
                         cudaFuncAttributeMaxDynamicSharedMemorySize, ATTN_SMEM);
    cudaFuncSetAttribute(wgemm_kernel,
                         cudaFuncAttributeMaxDynamicSharedMemorySize, WG_SMEM);

    xcvt_kernel<<<dim3(NN / 64, CC / 64, BB), 256>>>(x);
    wcvt_kernel<<<64, 256>>>(gw, tw, pw, Ww);
    proj_kernel<<<dim3(NN / 128, BB, 3), 256, PROJ_SMEM>>>(gb, tb, pb);
    attn_kernel<<<dim3(NN / 128, BB), 256, ATTN_SMEM>>>();
    wgemm_kernel<<<dim3(NN / 128, 2, BB), 256, WG_SMEM>>>(Wb);
    stats1_kernel<<<128, 256>>>();
    stats2_kernel<<<1, 256>>>();
    apply_kernel<<<dim3(NN / 64, CC / 64, BB), 256>>>(x, gamma, beta, scale, out);
}

// round 7
// speedup vs baseline: 4.7784x; 1.1183x over previous
#include <cuda_runtime.h>

#define BB 4
#define CC 256
#define CI 128
#define NN 4096
#define BN_EPS 1e-5f

typedef unsigned int uint;
typedef unsigned short ushort;

// ---------------- scratch (no allocations allowed) ----------------
__device__ __align__(16) ushort g_Xh[BB * NN * CC];   // x^T hi [b][n][c]
__device__ __align__(16) ushort g_Xl[BB * NN * CC];
__device__ __align__(16) ushort g_PWh[3 * CI * CC];   // proj weights hi (g, theta, phi) [which][o][c]
__device__ __align__(16) ushort g_PWl[3 * CI * CC];
__device__ __align__(16) ushort g_Wwh[CC * CI];       // W conv weight hi [o][d]
__device__ __align__(16) ushort g_Wwl[CC * CI];
__device__ __align__(16) ushort g_Qh[BB * NN * CI];   // theta hi  [b][n][d]
__device__ __align__(16) ushort g_Ql[BB * NN * CI];
__device__ __align__(16) ushort g_Kh[BB * NN * CI];   // phi hi    [b][m][d]
__device__ __align__(16) ushort g_Kl[BB * NN * CI];
__device__ __align__(16) ushort g_Gth[BB * CI * NN];  // g^T hi    [b][d][m]
__device__ __align__(16) float g_Op[2 * BB * NN * CI]; // partial O (unnormalized), z slabs
__device__ __align__(16) float g_lp[2 * BB * NN];      // partial l
__device__ __align__(16) ushort g_Yh[BB * NN * CI];   // attention out hi [b][n][d]
__device__ __align__(16) ushort g_Yl[BB * NN * CI];
__device__ __align__(16) float g_WY[BB * NN * CC];    // W conv out [b][n][o]
__device__ __align__(16) float g_psum[128 * CC];
__device__ __align__(16) float g_psq [128 * CC];
__device__ float g_mean[CC];
__device__ float g_rstd[CC];

// ---------------- helpers ----------------
__device__ __forceinline__ ushort bf16rn(float v) {
    uint u = __float_as_uint(v);
    return (ushort)((u + 0x7FFFu + ((u >> 16) & 1u)) >> 16);
}
__device__ __forceinline__ uint smem_u32(const void* p) {
    uint a;
    asm("{ .reg .u64 t; cvta.to.shared.u64 t, %1; cvt.u32.u64 %0, t; }" : "=r"(a) : "l"(p));
    return a;
}
__device__ __forceinline__ void cpa16(uint s, const void* g) {
    asm volatile("cp.async.cg.shared.global [%0], [%1], 16;" :: "r"(s), "l"(g) : "memory");
}
#define CP_COMMIT() asm volatile("cp.async.commit_group;" ::: "memory")
#define CP_WAIT0()  asm volatile("cp.async.wait_group 0;" ::: "memory")
#define CP_WAIT1()  asm volatile("cp.async.wait_group 1;" ::: "memory")

// pack2(lo, hi): bf16x2 with lo in low half
__device__ __forceinline__ uint pack2(float lo, float hi) {
    uint r;
    asm("cvt.rn.bf16x2.f32 %0, %1, %2;" : "=r"(r) : "f"(hi), "f"(lo));
    return r;
}
__device__ __forceinline__ void mma_bf(float& d0, float& d1, float& d2, float& d3,
                                       uint a0, uint a1, uint a2, uint a3,
                                       uint b0, uint b1) {
    asm volatile("mma.sync.aligned.m16n8k16.row.col.f32.bf16.bf16.f32 "
        "{%0,%1,%2,%3},{%4,%5,%6,%7},{%8,%9},{%0,%1,%2,%3};"
        : "+f"(d0), "+f"(d1), "+f"(d2), "+f"(d3)
        : "r"(a0), "r"(a1), "r"(a2), "r"(a3), "r"(b0), "r"(b1));
}

// ---------------- kernel 0a: transpose + split x -> bf16 hi/lo [b][n][c] ----------------
__global__ void __launch_bounds__(256) xcvt_kernel(const float* __restrict__ x)
{
    __shared__ float st[64 * 65];
    const int n0 = blockIdx.x * 64;
    const int c0 = blockIdx.y * 64;
    const int b  = blockIdx.z;
    const int tid = threadIdx.x;
#pragma unroll
    for (int r = 0; r < 16; r++) {
        int idx = tid + r * 256;
        int cc = idx >> 6, nl = idx & 63;
        st[nl * 65 + cc] = x[((size_t)(b * CC + c0 + cc)) * NN + n0 + nl];
    }
    __syncthreads();
#pragma unroll
    for (int r = 0; r < 16; r++) {
        int idx = tid + r * 256;
        int nl = idx >> 6, cc = idx & 63;
        float v = st[nl * 65 + cc];
        ushort h = bf16rn(v);
        ushort l = bf16rn(v - __uint_as_float(((uint)h) << 16));
        size_t o = ((size_t)(b * NN + n0 + nl)) * CC + c0 + cc;
        g_Xh[o] = h;
        g_Xl[o] = l;
    }
}

// ---------------- kernel 0b: split weights -> bf16 hi/lo ----------------
__global__ void __launch_bounds__(256) wcvt_kernel(
    const float* __restrict__ gw, const float* __restrict__ tw,
    const float* __restrict__ pw, const float* __restrict__ Ww)
{
    const int total = 3 * CI * CC + CC * CI;
    for (int idx = blockIdx.x * 256 + threadIdx.x; idx < total; idx += gridDim.x * 256) {
        float v;
        if (idx < 3 * CI * CC) {
            int which = idx / (CI * CC), r = idx % (CI * CC);
            v = (which == 0 ? gw : which == 1 ? tw : pw)[r];
            ushort h = bf16rn(v);
            g_PWh[idx] = h;
            g_PWl[idx] = bf16rn(v - __uint_as_float(((uint)h) << 16));
        } else {
            int r = idx - 3 * CI * CC;
            v = Ww[r];
            ushort h = bf16rn(v);
            g_Wwh[r] = h;
            g_Wwl[r] = bf16rn(v - __uint_as_float(((uint)h) << 16));
        }
    }
}

// ---------------- kernel 1: mma projections ----------------
#define PJ_XH(buf) ((buf) * 73728)
#define PJ_XL(buf) ((buf) * 73728 + 18432)
#define PJ_WH(buf) ((buf) * 73728 + 36864)
#define PJ_WL(buf) ((buf) * 73728 + 55296)
#define PROJ_SMEM (2 * 73728)

extern __shared__ char sm_p[];

__global__ void __launch_bounds__(256, 1) proj_kernel(
    const float* __restrict__ gb_, const float* __restrict__ tb_,
    const float* __restrict__ pb_)
{
    const int b  = blockIdx.y;
    const int n0 = blockIdx.x * 128;
    const int which = blockIdx.z;              // 0=g->Gt(hi only), 1=theta->Q, 2=phi->K
    const int tid = threadIdx.x;
    const int lane = tid & 31, warp = tid >> 5;
    const uint sb = smem_u32(sm_p);
    const float* bias = (which == 0) ? gb_ : (which == 1) ? tb_ : pb_;

    const char* Xh_g = (const char*)(g_Xh + (size_t)(b * NN + n0) * CC);
    const char* Xl_g = (const char*)(g_Xl + (size_t)(b * NN + n0) * CC);
    const char* Wh_g = (const char*)(g_PWh + which * CI * CC);
    const char* Wl_g = (const char*)(g_PWl + which * CI * CC);

    auto load_chunk = [&](int ch) {
        if (ch < 4) {
            int buf = ch & 1;
            int cb = ch * 128;
#pragma unroll
            for (int it = 0; it < 4; it++) {
                int u = tid + it * 256;
                int row = u >> 3, seg = u & 7;
                cpa16(sb + PJ_XH(buf) + row * 144 + seg * 16, Xh_g + (size_t)row * 512 + cb + seg * 16);
                cpa16(sb + PJ_XL(buf) + row * 144 + seg * 16, Xl_g + (size_t)row * 512 + cb + seg * 16);
                cpa16(sb + PJ_WH(buf) + row * 144 + seg * 16, Wh_g + (size_t)row * 512 + cb + seg * 16);
                cpa16(sb + PJ_WL(buf) + row * 144 + seg * 16, Wl_g + (size_t)row * 512 + cb + seg * 16);
            }
        }
        CP_COMMIT();
    };

    load_chunk(0);
    load_chunk(1);

    const int r0 = warp * 16 + (lane >> 2);
    float acc[16][4];
#pragma unroll
    for (int i = 0; i < 16; i++)
#pragma unroll
        for (int c = 0; c < 4; c++) acc[i][c] = 0.f;

    for (int ch = 0; ch < 4; ch++) {
        CP_WAIT1();
        __syncthreads();
        int buf = ch & 1;
        const char* axh = sm_p + PJ_XH(buf);
        const char* axl = sm_p + PJ_XL(buf);
        const char* bwh = sm_p + PJ_WH(buf);
        const char* bwl = sm_p + PJ_WL(buf);
#pragma unroll
        for (int kt = 0; kt < 4; kt++) {
            int kk2 = (kt * 16 + (lane & 3) * 2) * 2;
            uint ah0 = *(const uint*)(axh + r0 * 144 + kk2);
            uint ah1 = *(const uint*)(axh + (r0 + 8) * 144 + kk2);
            uint ah2 = *(const uint*)(axh + r0 * 144 + kk2 + 16);
            uint ah3 = *(const uint*)(axh + (r0 + 8) * 144 + kk2 + 16);
            uint al0 = *(const uint*)(axl + r0 * 144 + kk2);
            uint al1 = *(const uint*)(axl + (r0 + 8) * 144 + kk2);
            uint al2 = *(const uint*)(axl + r0 * 144 + kk2 + 16);
            uint al3 = *(const uint*)(axl + (r0 + 8) * 144 + kk2 + 16);
#pragma unroll
            for (int ot = 0; ot < 16; ot++) {
                int j = ot * 8 + (lane >> 2);
                uint bh0 = *(const uint*)(bwh + j * 144 + kk2);
                uint bh1 = *(const uint*)(bwh + j * 144 + kk2 + 16);
                uint bl0 = *(const uint*)(bwl + j * 144 + kk2);
                uint bl1 = *(const uint*)(bwl + j * 144 + kk2 + 16);
                mma_bf(acc[ot][0], acc[ot][1], acc[ot][2], acc[ot][3],
                       ah0, ah1, ah2, ah3, bh0, bh1);
                mma_bf(acc[ot][0], acc[ot][1], acc[ot][2], acc[ot][3],
                       ah0, ah1, ah2, ah3, bl0, bl1);
                mma_bf(acc[ot][0], acc[ot][1], acc[ot][2], acc[ot][3],
                       al0, al1, al2, al3, bh0, bh1);
            }
        }
        __syncthreads();
        load_chunk(ch + 2);
    }
    CP_WAIT0();

#pragma unroll
    for (int ot = 0; ot < 16; ot++) {
        int o = ot * 8 + (lane & 3) * 2;
        float b0 = bias[o], b1 = bias[o + 1];
        acc[ot][0] += b0; acc[ot][1] += b1;
        acc[ot][2] += b0; acc[ot][3] += b1;
    }

    if (which != 0) {
        uint* dh = (uint*)((which == 1) ? g_Qh : g_Kh) + (size_t)(b * NN + n0) * (CI / 2);
        uint* dl = (uint*)((which == 1) ? g_Ql : g_Kl) + (size_t)(b * NN + n0) * (CI / 2);
#pragma unroll
        for (int ot = 0; ot < 16; ot++) {
            uint i0 = (uint)r0 * 64 + ot * 4 + (lane & 3);
            uint i1 = i0 + 8 * 64;
            uint h0 = pack2(acc[ot][0], acc[ot][1]);
            uint h1 = pack2(acc[ot][2], acc[ot][3]);
            float e0 = acc[ot][0] - __uint_as_float(h0 << 16);
            float e1 = acc[ot][1] - __uint_as_float(h0 & 0xffff0000u);
            float e2 = acc[ot][2] - __uint_as_float(h1 << 16);
            float e3 = acc[ot][3] - __uint_as_float(h1 & 0xffff0000u);
            dh[i0] = h0; dl[i0] = pack2(e0, e1);
            dh[i1] = h1; dl[i1] = pack2(e2, e3);
        }
    } else {
        // hi-only transpose through smem: st[o][n] stride 136 ushort
        ushort* st = (ushort*)sm_p;
        __syncthreads();
#pragma unroll
        for (int ot = 0; ot < 16; ot++) {
            int o = ot * 8 + (lane & 3) * 2;
#pragma unroll
            for (int c = 0; c < 4; c++) {
                int oo = o + (c & 1);
                int rr = (c < 2) ? r0 : (r0 + 8);
                st[oo * 136 + rr] = bf16rn(acc[ot][c]);
            }
        }
        __syncthreads();
#pragma unroll
        for (int it = 0; it < 8; it++) {
            int u = tid + it * 256;
            int o = u >> 4, seg = u & 15;
            *(uint4*)((char*)g_Gth + (((size_t)(b * CI + o)) * NN + n0) * 2 + seg * 16)
                = *(const uint4*)((const char*)st + o * 272 + seg * 16);
        }
    }
}

// ---------------- kernel 2: mma.sync flash attention (split-K, 2-term PV) ----------------
#define SQH 0
#define SQL 34816
#define SKH(s) (69632 + (s) * 17408)
#define SKL(s) (104448 + (s) * 17408)
#define SGH(s) (139264 + (s) * 18432)
#define ATTN_SMEM 176128
#define KTILES 32

extern __shared__ char sm_a[];

__global__ void __launch_bounds__(256, 1) attn_kernel()
{
    const int b  = blockIdx.y;
    const int qt = blockIdx.x;
    const int z  = blockIdx.z;                 // key half
    const int tid = threadIdx.x;
    const int lane = tid & 31, warp = tid >> 5;
    const uint sb = smem_u32(sm_a);

    const size_t qbase = (size_t)(b * NN + qt * 128) * CI;
    const char* Qh_g = (const char*)(g_Qh + qbase);
    const char* Ql_g = (const char*)(g_Ql + qbase);
    const char* gh_g = (const char*)(g_Gth + (size_t)(b * CI) * NN);

#pragma unroll
    for (int it = 0; it < 8; it++) {
        int u = tid + it * 256;
        int row = u >> 4, ch = u & 15;
        cpa16(sb + SQH + row * 272 + ch * 16, Qh_g + row * 256 + ch * 16);
        cpa16(sb + SQL + row * 272 + ch * 16, Ql_g + row * 256 + ch * 16);
    }
#pragma unroll
    for (int s = 0; s < 2; s++) {
        int kt = z * KTILES + s;
        const char* khs = (const char*)(g_Kh + (size_t)(b * NN + kt * 64) * CI);
        const char* kls = (const char*)(g_Kl + (size_t)(b * NN + kt * 64) * CI);
#pragma unroll
        for (int it = 0; it < 4; it++) {
            int u = tid + it * 256;
            int row = u >> 4, ch = u & 15;
            cpa16(sb + SKH(s) + row * 272 + ch * 16, khs + row * 256 + ch * 16);
            cpa16(sb + SKL(s) + row * 272 + ch * 16, kls + row * 256 + ch * 16);
        }
#pragma unroll
        for (int it = 0; it < 4; it++) {
            int u = tid + it * 256;
            int row = u >> 3, ch = u & 7;
            cpa16(sb + SGH(s) + row * 144 + ch * 16, gh_g + (size_t)row * NN * 2 + kt * 128 + ch * 16);
        }
        CP_COMMIT();
    }

    const int r0 = warp * 16 + (lane >> 2);
    float o[16][4];
#pragma unroll
    for (int d = 0; d < 16; d++)
#pragma unroll
        for (int c = 0; c < 4; c++) o[d][c] = 0.f;
    float l0 = 0.f, l1 = 0.f;

    for (int t = 0; t < KTILES; t++) {
        CP_WAIT1();
        __syncthreads();
        const char* skh = sm_a + SKH(t & 1);
        const char* skl = sm_a + SKL(t & 1);
        const char* sgh = sm_a + SGH(t & 1);

        float acc[8][4];
#pragma unroll
        for (int nt = 0; nt < 8; nt++)
#pragma unroll
            for (int c = 0; c < 4; c++) acc[nt][c] = 0.f;

#pragma unroll
        for (int kt = 0; kt < 8; kt++) {
            int kk = kt * 16 + (lane & 3) * 2;
            uint ah0 = *(const uint*)(sm_a + SQH + r0 * 272 + kk * 2);
            uint ah1 = *(const uint*)(sm_a + SQH + (r0 + 8) * 272 + kk * 2);
            uint ah2 = *(const uint*)(sm_a + SQH + r0 * 272 + kk * 2 + 16);
            uint ah3 = *(const uint*)(sm_a + SQH + (r0 + 8) * 272 + kk * 2 + 16);
            uint al0 = *(const uint*)(sm_a + SQL + r0 * 272 + kk * 2);
            uint al1 = *(const uint*)(sm_a + SQL + (r0 + 8) * 272 + kk * 2);
            uint al2 = *(const uint*)(sm_a + SQL + r0 * 272 + kk * 2 + 16);
            uint al3 = *(const uint*)(sm_a + SQL + (r0 + 8) * 272 + kk * 2 + 16);
#pragma unroll
            for (int nt = 0; nt < 8; nt++) {
                int j = nt * 8 + (lane >> 2);
                uint bh0 = *(const uint*)(skh + j * 272 + kk * 2);
                uint bh1 = *(const uint*)(skh + j * 272 + kk * 2 + 16);
                uint bl0 = *(const uint*)(skl + j * 272 + kk * 2);
                uint bl1 = *(const uint*)(skl + j * 272 + kk * 2 + 16);
                mma_bf(acc[nt][0], acc[nt][1], acc[nt][2], acc[nt][3],
                       ah0, ah1, ah2, ah3, bh0, bh1);
                mma_bf(acc[nt][0], acc[nt][1], acc[nt][2], acc[nt][3],
                       ah0, ah1, ah2, ah3, bl0, bl1);
                mma_bf(acc[nt][0], acc[nt][1], acc[nt][2], acc[nt][3],
                       al0, al1, al2, al3, bh0, bh1);
            }
        }

        uint ph[8][2], pl[8][2];
#pragma unroll
        for (int nt = 0; nt < 8; nt++) {
            float p0 = __expf(acc[nt][0]);
            float p1 = __expf(acc[nt][1]);
            float p2 = __expf(acc[nt][2]);
            float p3 = __expf(acc[nt][3]);
            l0 += p0 + p1;
            l1 += p2 + p3;
            uint h01 = pack2(p0, p1);
            uint h23 = pack2(p2, p3);
            float e0 = p0 - __uint_as_float(h01 << 16);
            float e1 = p1 - __uint_as_float(h01 & 0xffff0000u);
            float e2 = p2 - __uint_as_float(h23 << 16);
            float e3 = p3 - __uint_as_float(h23 & 0xffff0000u);
            ph[nt][0] = h01; ph[nt][1] = h23;
            pl[nt][0] = pack2(e0, e1); pl[nt][1] = pack2(e2, e3);
        }

        // O += P_hi*G_hi + P_lo*G_hi  (G lo term dropped)
#pragma unroll
        for (int kt2 = 0; kt2 < 4; kt2++) {
            uint ah0 = ph[2 * kt2][0], ah1 = ph[2 * kt2][1];
            uint ah2 = ph[2 * kt2 + 1][0], ah3 = ph[2 * kt2 + 1][1];
            uint al0 = pl[2 * kt2][0], al1 = pl[2 * kt2][1];
            uint al2 = pl[2 * kt2 + 1][0], al3 = pl[2 * kt2 + 1][1];
            int kk = kt2 * 16 + (lane & 3) * 2;
#pragma unroll
            for (int dn = 0; dn < 16; dn++) {
                int nd = dn * 8 + (lane >> 2);
                uint bh0 = *(const uint*)(sgh + nd * 144 + kk * 2);
                uint bh1 = *(const uint*)(sgh + nd * 144 + kk * 2 + 16);
                mma_bf(o[dn][0], o[dn][1], o[dn][2], o[dn][3],
                       ah0, ah1, ah2, ah3, bh0, bh1);
                mma_bf(o[dn][0], o[dn][1], o[dn][2], o[dn][3],
                       al0, al1, al2, al3, bh0, bh1);
            }
        }

        __syncthreads();
        if (t + 2 < KTILES) {
            int kt = z * KTILES + t + 2;
            int s = t & 1;
            const char* khs = (const char*)(g_Kh + (size_t)(b * NN + kt * 64) * CI);
            const char* kls = (const char*)(g_Kl + (size_t)(b * NN + kt * 64) * CI);
#pragma unroll
            for (int it = 0; it < 4; it++) {
                int u = tid + it * 256;
                int row = u >> 4, ch = u & 15;
                cpa16(sb + SKH(s) + row * 272 + ch * 16, khs + row * 256 + ch * 16);
                cpa16(sb + SKL(s) + row * 272 + ch * 16, kls + row * 256 + ch * 16);
            }
#pragma unroll
            for (int it = 0; it < 4; it++) {
                int u = tid + it * 256;
                int row = u >> 3, ch = u & 7;
                cpa16(sb + SGH(s) + row * 144 + ch * 16, gh_g + (size_t)row * NN * 2 + kt * 128 + ch * 16);
            }
        }
        CP_COMMIT();
    }

    // epilogue: quad-reduce l, write partial O (unnormalized) + partial l
    l0 += __shfl_xor_sync(0xffffffffu, l0, 1);
    l0 += __shfl_xor_sync(0xffffffffu, l0, 2);
    l1 += __shfl_xor_sync(0xffffffffu, l1, 1);
    l1 += __shfl_xor_sync(0xffffffffu, l1, 2);

    float* obase = g_Op + ((size_t)(z * BB + b) * NN + qt * 128) * CI;
#pragma unroll
    for (int dn = 0; dn < 16; dn++) {
        int col = dn * 8 + (lane & 3) * 2;
        *(float2*)(obase + (size_t)r0 * CI + col) = make_float2(o[dn][0], o[dn][1]);
        *(float2*)(obase + (size_t)(r0 + 8) * CI + col) = make_float2(o[dn][2], o[dn][3]);
    }
    if ((lane & 3) == 0) {
        g_lp[(size_t)(z * BB + b) * NN + qt * 128 + r0] = l0;
        g_lp[(size_t)(z * BB + b) * NN + qt * 128 + r0 + 8] = l1;
    }
}

// ---------------- kernel 2b: combine key-halves, emit Y bf16 hi/lo ----------------
__global__ void __launch_bounds__(256) combine_kernel()
{
    const int idx = blockIdx.x * 256 + threadIdx.x;   // float4 index, BB*NN*CI/4 total
    const int row = idx >> 5;                          // CI/4 = 32 groups per row
    const float l = g_lp[row] + g_lp[BB * NN + row];
    const float inv = 1.0f / l;
    float4 a = ((const float4*)g_Op)[idx];
    float4 c = ((const float4*)(g_Op + (size_t)BB * NN * CI))[idx];
    float y0 = (a.x + c.x) * inv, y1 = (a.y + c.y) * inv;
    float y2 = (a.z + c.z) * inv, y3 = (a.w + c.w) * inv;
    uint h01 = pack2(y0, y1), h23 = pack2(y2, y3);
    float e0 = y0 - __uint_as_float(h01 << 16);
    float e1 = y1 - __uint_as_float(h01 & 0xffff0000u);
    float e2 = y2 - __uint_as_float(h23 << 16);
    float e3 = y3 - __uint_as_float(h23 & 0xffff0000u);
    ((uint2*)g_Yh)[idx] = make_uint2(h01, h23);
    ((uint2*)g_Yl)[idx] = make_uint2(pack2(e0, e1), pack2(e2, e3));
}

// ---------------- kernel 3: mma wgemm: WY[b][n][o] = Y[n][:]·Ww[o][:] + Wb[o] ----------------
#define WG_YH 0
#define WG_YL 34816
#define WG_WH 69632
#define WG_WL 104448
#define WG_SMEM 139264

extern __shared__ char sm_w[];

__global__ void __launch_bounds__(256, 1) wgemm_kernel(const float* __restrict__ Wb)
{
    const int b  = blockIdx.z;
    const int oh = blockIdx.y;
    const int n0 = blockIdx.x * 128;
    const int tid = threadIdx.x;
    const int lane = tid & 31, warp = tid >> 5;
    const uint sb = smem_u32(sm_w);

    {
        const char* yh = (const char*)(g_Yh + (size_t)(b * NN + n0) * CI);
        const char* yl = (const char*)(g_Yl + (size_t)(b * NN + n0) * CI);
        const char* wh = (const char*)(g_Wwh + (size_t)(oh * 128) * CI);
        const char* wl = (const char*)(g_Wwl + (size_t)(oh * 128) * CI);
#pragma unroll
        for (int it = 0; it < 8; it++) {
            int u = tid + it * 256;
            int row = u >> 4, ch = u & 15;
            cpa16(sb + WG_YH + row * 272 + ch * 16, yh + (size_t)row * 256 + ch * 16);
            cpa16(sb + WG_YL + row * 272 + ch * 16, yl + (size_t)row * 256 + ch * 16);
            cpa16(sb + WG_WH + row * 272 + ch * 16, wh + (size_t)row * 256 + ch * 16);
            cpa16(sb + WG_WL + row * 272 + ch * 16, wl + (size_t)row * 256 + ch * 16);
        }
    }
    CP_COMMIT();
    CP_WAIT0();
    __syncthreads();

    const int r0 = warp * 16 + (lane >> 2);
    float acc[16][4];
#pragma unroll
    for (int i = 0; i < 16; i++)
#pragma unroll
        for (int c = 0; c < 4; c++) acc[i][c] = 0.f;

#pragma unroll
    for (int kt = 0; kt < 8; kt++) {
        int kk2 = (kt * 16 + (lane & 3) * 2) * 2;
        uint ah0 = *(const uint*)(sm_w + WG_YH + r0 * 272 + kk2);
        uint ah1 = *(const uint*)(sm_w + WG_YH + (r0 + 8) * 272 + kk2);
        uint ah2 = *(const uint*)(sm_w + WG_YH + r0 * 272 + kk2 + 16);
        uint ah3 = *(const uint*)(sm_w + WG_YH + (r0 + 8) * 272 + kk2 + 16);
        uint al0 = *(const uint*)(sm_w + WG_YL + r0 * 272 + kk2);
        uint al1 = *(const uint*)(sm_w + WG_YL + (r0 + 8) * 272 + kk2);
        uint al2 = *(const uint*)(sm_w + WG_YL + r0 * 272 + kk2 + 16);
        uint al3 = *(const uint*)(sm_w + WG_YL + (r0 + 8) * 272 + kk2 + 16);
#pragma unroll
        for (int ot = 0; ot < 16; ot++) {
            int j = ot * 8 + (lane >> 2);
            uint bh0 = *(const uint*)(sm_w + WG_WH + j * 272 + kk2);
            uint bh1 = *(const uint*)(sm_w + WG_WH + j * 272 + kk2 + 16);
            uint bl0 = *(const uint*)(sm_w + WG_WL + j * 272 + kk2);
            uint bl1 = *(const uint*)(sm_w + WG_WL + j * 272 + kk2 + 16);
            mma_bf(acc[ot][0], acc[ot][1], acc[ot][2], acc[ot][3],
                   ah0, ah1, ah2, ah3, bh0, bh1);
            mma_bf(acc[ot][0], acc[ot][1], acc[ot][2], acc[ot][3],
                   ah0, ah1, ah2, ah3, bl0, bl1);
            mma_bf(acc[ot][0], acc[ot][1], acc[ot][2], acc[ot][3],
                   al0, al1, al2, al3, bh0, bh1);
        }
    }

    float* wy = g_WY + (size_t)(b * NN + n0) * CC + oh * 128;
#pragma unroll
    for (int ot = 0; ot < 16; ot++) {
        int o = ot * 8 + (lane & 3) * 2;
        float b0 = Wb[oh * 128 + o], b1 = Wb[oh * 128 + o + 1];
        *(float2*)(wy + (size_t)r0 * CC + o) = make_float2(acc[ot][0] + b0, acc[ot][1] + b1);
        *(float2*)(wy + (size_t)(r0 + 8) * CC + o) = make_float2(acc[ot][2] + b0, acc[ot][3] + b1);
    }
}

// ---------------- kernel 4a/4b: deterministic BN stats ----------------
__global__ void __launch_bounds__(256) stats1_kernel()
{
    const int blk = blockIdx.x;
    const int t = threadIdx.x;
    float s = 0.f, q = 0.f;
    const float* base = g_WY + (size_t)blk * 128 * CC + t;
    for (int r = 0; r < 128; r++) {
        float v = base[(size_t)r * CC];
        s += v; q += v * v;
    }
    g_psum[blk * CC + t] = s;
    g_psq [blk * CC + t] = q;
}
__global__ void __launch_bounds__(256) stats2_kernel()
{
    const int t = threadIdx.x;
    float s = 0.f, q = 0.f;
    for (int p = 0; p < 128; p++) {
        s += g_psum[p * CC + t];
        q += g_psq [p * CC + t];
    }
    const float invn = 1.0f / (float)(BB * NN);
    float mean = s * invn;
    float var  = q * invn - mean * mean;
    g_mean[t] = mean;
    g_rstd[t] = rsqrtf(var + BN_EPS);
}

// ---------------- kernel 5: BN apply + scale + residual (with transpose) ----------------
__global__ void __launch_bounds__(256) apply_kernel(
    const float* __restrict__ x,
    const float* __restrict__ gamma, const float* __restrict__ beta,
    const float* __restrict__ scale, float* __restrict__ out)
{
    __shared__ float st[64 * 65];
    const int n0 = blockIdx.x * 64;
    const int c0 = blockIdx.y * 64;
    const int b  = blockIdx.z;
    const int tid = threadIdx.x;
    const float s = scale[0];

#pragma unroll
    for (int r = 0; r < 16; r++) {
        int idx = tid + r * 256;
        int nl = idx >> 6, cc = idx & 63;
        st[cc * 65 + nl] = g_WY[((size_t)(b * NN + n0 + nl)) * CC + c0 + cc];
    }
    __syncthreads();
#pragma unroll
    for (int r = 0; r < 16; r++) {
        int idx = tid + r * 256;
        int cc = idx >> 6, nl = idx & 63;
        int c = c0 + cc;
        float wv = st[cc * 65 + nl];
        float v = s * ((wv - g_mean[c]) * g_rstd[c] * gamma[c] + beta[c])
                + x[((size_t)(b * CC + c)) * NN + n0 + nl];
        out[((size_t)(b * CC + c)) * NN + n0 + nl] = v;
    }
}

// ---------------- launcher ----------------
extern "C" void kernel_launch(void* const* d_in, const int* in_sizes, int n_in,
                              void* d_out, int out_size)
{
    const float* x     = (const float*)d_in[0];
    const float* gw    = (const float*)d_in[1];
    const float* gb    = (const float*)d_in[2];
    const float* tw    = (const float*)d_in[3];
    const float* tb    = (const float*)d_in[4];
    const float* pw    = (const float*)d_in[5];
    const float* pb    = (const float*)d_in[6];
    const float* Ww    = (const float*)d_in[7];
    const float* Wb    = (const float*)d_in[8];
    const float* gamma = (const float*)d_in[9];
    const float* beta  = (const float*)d_in[10];
    const float* scale = (const float*)d_in[11];
    float* out = (float*)d_out;

    cudaFuncSetAttribute(proj_kernel,
                         cudaFuncAttributeMaxDynamicSharedMemorySize, PROJ_SMEM);
    cudaFuncSetAttribute(attn_kernel,
                         cudaFuncAttributeMaxDynamicSharedMemorySize, ATTN_SMEM);
    cudaFuncSetAttribute(wgemm_kernel,
                         cudaFuncAttributeMaxDynamicSharedMemorySize, WG_SMEM);

    xcvt_kernel<<<dim3(NN / 64, CC / 64, BB), 256>>>(x);
    wcvt_kernel<<<64, 256>>>(gw, tw, pw, Ww);
    proj_kernel<<<dim3(NN / 128, BB, 3), 256, PROJ_SMEM>>>(gb, tb, pb);
    attn_kernel<<<dim3(NN / 128, BB, 2), 256, ATTN_SMEM>>>();
    combine_kernel<<<BB * NN * CI / 4 / 256, 256>>>();
    wgemm_kernel<<<dim3(NN / 128, 2, BB), 256, WG_SMEM>>>(Wb);
    stats1_kernel<<<128, 256>>>();
    stats2_kernel<<<1, 256>>>();
    apply_kernel<<<dim3(NN / 64, CC / 64, BB), 256>>>(x, gamma, beta, scale, out);
}

// round 9
// speedup vs baseline: 4.9705x; 1.0402x over previous
#include <cuda_runtime.h>

#define BB 4
#define CC 256
#define CI 128
#define NN 4096
#define BN_EPS 1e-5f

typedef unsigned int uint;
typedef unsigned short ushort;

// ---------------- scratch (no allocations allowed) ----------------
__device__ __align__(16) ushort g_Xh[BB * NN * CC];   // x^T hi [b][n][c]
__device__ __align__(16) ushort g_Xl[BB * NN * CC];
__device__ __align__(16) ushort g_PWh[3 * CI * CC];   // proj weights hi (g, theta, phi) [which][o][c]
__device__ __align__(16) ushort g_PWl[3 * CI * CC];
__device__ __align__(16) ushort g_Wwh[CC * CI];       // W conv weight hi [o][d]
__device__ __align__(16) ushort g_Wwl[CC * CI];
__device__ __align__(16) ushort g_Qh[BB * NN * CI];   // theta hi  [b][n][d]
__device__ __align__(16) ushort g_Ql[BB * NN * CI];
__device__ __align__(16) ushort g_Kh[BB * NN * CI];   // phi hi    [b][m][d]
__device__ __align__(16) ushort g_Kl[BB * NN * CI];
__device__ __align__(16) ushort g_Gth[BB * CI * NN];  // g^T hi    [b][d][m]
__device__ __align__(16) float g_Op[2 * BB * NN * CI]; // partial O (unnormalized), z slabs
__device__ __align__(16) float g_lp[2 * BB * NN];      // partial l
__device__ __align__(16) ushort g_Yh[BB * NN * CI];   // attention out hi [b][n][d]
__device__ __align__(16) ushort g_Yl[BB * NN * CI];
__device__ __align__(16) float g_WY[BB * NN * CC];    // W conv out [b][n][o]
__device__ __align__(16) float g_psum[128 * CC];
__device__ __align__(16) float g_psq [128 * CC];
__device__ float g_mean[CC];
__device__ float g_rstd[CC];

// ---------------- helpers ----------------
__device__ __forceinline__ ushort bf16rn(float v) {
    uint u = __float_as_uint(v);
    return (ushort)((u + 0x7FFFu + ((u >> 16) & 1u)) >> 16);
}
__device__ __forceinline__ uint smem_u32(const void* p) {
    uint a;
    asm("{ .reg .u64 t; cvta.to.shared.u64 t, %1; cvt.u32.u64 %0, t; }" : "=r"(a) : "l"(p));
    return a;
}
__device__ __forceinline__ void cpa16(uint s, const void* g) {
    asm volatile("cp.async.cg.shared.global [%0], [%1], 16;" :: "r"(s), "l"(g) : "memory");
}
#define CP_COMMIT() asm volatile("cp.async.commit_group;" ::: "memory")
#define CP_WAIT0()  asm volatile("cp.async.wait_group 0;" ::: "memory")
#define CP_WAIT1()  asm volatile("cp.async.wait_group 1;" ::: "memory")

#define LDSM4(r0, r1, r2, r3, addr) \
    asm volatile("ldmatrix.sync.aligned.m8n8.x4.shared.b16 {%0,%1,%2,%3}, [%4];" \
        : "=r"(r0), "=r"(r1), "=r"(r2), "=r"(r3) : "r"(addr))

// pack2(lo, hi): bf16x2 with lo in low half
__device__ __forceinline__ uint pack2(float lo, float hi) {
    uint r;
    asm("cvt.rn.bf16x2.f32 %0, %1, %2;" : "=r"(r) : "f"(hi), "f"(lo));
    return r;
}
__device__ __forceinline__ void mma_bf(float& d0, float& d1, float& d2, float& d3,
                                       uint a0, uint a1, uint a2, uint a3,
                                       uint b0, uint b1) {
    asm volatile("mma.sync.aligned.m16n8k16.row.col.f32.bf16.bf16.f32 "
        "{%0,%1,%2,%3},{%4,%5,%6,%7},{%8,%9},{%0,%1,%2,%3};"
        : "+f"(d0), "+f"(d1), "+f"(d2), "+f"(d3)
        : "r"(a0), "r"(a1), "r"(a2), "r"(a3), "r"(b0), "r"(b1));
}

// ---------------- kernel 0a: transpose + split x -> bf16 hi/lo [b][n][c] ----------------
__global__ void __launch_bounds__(256) xcvt_kernel(const float* __restrict__ x)
{
    __shared__ float st[64 * 65];
    const int n0 = blockIdx.x * 64;
    const int c0 = blockIdx.y * 64;
    const int b  = blockIdx.z;
    const int tid = threadIdx.x;
#pragma unroll
    for (int r = 0; r < 16; r++) {
        int idx = tid + r * 256;
        int cc = idx >> 6, nl = idx & 63;
        st[nl * 65 + cc] = x[((size_t)(b * CC + c0 + cc)) * NN + n0 + nl];
    }
    __syncthreads();
#pragma unroll
    for (int r = 0; r < 16; r++) {
        int idx = tid + r * 256;
        int nl = idx >> 6, cc = idx & 63;
        float v = st[nl * 65 + cc];
        ushort h = bf16rn(v);
        ushort l = bf16rn(v - __uint_as_float(((uint)h) << 16));
        size_t o = ((size_t)(b * NN + n0 + nl)) * CC + c0 + cc;
        g_Xh[o] = h;
        g_Xl[o] = l;
    }
}

// ---------------- kernel 0b: split weights -> bf16 hi/lo ----------------
__global__ void __launch_bounds__(256) wcvt_kernel(
    const float* __restrict__ gw, const float* __restrict__ tw,
    const float* __restrict__ pw, const float* __restrict__ Ww)
{
    const int total = 3 * CI * CC + CC * CI;
    for (int idx = blockIdx.x * 256 + threadIdx.x; idx < total; idx += gridDim.x * 256) {
        float v;
        if (idx < 3 * CI * CC) {
            int which = idx / (CI * CC), r = idx % (CI * CC);
            v = (which == 0 ? gw : which == 1 ? tw : pw)[r];
            ushort h = bf16rn(v);
            g_PWh[idx] = h;
            g_PWl[idx] = bf16rn(v - __uint_as_float(((uint)h) << 16));
        } else {
            int r = idx - 3 * CI * CC;
            v = Ww[r];
            ushort h = bf16rn(v);
            g_Wwh[r] = h;
            g_Wwl[r] = bf16rn(v - __uint_as_float(((uint)h) << 16));
        }
    }
}

// ---------------- kernel 1: mma projections ----------------
#define PJ_XH(buf) ((buf) * 73728)
#define PJ_XL(buf) ((buf) * 73728 + 18432)
#define PJ_WH(buf) ((buf) * 73728 + 36864)
#define PJ_WL(buf) ((buf) * 73728 + 55296)
#define PROJ_SMEM (2 * 73728)

extern __shared__ char sm_p[];

__global__ void __launch_bounds__(256, 1) proj_kernel(
    const float* __restrict__ gb_, const float* __restrict__ tb_,
    const float* __restrict__ pb_)
{
    const int b  = blockIdx.y;
    const int n0 = blockIdx.x * 128;
    const int which = blockIdx.z;              // 0=g->Gt(hi only), 1=theta->Q, 2=phi->K
    const int tid = threadIdx.x;
    const int lane = tid & 31, warp = tid >> 5;
    const uint sb = smem_u32(sm_p);
    const float* bias = (which == 0) ? gb_ : (which == 1) ? tb_ : pb_;

    const char* Xh_g = (const char*)(g_Xh + (size_t)(b * NN + n0) * CC);
    const char* Xl_g = (const char*)(g_Xl + (size_t)(b * NN + n0) * CC);
    const char* Wh_g = (const char*)(g_PWh + which * CI * CC);
    const char* Wl_g = (const char*)(g_PWl + which * CI * CC);

    auto load_chunk = [&](int ch) {
        if (ch < 4) {
            int buf = ch & 1;
            int cb = ch * 128;
#pragma unroll
            for (int it = 0; it < 4; it++) {
                int u = tid + it * 256;
                int row = u >> 3, seg = u & 7;
                cpa16(sb + PJ_XH(buf) + row * 144 + seg * 16, Xh_g + (size_t)row * 512 + cb + seg * 16);
                cpa16(sb + PJ_XL(buf) + row * 144 + seg * 16, Xl_g + (size_t)row * 512 + cb + seg * 16);
                cpa16(sb + PJ_WH(buf) + row * 144 + seg * 16, Wh_g + (size_t)row * 512 + cb + seg * 16);
                cpa16(sb + PJ_WL(buf) + row * 144 + seg * 16, Wl_g + (size_t)row * 512 + cb + seg * 16);
            }
        }
        CP_COMMIT();
    };

    load_chunk(0);
    load_chunk(1);

    const int r0 = warp * 16 + (lane >> 2);
    float acc[16][4];
#pragma unroll
    for (int i = 0; i < 16; i++)
#pragma unroll
        for (int c = 0; c < 4; c++) acc[i][c] = 0.f;

    // ldmatrix per-thread invariant offsets (144B row stride)
    const uint qoff144 = (uint)(warp * 16 + (lane & 15)) * 144 + ((lane >> 4) << 4);
    const uint koff144 = (uint)((lane & 7) + ((lane >> 4) << 3)) * 144 + (((lane >> 3) & 1) << 4);

    for (int ch = 0; ch < 4; ch++) {
        CP_WAIT1();
        __syncthreads();
        int buf = ch & 1;
#pragma unroll
        for (int kt = 0; kt < 4; kt++) {
            uint ah0, ah1, ah2, ah3, al0, al1, al2, al3;
            LDSM4(ah0, ah1, ah2, ah3, sb + PJ_XH(buf) + qoff144 + kt * 32);
            LDSM4(al0, al1, al2, al3, sb + PJ_XL(buf) + qoff144 + kt * 32);
#pragma unroll
            for (int op = 0; op < 8; op++) {
                uint bh0, bh1, bh2, bh3, bl0, bl1, bl2, bl3;
                LDSM4(bh0, bh1, bh2, bh3, sb + PJ_WH(buf) + koff144 + (uint)op * 16 * 144 + kt * 32);
                LDSM4(bl0, bl1, bl2, bl3, sb + PJ_WL(buf) + koff144 + (uint)op * 16 * 144 + kt * 32);
                mma_bf(acc[2*op][0], acc[2*op][1], acc[2*op][2], acc[2*op][3],
                       ah0, ah1, ah2, ah3, bh0, bh1);
                mma_bf(acc[2*op][0], acc[2*op][1], acc[2*op][2], acc[2*op][3],
                       ah0, ah1, ah2, ah3, bl0, bl1);
                mma_bf(acc[2*op][0], acc[2*op][1], acc[2*op][2], acc[2*op][3],
                       al0, al1, al2, al3, bh0, bh1);
                mma_bf(acc[2*op+1][0], acc[2*op+1][1], acc[2*op+1][2], acc[2*op+1][3],
                       ah0, ah1, ah2, ah3, bh2, bh3);
                mma_bf(acc[2*op+1][0], acc[2*op+1][1], acc[2*op+1][2], acc[2*op+1][3],
                       ah0, ah1, ah2, ah3, bl2, bl3);
                mma_bf(acc[2*op+1][0], acc[2*op+1][1], acc[2*op+1][2], acc[2*op+1][3],
                       al0, al1, al2, al3, bh2, bh3);
            }
        }
        __syncthreads();
        load_chunk(ch + 2);
    }
    CP_WAIT0();

#pragma unroll
    for (int ot = 0; ot < 16; ot++) {
        int o = ot * 8 + (lane & 3) * 2;
        float b0 = bias[o], b1 = bias[o + 1];
        acc[ot][0] += b0; acc[ot][1] += b1;
        acc[ot][2] += b0; acc[ot][3] += b1;
    }

    if (which != 0) {
        uint* dh = (uint*)((which == 1) ? g_Qh : g_Kh) + (size_t)(b * NN + n0) * (CI / 2);
        uint* dl = (uint*)((which == 1) ? g_Ql : g_Kl) + (size_t)(b * NN + n0) * (CI / 2);
#pragma unroll
        for (int ot = 0; ot < 16; ot++) {
            uint i0 = (uint)r0 * 64 + ot * 4 + (lane & 3);
            uint i1 = i0 + 8 * 64;
            uint h0 = pack2(acc[ot][0], acc[ot][1]);
            uint h1 = pack2(acc[ot][2], acc[ot][3]);
            float e0 = acc[ot][0] - __uint_as_float(h0 << 16);
            float e1 = acc[ot][1] - __uint_as_float(h0 & 0xffff0000u);
            float e2 = acc[ot][2] - __uint_as_float(h1 << 16);
            float e3 = acc[ot][3] - __uint_as_float(h1 & 0xffff0000u);
            dh[i0] = h0; dl[i0] = pack2(e0, e1);
            dh[i1] = h1; dl[i1] = pack2(e2, e3);
        }
    } else {
        ushort* st = (ushort*)sm_p;
        __syncthreads();
#pragma unroll
        for (int ot = 0; ot < 16; ot++) {
            int o = ot * 8 + (lane & 3) * 2;
#pragma unroll
            for (int c = 0; c < 4; c++) {
                int oo = o + (c & 1);
                int rr = (c < 2) ? r0 : (r0 + 8);
                st[oo * 136 + rr] = bf16rn(acc[ot][c]);
            }
        }
        __syncthreads();
#pragma unroll
        for (int it = 0; it < 8; it++) {
            int u = tid + it * 256;
            int o = u >> 4, seg = u & 15;
            *(uint4*)((char*)g_Gth + (((size_t)(b * CI + o)) * NN + n0) * 2 + seg * 16)
                = *(const uint4*)((const char*)st + o * 272 + seg * 16);
        }
    }
}

// ---------------- kernel 2: mma.sync flash attention (split-K, ldmatrix) ----------------
#define SQH 0
#define SQL 34816
#define SKH(s) (69632 + (s) * 17408)
#define SKL(s) (104448 + (s) * 17408)
#define SGH(s) (139264 + (s) * 18432)
#define ATTN_SMEM 176128
#define KTILES 32

extern __shared__ char sm_a[];

__global__ void __launch_bounds__(256, 1) attn_kernel()
{
    const int b  = blockIdx.y;
    const int qt = blockIdx.x;
    const int z  = blockIdx.z;                 // key half
    const int tid = threadIdx.x;
    const int lane = tid & 31, warp = tid >> 5;
    const uint sb = smem_u32(sm_a);

    const size_t qbase = (size_t)(b * NN + qt * 128) * CI;
    const char* Qh_g = (const char*)(g_Qh + qbase);
    const char* Ql_g = (const char*)(g_Ql + qbase);
    const char* gh_g = (const char*)(g_Gth + (size_t)(b * CI) * NN);

#pragma unroll
    for (int it = 0; it < 8; it++) {
        int u = tid + it * 256;
        int row = u >> 4, ch = u & 15;
        cpa16(sb + SQH + row * 272 + ch * 16, Qh_g + row * 256 + ch * 16);
        cpa16(sb + SQL + row * 272 + ch * 16, Ql_g + row * 256 + ch * 16);
    }
#pragma unroll
    for (int s = 0; s < 2; s++) {
        int kt = z * KTILES + s;
        const char* khs = (const char*)(g_Kh + (size_t)(b * NN + kt * 64) * CI);
        const char* kls = (const char*)(g_Kl + (size_t)(b * NN + kt * 64) * CI);
#pragma unroll
        for (int it = 0; it < 4; it++) {
            int u = tid + it * 256;
            int row = u >> 4, ch = u & 15;
            cpa16(sb + SKH(s) + row * 272 + ch * 16, khs + row * 256 + ch * 16);
            cpa16(sb + SKL(s) + row * 272 + ch * 16, kls + row * 256 + ch * 16);
        }
#pragma unroll
        for (int it = 0; it < 4; it++) {
            int u = tid + it * 256;
            int row = u >> 3, ch = u & 7;
            cpa16(sb + SGH(s) + row * 144 + ch * 16, gh_g + (size_t)row * NN * 2 + kt * 128 + ch * 16);
        }
        CP_COMMIT();
    }

    const int r0 = warp * 16 + (lane >> 2);
    float o[16][4];
#pragma unroll
    for (int d = 0; d < 16; d++)
#pragma unroll
        for (int c = 0; c < 4; c++) o[d][c] = 0.f;
    float l0 = 0.f, l1 = 0.f;

    // ldmatrix per-thread invariant offsets
    const uint qoff = (uint)(warp * 16 + (lane & 15)) * 272 + ((lane >> 4) << 4);
    const uint koff = (uint)((lane & 7) + ((lane >> 4) << 3)) * 272 + (((lane >> 3) & 1) << 4);
    const uint goff = (uint)((lane & 7) + ((lane >> 4) << 3)) * 144 + (((lane >> 3) & 1) << 4);

    for (int t = 0; t < KTILES; t++) {
        CP_WAIT1();
        __syncthreads();
        const uint skh = sb + SKH(t & 1);
        const uint skl = sb + SKL(t & 1);
        const uint sgh = sb + SGH(t & 1);

        float acc[8][4];
#pragma unroll
        for (int nt = 0; nt < 8; nt++)
#pragma unroll
            for (int c = 0; c < 4; c++) acc[nt][c] = 0.f;

#pragma unroll
        for (int kt = 0; kt < 8; kt++) {
            uint ah0, ah1, ah2, ah3, al0, al1, al2, al3;
            LDSM4(ah0, ah1, ah2, ah3, sb + SQH + qoff + kt * 32);
            LDSM4(al0, al1, al2, al3, sb + SQL + qoff + kt * 32);
#pragma unroll
            for (int np = 0; np < 4; np++) {
                uint bh0, bh1, bh2, bh3, bl0, bl1, bl2, bl3;
                LDSM4(bh0, bh1, bh2, bh3, skh + koff + (uint)np * 16 * 272 + kt * 32);
                LDSM4(bl0, bl1, bl2, bl3, skl + koff + (uint)np * 16 * 272 + kt * 32);
                mma_bf(acc[2*np][0], acc[2*np][1], acc[2*np][2], acc[2*np][3],
                       ah0, ah1, ah2, ah3, bh0, bh1);
                mma_bf(acc[2*np][0], acc[2*np][1], acc[2*np][2], acc[2*np][3],
                       ah0, ah1, ah2, ah3, bl0, bl1);
                mma_bf(acc[2*np][0], acc[2*np][1], acc[2*np][2], acc[2*np][3],
                       al0, al1, al2, al3, bh0, bh1);
                mma_bf(acc[2*np+1][0], acc[2*np+1][1], acc[2*np+1][2], acc[2*np+1][3],
                       ah0, ah1, ah2, ah3, bh2, bh3);
                mma_bf(acc[2*np+1][0], acc[2*np+1][1], acc[2*np+1][2], acc[2*np+1][3],
                       ah0, ah1, ah2, ah3, bl2, bl3);
                mma_bf(acc[2*np+1][0], acc[2*np+1][1], acc[2*np+1][2], acc[2*np+1][3],
                       al0, al1, al2, al3, bh2, bh3);
            }
        }

        uint ph[8][2], pl[8][2];
#pragma unroll
        for (int nt = 0; nt < 8; nt++) {
            float p0 = __expf(acc[nt][0]);
            float p1 = __expf(acc[nt][1]);
            float p2 = __expf(acc[nt][2]);
            float p3 = __expf(acc[nt][3]);
            l0 += p0 + p1;
            l1 += p2 + p3;
            uint h01 = pack2(p0, p1);
            uint h23 = pack2(p2, p3);
            float e0 = p0 - __uint_as_float(h01 << 16);
            float e1 = p1 - __uint_as_float(h01 & 0xffff0000u);
            float e2 = p2 - __uint_as_float(h23 << 16);
            float e3 = p3 - __uint_as_float(h23 & 0xffff0000u);
            ph[nt][0] = h01; ph[nt][1] = h23;
            pl[nt][0] = pack2(e0, e1); pl[nt][1] = pack2(e2, e3);
        }

        // O += P_hi*G_hi + P_lo*G_hi
#pragma unroll
        for (int kt2 = 0; kt2 < 4; kt2++) {
            uint ah0 = ph[2 * kt2][0], ah1 = ph[2 * kt2][1];
            uint ah2 = ph[2 * kt2 + 1][0], ah3 = ph[2 * kt2 + 1][1];
            uint al0 = pl[2 * kt2][0], al1 = pl[2 * kt2][1];
            uint al2 = pl[2 * kt2 + 1][0], al3 = pl[2 * kt2 + 1][1];
#pragma unroll
            for (int dp = 0; dp < 8; dp++) {
                uint g0, g1, g2, g3;
                LDSM4(g0, g1, g2, g3, sgh + goff + (uint)dp * 16 * 144 + kt2 * 32);
                mma_bf(o[2*dp][0], o[2*dp][1], o[2*dp][2], o[2*dp][3],
                       ah0, ah1, ah2, ah3, g0, g1);
                mma_bf(o[2*dp][0], o[2*dp][1], o[2*dp][2], o[2*dp][3],
                       al0, al1, al2, al3, g0, g1);
                mma_bf(o[2*dp+1][0], o[2*dp+1][1], o[2*dp+1][2], o[2*dp+1][3],
                       ah0, ah1, ah2, ah3, g2, g3);
                mma_bf(o[2*dp+1][0], o[2*dp+1][1], o[2*dp+1][2], o[2*dp+1][3],
                       al0, al1, al2, al3, g2, g3);
            }
        }

        __syncthreads();
        if (t + 2 < KTILES) {
            int kt = z * KTILES + t + 2;
            int s = t & 1;
            const char* khs = (const char*)(g_Kh + (size_t)(b * NN + kt * 64) * CI);
            const char* kls = (const char*)(g_Kl + (size_t)(b * NN + kt * 64) * CI);
#pragma unroll
            for (int it = 0; it < 4; it++) {
                int u = tid + it * 256;
                int row = u >> 4, ch = u & 15;
                cpa16(sb + SKH(s) + row * 272 + ch * 16, khs + row * 256 + ch * 16);
                cpa16(sb + SKL(s) + row * 272 + ch * 16, kls + row * 256 + ch * 16);
            }
#pragma unroll
            for (int it = 0; it < 4; it++) {
                int u = tid + it * 256;
                int row = u >> 3, ch = u & 7;
                cpa16(sb + SGH(s) + row * 144 + ch * 16, gh_g + (size_t)row * NN * 2 + kt * 128 + ch * 16);
            }
        }
        CP_COMMIT();
    }

    // epilogue: quad-reduce l, write partial O + partial l
    l0 += __shfl_xor_sync(0xffffffffu, l0, 1);
    l0 += __shfl_xor_sync(0xffffffffu, l0, 2);
    l1 += __shfl_xor_sync(0xffffffffu, l1, 1);
    l1 += __shfl_xor_sync(0xffffffffu, l1, 2);

    float* obase = g_Op + ((size_t)(z * BB + b) * NN + qt * 128) * CI;
#pragma unroll
    for (int dn = 0; dn < 16; dn++) {
        int col = dn * 8 + (lane & 3) * 2;
        *(float2*)(obase + (size_t)r0 * CI + col) = make_float2(o[dn][0], o[dn][1]);
        *(float2*)(obase + (size_t)(r0 + 8) * CI + col) = make_float2(o[dn][2], o[dn][3]);
    }
    if ((lane & 3) == 0) {
        g_lp[(size_t)(z * BB + b) * NN + qt * 128 + r0] = l0;
        g_lp[(size_t)(z * BB + b) * NN + qt * 128 + r0 + 8] = l1;
    }
}

// ---------------- kernel 2b: combine key-halves, emit Y bf16 hi/lo ----------------
__global__ void __launch_bounds__(256) combine_kernel()
{
    const int idx = blockIdx.x * 256 + threadIdx.x;
    const int row = idx >> 5;
    const float l = g_lp[row] + g_lp[BB * NN + row];
    const float inv = 1.0f / l;
    float4 a = ((const float4*)g_Op)[idx];
    float4 c = ((const float4*)(g_Op + (size_t)BB * NN * CI))[idx];
    float y0 = (a.x + c.x) * inv, y1 = (a.y + c.y) * inv;
    float y2 = (a.z + c.z) * inv, y3 = (a.w + c.w) * inv;
    uint h01 = pack2(y0, y1), h23 = pack2(y2, y3);
    float e0 = y0 - __uint_as_float(h01 << 16);
    float e1 = y1 - __uint_as_float(h01 & 0xffff0000u);
    float e2 = y2 - __uint_as_float(h23 << 16);
    float e3 = y3 - __uint_as_float(h23 & 0xffff0000u);
    ((uint2*)g_Yh)[idx] = make_uint2(h01, h23);
    ((uint2*)g_Yl)[idx] = make_uint2(pack2(e0, e1), pack2(e2, e3));
}

// ---------------- kernel 3: mma wgemm (ldmatrix) ----------------
#define WG_YH 0
#define WG_YL 34816
#define WG_WH 69632
#define WG_WL 104448
#define WG_SMEM 139264

extern __shared__ char sm_w[];

__global__ void __launch_bounds__(256, 1) wgemm_kernel(const float* __restrict__ Wb)
{
    const int b  = blockIdx.z;
    const int oh = blockIdx.y;
    const int n0 = blockIdx.x * 128;
    const int tid = threadIdx.x;
    const int lane = tid & 31, warp = tid >> 5;
    const uint sb = smem_u32(sm_w);

    {
        const char* yh = (const char*)(g_Yh + (size_t)(b * NN + n0) * CI);
        const char* yl = (const char*)(g_Yl + (size_t)(b * NN + n0) * CI);
        const char* wh = (const char*)(g_Wwh + (size_t)(oh * 128) * CI);
        const char* wl = (const char*)(g_Wwl + (size_t)(oh * 128) * CI);
#pragma unroll
        for (int it = 0; it < 8; it++) {
            int u = tid + it * 256;
            int row = u >> 4, ch = u & 15;
            cpa16(sb + WG_YH + row * 272 + ch * 16, yh + (size_t)row * 256 + ch * 16);
            cpa16(sb + WG_YL + row * 272 + ch * 16, yl + (size_t)row * 256 + ch * 16);
            cpa16(sb + WG_WH + row * 272 + ch * 16, wh + (size_t)row * 256 + ch * 16);
            cpa16(sb + WG_WL + row * 272 + ch * 16, wl + (size_t)row * 256 + ch * 16);
        }
    }
    CP_COMMIT();
    CP_WAIT0();
    __syncthreads();

    const int r0 = warp * 16 + (lane >> 2);
    float acc[16][4];
#pragma unroll
    for (int i = 0; i < 16; i++)
#pragma unroll
        for (int c = 0; c < 4; c++) acc[i][c] = 0.f;

    const uint qoff = (uint)(warp * 16 + (lane & 15)) * 272 + ((lane >> 4) << 4);
    const uint koff = (uint)((lane & 7) + ((lane >> 4) << 3)) * 272 + (((lane >> 3) & 1) << 4);

#pragma unroll
    for (int kt = 0; kt < 8; kt++) {
        uint ah0, ah1, ah2, ah3, al0, al1, al2, al3;
        LDSM4(ah0, ah1, ah2, ah3, sb + WG_YH + qoff + kt * 32);
        LDSM4(al0, al1, al2, al3, sb + WG_YL + qoff + kt * 32);
#pragma unroll
        for (int op = 0; op < 8; op++) {
            uint bh0, bh1, bh2, bh3, bl0, bl1, bl2, bl3;
            LDSM4(bh0, bh1, bh2, bh3, sb + WG_WH + koff + (uint)op * 16 * 272 + kt * 32);
            LDSM4(bl0, bl1, bl2, bl3, sb + WG_WL + koff + (uint)op * 16 * 272 + kt * 32);
            mma_bf(acc[2*op][0], acc[2*op][1], acc[2*op][2], acc[2*op][3],
                   ah0, ah1, ah2, ah3, bh0, bh1);
            mma_bf(acc[2*op][0], acc[2*op][1], acc[2*op][2], acc[2*op][3],
                   ah0, ah1, ah2, ah3, bl0, bl1);
            mma_bf(acc[2*op][0], acc[2*op][1], acc[2*op][2], acc[2*op][3],
                   al0, al1, al2, al3, bh0, bh1);
            mma_bf(acc[2*op+1][0], acc[2*op+1][1], acc[2*op+1][2], acc[2*op+1][3],
                   ah0, ah1, ah2, ah3, bh2, bh3);
            mma_bf(acc[2*op+1][0], acc[2*op+1][1], acc[2*op+1][2], acc[2*op+1][3],
                   ah0, ah1, ah2, ah3, bl2, bl3);
            mma_bf(acc[2*op+1][0], acc[2*op+1][1], acc[2*op+1][2], acc[2*op+1][3],
                   al0, al1, al2, al3, bh2, bh3);
        }
    }

    float* wy = g_WY + (size_t)(b * NN + n0) * CC + oh * 128;
#pragma unroll
    for (int ot = 0; ot < 16; ot++) {
        int o = ot * 8 + (lane & 3) * 2;
        float b0 = Wb[oh * 128 + o], b1 = Wb[oh * 128 + o + 1];
        *(float2*)(wy + (size_t)r0 * CC + o) = make_float2(acc[ot][0] + b0, acc[ot][1] + b1);
        *(float2*)(wy + (size_t)(r0 + 8) * CC + o) = make_float2(acc[ot][2] + b0, acc[ot][3] + b1);
    }
}

// ---------------- kernel 4a/4b: deterministic BN stats ----------------
__global__ void __launch_bounds__(256) stats1_kernel()
{
    const int blk = blockIdx.x;
    const int t = threadIdx.x;
    float s = 0.f, q = 0.f;
    const float* base = g_WY + (size_t)blk * 128 * CC + t;
    for (int r = 0; r < 128; r++) {
        float v = base[(size_t)r * CC];
        s += v; q += v * v;
    }
    g_psum[blk * CC + t] = s;
    g_psq [blk * CC + t] = q;
}
__global__ void __launch_bounds__(256) stats2_kernel()
{
    const int t = threadIdx.x;
    float s = 0.f, q = 0.f;
    for (int p = 0; p < 128; p++) {
        s += g_psum[p * CC + t];
        q += g_psq [p * CC + t];
    }
    const float invn = 1.0f / (float)(BB * NN);
    float mean = s * invn;
    float var  = q * invn - mean * mean;
    g_mean[t] = mean;
    g_rstd[t] = rsqrtf(var + BN_EPS);
}

// ---------------- kernel 5: BN apply + scale + residual (with transpose) ----------------
__global__ void __launch_bounds__(256) apply_kernel(
    const float* __restrict__ x,
    const float* __restrict__ gamma, const float* __restrict__ beta,
    const float* __restrict__ scale, float* __restrict__ out)
{
    __shared__ float st[64 * 65];
    const int n0 = blockIdx.x * 64;
    const int c0 = blockIdx.y * 64;
    const int b  = blockIdx.z;
    const int tid = threadIdx.x;
    const float s = scale[0];

#pragma unroll
    for (int r = 0; r < 16; r++) {
        int idx = tid + r * 256;
        int nl = idx >> 6, cc = idx & 63;
        st[cc * 65 + nl] = g_WY[((size_t)(b * NN + n0 + nl)) * CC + c0 + cc];
    }
    __syncthreads();
#pragma unroll
    for (int r = 0; r < 16; r++) {
        int idx = tid + r * 256;
        int cc = idx >> 6, nl = idx & 63;
        int c = c0 + cc;
        float wv = st[cc * 65 + nl];
        float v = s * ((wv - g_mean[c]) * g_rstd[c] * gamma[c] + beta[c])
                + x[((size_t)(b * CC + c)) * NN + n0 + nl];
        out[((size_t)(b * CC + c)) * NN + n0 + nl] = v;
    }
}

// ---------------- launcher ----------------
extern "C" void kernel_launch(void* const* d_in, const int* in_sizes, int n_in,
                              void* d_out, int out_size)
{
    const float* x     = (const float*)d_in[0];
    const float* gw    = (const float*)d_in[1];
    const float* gb    = (const float*)d_in[2];
    const float* tw    = (const float*)d_in[3];
    const float* tb    = (const float*)d_in[4];
    const float* pw    = (const float*)d_in[5];
    const float* pb    = (const float*)d_in[6];
    const float* Ww    = (const float*)d_in[7];
    const float* Wb    = (const float*)d_in[8];
    const float* gamma = (const float*)d_in[9];
    const float* beta  = (const float*)d_in[10];
    const float* scale = (const float*)d_in[11];
    float* out = (float*)d_out;

    cudaFuncSetAttribute(proj_kernel,
                         cudaFuncAttributeMaxDynamicSharedMemorySize, PROJ_SMEM);
    cudaFuncSetAttribute(attn_kernel,
                         cudaFuncAttributeMaxDynamicSharedMemorySize, ATTN_SMEM);
    cudaFuncSetAttribute(wgemm_kernel,
                         cudaFuncAttributeMaxDynamicSharedMemorySize, WG_SMEM);

    xcvt_kernel<<<dim3(NN / 64, CC / 64, BB), 256>>>(x);
    wcvt_kernel<<<64, 256>>>(gw, tw, pw, Ww);
    proj_kernel<<<dim3(NN / 128, BB, 3), 256, PROJ_SMEM>>>(gb, tb, pb);
    attn_kernel<<<dim3(NN / 128, BB, 2), 256, ATTN_SMEM>>>();
    combine_kernel<<<BB * NN * CI / 4 / 256, 256>>>();
    wgemm_kernel<<<dim3(NN / 128, 2, BB), 256, WG_SMEM>>>(Wb);
    stats1_kernel<<<128, 256>>>();
    stats2_kernel<<<1, 256>>>();
    apply_kernel<<<dim3(NN / 64, CC / 64, BB), 256>>>(x, gamma, beta, scale, out);
}

// round 10
// speedup vs baseline: 5.0626x; 1.0185x over previous
#include <cuda_runtime.h>

#define BB 4
#define CC 256
#define CI 128
#define NN 4096
#define BN_EPS 1e-5f

typedef unsigned int uint;
typedef unsigned short ushort;

// ---------------- scratch (no allocations allowed) ----------------
__device__ __align__(16) ushort g_Xh[BB * NN * CC];   // x^T hi [b][n][c]
__device__ __align__(16) ushort g_Xl[BB * NN * CC];
__device__ __align__(16) ushort g_PWh[3 * CI * CC];   // proj weights hi (g, theta, phi) [which][o][c]
__device__ __align__(16) ushort g_PWl[3 * CI * CC];
__device__ __align__(16) ushort g_Wwh[CC * CI];       // W conv weight hi [o][d]
__device__ __align__(16) ushort g_Wwl[CC * CI];
__device__ __align__(16) ushort g_Qh[BB * NN * CI];   // theta hi  [b][n][d]
__device__ __align__(16) ushort g_Ql[BB * NN * CI];
__device__ __align__(16) ushort g_Kh[BB * NN * CI];   // phi hi    [b][m][d]
__device__ __align__(16) ushort g_Kl[BB * NN * CI];
__device__ __align__(16) ushort g_Gth[BB * CI * NN];  // g^T hi    [b][d][m]
__device__ __align__(16) float g_Op[2 * BB * NN * CI]; // partial O (unnormalized), z slabs
__device__ __align__(16) float g_lp[2 * BB * NN];      // partial l
__device__ __align__(16) ushort g_Yh[BB * NN * CI];   // attention out hi [b][n][d]
__device__ __align__(16) ushort g_Yl[BB * NN * CI];
__device__ __align__(16) float g_WY[BB * NN * CC];    // W conv out [b][n][o]
__device__ __align__(16) float g_psum[128 * CC];
__device__ __align__(16) float g_psq [128 * CC];
__device__ float g_mean[CC];
__device__ float g_rstd[CC];

// ---------------- helpers ----------------
__device__ __forceinline__ ushort bf16rn(float v) {
    uint u = __float_as_uint(v);
    return (ushort)((u + 0x7FFFu + ((u >> 16) & 1u)) >> 16);
}
__device__ __forceinline__ uint smem_u32(const void* p) {
    uint a;
    asm("{ .reg .u64 t; cvta.to.shared.u64 t, %1; cvt.u32.u64 %0, t; }" : "=r"(a) : "l"(p));
    return a;
}
__device__ __forceinline__ void cpa16(uint s, const void* g) {
    asm volatile("cp.async.cg.shared.global [%0], [%1], 16;" :: "r"(s), "l"(g) : "memory");
}
#define CP_COMMIT() asm volatile("cp.async.commit_group;" ::: "memory")
#define CP_WAIT0()  asm volatile("cp.async.wait_group 0;" ::: "memory")
#define CP_WAIT1()  asm volatile("cp.async.wait_group 1;" ::: "memory")

#define LDSM4(r0, r1, r2, r3, addr) \
    asm volatile("ldmatrix.sync.aligned.m8n8.x4.shared.b16 {%0,%1,%2,%3}, [%4];" \
        : "=r"(r0), "=r"(r1), "=r"(r2), "=r"(r3) : "r"(addr))

// pack2(lo, hi): bf16x2 with lo in low half
__device__ __forceinline__ uint pack2(float lo, float hi) {
    uint r;
    asm("cvt.rn.bf16x2.f32 %0, %1, %2;" : "=r"(r) : "f"(hi), "f"(lo));
    return r;
}
__device__ __forceinline__ void mma_bf(float& d0, float& d1, float& d2, float& d3,
                                       uint a0, uint a1, uint a2, uint a3,
                                       uint b0, uint b1) {
    asm volatile("mma.sync.aligned.m16n8k16.row.col.f32.bf16.bf16.f32 "
        "{%0,%1,%2,%3},{%4,%5,%6,%7},{%8,%9},{%0,%1,%2,%3};"
        : "+f"(d0), "+f"(d1), "+f"(d2), "+f"(d3)
        : "r"(a0), "r"(a1), "r"(a2), "r"(a3), "r"(b0), "r"(b1));
}

// ---------------- kernel 0a: transpose + split x -> bf16 hi/lo [b][n][c] ----------------
__global__ void __launch_bounds__(256) xcvt_kernel(const float* __restrict__ x)
{
    __shared__ float st[64 * 65];
    const int n0 = blockIdx.x * 64;
    const int c0 = blockIdx.y * 64;
    const int b  = blockIdx.z;
    const int tid = threadIdx.x;
#pragma unroll
    for (int r = 0; r < 16; r++) {
        int idx = tid + r * 256;
        int cc = idx >> 6, nl = idx & 63;
        st[nl * 65 + cc] = x[((size_t)(b * CC + c0 + cc)) * NN + n0 + nl];
    }
    __syncthreads();
#pragma unroll
    for (int r = 0; r < 16; r++) {
        int idx = tid + r * 256;
        int nl = idx >> 6, cc = idx & 63;
        float v = st[nl * 65 + cc];
        ushort h = bf16rn(v);
        ushort l = bf16rn(v - __uint_as_float(((uint)h) << 16));
        size_t o = ((size_t)(b * NN + n0 + nl)) * CC + c0 + cc;
        g_Xh[o] = h;
        g_Xl[o] = l;
    }
}

// ---------------- kernel 0b: split weights -> bf16 hi/lo ----------------
__global__ void __launch_bounds__(256) wcvt_kernel(
    const float* __restrict__ gw, const float* __restrict__ tw,
    const float* __restrict__ pw, const float* __restrict__ Ww)
{
    const int total = 3 * CI * CC + CC * CI;
    for (int idx = blockIdx.x * 256 + threadIdx.x; idx < total; idx += gridDim.x * 256) {
        float v;
        if (idx < 3 * CI * CC) {
            int which = idx / (CI * CC), r = idx % (CI * CC);
            v = (which == 0 ? gw : which == 1 ? tw : pw)[r];
            ushort h = bf16rn(v);
            g_PWh[idx] = h;
            g_PWl[idx] = bf16rn(v - __uint_as_float(((uint)h) << 16));
        } else {
            int r = idx - 3 * CI * CC;
            v = Ww[r];
            ushort h = bf16rn(v);
            g_Wwh[r] = h;
            g_Wwl[r] = bf16rn(v - __uint_as_float(((uint)h) << 16));
        }
    }
}

// ---------------- kernel 1: mma projections ----------------
#define PJ_XH(buf) ((buf) * 73728)
#define PJ_XL(buf) ((buf) * 73728 + 18432)
#define PJ_WH(buf) ((buf) * 73728 + 36864)
#define PJ_WL(buf) ((buf) * 73728 + 55296)
#define PROJ_SMEM (2 * 73728)

extern __shared__ char sm_p[];

__global__ void __launch_bounds__(256, 1) proj_kernel(
    const float* __restrict__ gb_, const float* __restrict__ tb_,
    const float* __restrict__ pb_)
{
    const int b  = blockIdx.y;
    const int n0 = blockIdx.x * 128;
    const int which = blockIdx.z;              // 0=g->Gt(hi only), 1=theta->Q, 2=phi->K
    const int tid = threadIdx.x;
    const int lane = tid & 31, warp = tid >> 5;
    const uint sb = smem_u32(sm_p);
    const float* bias = (which == 0) ? gb_ : (which == 1) ? tb_ : pb_;

    const char* Xh_g = (const char*)(g_Xh + (size_t)(b * NN + n0) * CC);
    const char* Xl_g = (const char*)(g_Xl + (size_t)(b * NN + n0) * CC);
    const char* Wh_g = (const char*)(g_PWh + which * CI * CC);
    const char* Wl_g = (const char*)(g_PWl + which * CI * CC);

    auto load_chunk = [&](int ch) {
        if (ch < 4) {
            int buf = ch & 1;
            int cb = ch * 128;
#pragma unroll
            for (int it = 0; it < 4; it++) {
                int u = tid + it * 256;
                int row = u >> 3, seg = u & 7;
                cpa16(sb + PJ_XH(buf) + row * 144 + seg * 16, Xh_g + (size_t)row * 512 + cb + seg * 16);
                cpa16(sb + PJ_XL(buf) + row * 144 + seg * 16, Xl_g + (size_t)row * 512 + cb + seg * 16);
                cpa16(sb + PJ_WH(buf) + row * 144 + seg * 16, Wh_g + (size_t)row * 512 + cb + seg * 16);
                cpa16(sb + PJ_WL(buf) + row * 144 + seg * 16, Wl_g + (size_t)row * 512 + cb + seg * 16);
            }
        }
        CP_COMMIT();
    };

    load_chunk(0);
    load_chunk(1);

    const int r0 = warp * 16 + (lane >> 2);
    float acc[16][4];
#pragma unroll
    for (int i = 0; i < 16; i++)
#pragma unroll
        for (int c = 0; c < 4; c++) acc[i][c] = 0.f;

    // ldmatrix per-thread invariant offsets (144B row stride)
    const uint qoff144 = (uint)(warp * 16 + (lane & 15)) * 144 + ((lane >> 4) << 4);
    const uint koff144 = (uint)((lane & 7) + ((lane >> 4) << 3)) * 144 + (((lane >> 3) & 1) << 4);

    for (int ch = 0; ch < 4; ch++) {
        CP_WAIT1();
        __syncthreads();
        int buf = ch & 1;
#pragma unroll
        for (int kt = 0; kt < 4; kt++) {
            uint ah0, ah1, ah2, ah3, al0, al1, al2, al3;
            LDSM4(ah0, ah1, ah2, ah3, sb + PJ_XH(buf) + qoff144 + kt * 32);
            LDSM4(al0, al1, al2, al3, sb + PJ_XL(buf) + qoff144 + kt * 32);
#pragma unroll
            for (int op = 0; op < 8; op++) {
                uint bh0, bh1, bh2, bh3, bl0, bl1, bl2, bl3;
                LDSM4(bh0, bh1, bh2, bh3, sb + PJ_WH(buf) + koff144 + (uint)op * 16 * 144 + kt * 32);
                LDSM4(bl0, bl1, bl2, bl3, sb + PJ_WL(buf) + koff144 + (uint)op * 16 * 144 + kt * 32);
                mma_bf(acc[2*op][0], acc[2*op][1], acc[2*op][2], acc[2*op][3],
                       ah0, ah1, ah2, ah3, bh0, bh1);
                mma_bf(acc[2*op][0], acc[2*op][1], acc[2*op][2], acc[2*op][3],
                       ah0, ah1, ah2, ah3, bl0, bl1);
                mma_bf(acc[2*op][0], acc[2*op][1], acc[2*op][2], acc[2*op][3],
                       al0, al1, al2, al3, bh0, bh1);
                mma_bf(acc[2*op+1][0], acc[2*op+1][1], acc[2*op+1][2], acc[2*op+1][3],
                       ah0, ah1, ah2, ah3, bh2, bh3);
                mma_bf(acc[2*op+1][0], acc[2*op+1][1], acc[2*op+1][2], acc[2*op+1][3],
                       ah0, ah1, ah2, ah3, bl2, bl3);
                mma_bf(acc[2*op+1][0], acc[2*op+1][1], acc[2*op+1][2], acc[2*op+1][3],
                       al0, al1, al2, al3, bh2, bh3);
            }
        }
        __syncthreads();
        load_chunk(ch + 2);
    }
    CP_WAIT0();

#pragma unroll
    for (int ot = 0; ot < 16; ot++) {
        int o = ot * 8 + (lane & 3) * 2;
        float b0 = bias[o], b1 = bias[o + 1];
        acc[ot][0] += b0; acc[ot][1] += b1;
        acc[ot][2] += b0; acc[ot][3] += b1;
    }

    if (which != 0) {
        uint* dh = (uint*)((which == 1) ? g_Qh : g_Kh) + (size_t)(b * NN + n0) * (CI / 2);
        uint* dl = (uint*)((which == 1) ? g_Ql : g_Kl) + (size_t)(b * NN + n0) * (CI / 2);
#pragma unroll
        for (int ot = 0; ot < 16; ot++) {
            uint i0 = (uint)r0 * 64 + ot * 4 + (lane & 3);
            uint i1 = i0 + 8 * 64;
            uint h0 = pack2(acc[ot][0], acc[ot][1]);
            uint h1 = pack2(acc[ot][2], acc[ot][3]);
            float e0 = acc[ot][0] - __uint_as_float(h0 << 16);
            float e1 = acc[ot][1] - __uint_as_float(h0 & 0xffff0000u);
            float e2 = acc[ot][2] - __uint_as_float(h1 << 16);
            float e3 = acc[ot][3] - __uint_as_float(h1 & 0xffff0000u);
            dh[i0] = h0; dl[i0] = pack2(e0, e1);
            dh[i1] = h1; dl[i1] = pack2(e2, e3);
        }
    } else {
        ushort* st = (ushort*)sm_p;
        __syncthreads();
#pragma unroll
        for (int ot = 0; ot < 16; ot++) {
            int o = ot * 8 + (lane & 3) * 2;
#pragma unroll
            for (int c = 0; c < 4; c++) {
                int oo = o + (c & 1);
                int rr = (c < 2) ? r0 : (r0 + 8);
                st[oo * 136 + rr] = bf16rn(acc[ot][c]);
            }
        }
        __syncthreads();
#pragma unroll
        for (int it = 0; it < 8; it++) {
            int u = tid + it * 256;
            int o = u >> 4, seg = u & 15;
            *(uint4*)((char*)g_Gth + (((size_t)(b * CI + o)) * NN + n0) * 2 + seg * 16)
                = *(const uint4*)((const char*)st + o * 272 + seg * 16);
        }
    }
}

// ---------------- kernel 2: mma.sync flash attention (split-K, ldmatrix, 3-stage) ----------------
#define SQH 0
#define SQL 34816
#define SKH(s) (69632 + (s) * 34816)
#define SKL(s) (69632 + (s) * 34816 + 17408)
#define SGH(s) (174080 + (s) * 18432)
#define ATTN_SMEM 229376
#define KTILES 32

extern __shared__ char sm_a[];

__global__ void __launch_bounds__(256, 1) attn_kernel()
{
    const int b  = blockIdx.y;
    const int qt = blockIdx.x;
    const int z  = blockIdx.z;                 // key half
    const int tid = threadIdx.x;
    const int lane = tid & 31, warp = tid >> 5;
    const uint sb = smem_u32(sm_a);

    const size_t qbase = (size_t)(b * NN + qt * 128) * CI;
    const char* Qh_g = (const char*)(g_Qh + qbase);
    const char* Ql_g = (const char*)(g_Ql + qbase);
    const char* gh_g = (const char*)(g_Gth + (size_t)(b * CI) * NN);

    // stage loader: tile index kt -> stage s (0..2)
    auto load_stage = [&](int kt, int s) {
        const char* khs = (const char*)(g_Kh + (size_t)(b * NN + kt * 64) * CI);
        const char* kls = (const char*)(g_Kl + (size_t)(b * NN + kt * 64) * CI);
#pragma unroll
        for (int it = 0; it < 4; it++) {
            int u = tid + it * 256;
            int row = u >> 4, ch = u & 15;
            cpa16(sb + SKH(s) + row * 272 + ch * 16, khs + row * 256 + ch * 16);
            cpa16(sb + SKL(s) + row * 272 + ch * 16, kls + row * 256 + ch * 16);
        }
#pragma unroll
        for (int it = 0; it < 4; it++) {
            int u = tid + it * 256;
            int row = u >> 3, ch = u & 7;
            cpa16(sb + SGH(s) + row * 144 + ch * 16, gh_g + (size_t)row * NN * 2 + kt * 128 + ch * 16);
        }
    };

    // prologue: Q + stage0 in group0, stage1 in group1
#pragma unroll
    for (int it = 0; it < 8; it++) {
        int u = tid + it * 256;
        int row = u >> 4, ch = u & 15;
        cpa16(sb + SQH + row * 272 + ch * 16, Qh_g + row * 256 + ch * 16);
        cpa16(sb + SQL + row * 272 + ch * 16, Ql_g + row * 256 + ch * 16);
    }
    load_stage(z * KTILES + 0, 0);
    CP_COMMIT();
    load_stage(z * KTILES + 1, 1);
    CP_COMMIT();

    const int r0 = warp * 16 + (lane >> 2);
    float o[16][4];
#pragma unroll
    for (int d = 0; d < 16; d++)
#pragma unroll
        for (int c = 0; c < 4; c++) o[d][c] = 0.f;
    float l0 = 0.f, l1 = 0.f;

    // ldmatrix per-thread invariant offsets
    const uint qoff = (uint)(warp * 16 + (lane & 15)) * 272 + ((lane >> 4) << 4);
    const uint koff = (uint)((lane & 7) + ((lane >> 4) << 3)) * 272 + (((lane >> 3) & 1) << 4);
    const uint goff = (uint)((lane & 7) + ((lane >> 4) << 3)) * 144 + (((lane >> 3) & 1) << 4);

    int stage = 0;
    for (int t = 0; t < KTILES; t++) {
        CP_WAIT1();            // stage(t) data complete (this thread)
        __syncthreads();       // publish all threads' copies; all warps done reading stage(t+2)%3
        // prefetch tile t+2 into stage (t+2)%3 — overlaps the whole iteration
        int pst = stage + 2 >= 3 ? stage - 1 : stage + 2;
        if (t + 2 < KTILES) load_stage(z * KTILES + t + 2, pst);
        CP_COMMIT();

        const uint skh = sb + SKH(stage);
        const uint skl = sb + SKL(stage);
        const uint sgh = sb + SGH(stage);

        float acc[8][4];
#pragma unroll
        for (int nt = 0; nt < 8; nt++)
#pragma unroll
            for (int c = 0; c < 4; c++) acc[nt][c] = 0.f;

#pragma unroll
        for (int kt = 0; kt < 8; kt++) {
            uint ah0, ah1, ah2, ah3, al0, al1, al2, al3;
            LDSM4(ah0, ah1, ah2, ah3, sb + SQH + qoff + kt * 32);
            LDSM4(al0, al1, al2, al3, sb + SQL + qoff + kt * 32);
#pragma unroll
            for (int np = 0; np < 4; np++) {
                uint bh0, bh1, bh2, bh3, bl0, bl1, bl2, bl3;
                LDSM4(bh0, bh1, bh2, bh3, skh + koff + (uint)np * 16 * 272 + kt * 32);
                LDSM4(bl0, bl1, bl2, bl3, skl + koff + (uint)np * 16 * 272 + kt * 32);
                mma_bf(acc[2*np][0], acc[2*np][1], acc[2*np][2], acc[2*np][3],
                       ah0, ah1, ah2, ah3, bh0, bh1);
                mma_bf(acc[2*np][0], acc[2*np][1], acc[2*np][2], acc[2*np][3],
                       ah0, ah1, ah2, ah3, bl0, bl1);
                mma_bf(acc[2*np][0], acc[2*np][1], acc[2*np][2], acc[2*np][3],
                       al0, al1, al2, al3, bh0, bh1);
                mma_bf(acc[2*np+1][0], acc[2*np+1][1], acc[2*np+1][2], acc[2*np+1][3],
                       ah0, ah1, ah2, ah3, bh2, bh3);
                mma_bf(acc[2*np+1][0], acc[2*np+1][1], acc[2*np+1][2], acc[2*np+1][3],
                       ah0, ah1, ah2, ah3, bl2, bl3);
                mma_bf(acc[2*np+1][0], acc[2*np+1][1], acc[2*np+1][2], acc[2*np+1][3],
                       al0, al1, al2, al3, bh2, bh3);
            }
        }

        uint ph[8][2], pl[8][2];
#pragma unroll
        for (int nt = 0; nt < 8; nt++) {
            float p0 = __expf(acc[nt][0]);
            float p1 = __expf(acc[nt][1]);
            float p2 = __expf(acc[nt][2]);
            float p3 = __expf(acc[nt][3]);
            l0 += p0 + p1;
            l1 += p2 + p3;
            uint h01 = pack2(p0, p1);
            uint h23 = pack2(p2, p3);
            float e0 = p0 - __uint_as_float(h01 << 16);
            float e1 = p1 - __uint_as_float(h01 & 0xffff0000u);
            float e2 = p2 - __uint_as_float(h23 << 16);
            float e3 = p3 - __uint_as_float(h23 & 0xffff0000u);
            ph[nt][0] = h01; ph[nt][1] = h23;
            pl[nt][0] = pack2(e0, e1); pl[nt][1] = pack2(e2, e3);
        }

        // O += P_hi*G_hi + P_lo*G_hi
#pragma unroll
        for (int kt2 = 0; kt2 < 4; kt2++) {
            uint ah0 = ph[2 * kt2][0], ah1 = ph[2 * kt2][1];
            uint ah2 = ph[2 * kt2 + 1][0], ah3 = ph[2 * kt2 + 1][1];
            uint al0 = pl[2 * kt2][0], al1 = pl[2 * kt2][1];
            uint al2 = pl[2 * kt2 + 1][0], al3 = pl[2 * kt2 + 1][1];
#pragma unroll
            for (int dp = 0; dp < 8; dp++) {
                uint g0, g1, g2, g3;
                LDSM4(g0, g1, g2, g3, sgh + goff + (uint)dp * 16 * 144 + kt2 * 32);
                mma_bf(o[2*dp][0], o[2*dp][1], o[2*dp][2], o[2*dp][3],
                       ah0, ah1, ah2, ah3, g0, g1);
                mma_bf(o[2*dp][0], o[2*dp][1], o[2*dp][2], o[2*dp][3],
                       al0, al1, al2, al3, g0, g1);
                mma_bf(o[2*dp+1][0], o[2*dp+1][1], o[2*dp+1][2], o[2*dp+1][3],
                       ah0, ah1, ah2, ah3, g2, g3);
                mma_bf(o[2*dp+1][0], o[2*dp+1][1], o[2*dp+1][2], o[2*dp+1][3],
                       al0, al1, al2, al3, g2, g3);
            }
        }

        stage = (stage + 1 == 3) ? 0 : stage + 1;
    }

    // epilogue: quad-reduce l, write partial O + partial l
    l0 += __shfl_xor_sync(0xffffffffu, l0, 1);
    l0 += __shfl_xor_sync(0xffffffffu, l0, 2);
    l1 += __shfl_xor_sync(0xffffffffu, l1, 1);
    l1 += __shfl_xor_sync(0xffffffffu, l1, 2);

    float* obase = g_Op + ((size_t)(z * BB + b) * NN + qt * 128) * CI;
#pragma unroll
    for (int dn = 0; dn < 16; dn++) {
        int col = dn * 8 + (lane & 3) * 2;
        *(float2*)(obase + (size_t)r0 * CI + col) = make_float2(o[dn][0], o[dn][1]);
        *(float2*)(obase + (size_t)(r0 + 8) * CI + col) = make_float2(o[dn][2], o[dn][3]);
    }
    if ((lane & 3) == 0) {
        g_lp[(size_t)(z * BB + b) * NN + qt * 128 + r0] = l0;
        g_lp[(size_t)(z * BB + b) * NN + qt * 128 + r0 + 8] = l1;
    }
}

// ---------------- kernel 2b: combine key-halves, emit Y bf16 hi/lo ----------------
__global__ void __launch_bounds__(256) combine_kernel()
{
    const int idx = blockIdx.x * 256 + threadIdx.x;
    const int row = idx >> 5;
    const float l = g_lp[row] + g_lp[BB * NN + row];
    const float inv = 1.0f / l;
    float4 a = ((const float4*)g_Op)[idx];
    float4 c = ((const float4*)(g_Op + (size_t)BB * NN * CI))[idx];
    float y0 = (a.x + c.x) * inv, y1 = (a.y + c.y) * inv;
    float y2 = (a.z + c.z) * inv, y3 = (a.w + c.w) * inv;
    uint h01 = pack2(y0, y1), h23 = pack2(y2, y3);
    float e0 = y0 - __uint_as_float(h01 << 16);
    float e1 = y1 - __uint_as_float(h01 & 0xffff0000u);
    float e2 = y2 - __uint_as_float(h23 << 16);
    float e3 = y3 - __uint_as_float(h23 & 0xffff0000u);
    ((uint2*)g_Yh)[idx] = make_uint2(h01, h23);
    ((uint2*)g_Yl)[idx] = make_uint2(pack2(e0, e1), pack2(e2, e3));
}

// ---------------- kernel 3: mma wgemm (ldmatrix) ----------------
#define WG_YH 0
#define WG_YL 34816
#define WG_WH 69632
#define WG_WL 104448
#define WG_SMEM 139264

extern __shared__ char sm_w[];

__global__ void __launch_bounds__(256, 1) wgemm_kernel(const float* __restrict__ Wb)
{
    const int b  = blockIdx.z;
    const int oh = blockIdx.y;
    const int n0 = blockIdx.x * 128;
    const int tid = threadIdx.x;
    const int lane = tid & 31, warp = tid >> 5;
    const uint sb = smem_u32(sm_w);

    {
        const char* yh = (const char*)(g_Yh + (size_t)(b * NN + n0) * CI);
        const char* yl = (const char*)(g_Yl + (size_t)(b * NN + n0) * CI);
        const char* wh = (const char*)(g_Wwh + (size_t)(oh * 128) * CI);
        const char* wl = (const char*)(g_Wwl + (size_t)(oh * 128) * CI);
#pragma unroll
        for (int it = 0; it < 8; it++) {
            int u = tid + it * 256;
            int row = u >> 4, ch = u & 15;
            cpa16(sb + WG_YH + row * 272 + ch * 16, yh + (size_t)row * 256 + ch * 16);
            cpa16(sb + WG_YL + row * 272 + ch * 16, yl + (size_t)row * 256 + ch * 16);
            cpa16(sb + WG_WH + row * 272 + ch * 16, wh + (size_t)row * 256 + ch * 16);
            cpa16(sb + WG_WL + row * 272 + ch * 16, wl + (size_t)row * 256 + ch * 16);
        }
    }
    CP_COMMIT();
    CP_WAIT0();
    __syncthreads();

    const int r0 = warp * 16 + (lane >> 2);
    float acc[16][4];
#pragma unroll
    for (int i = 0; i < 16; i++)
#pragma unroll
        for (int c = 0; c < 4; c++) acc[i][c] = 0.f;

    const uint qoff = (uint)(warp * 16 + (lane & 15)) * 272 + ((lane >> 4) << 4);
    const uint koff = (uint)((lane & 7) + ((lane >> 4) << 3)) * 272 + (((lane >> 3) & 1) << 4);

#pragma unroll
    for (int kt = 0; kt < 8; kt++) {
        uint ah0, ah1, ah2, ah3, al0, al1, al2, al3;
        LDSM4(ah0, ah1, ah2, ah3, sb + WG_YH + qoff + kt * 32);
        LDSM4(al0, al1, al2, al3, sb + WG_YL + qoff + kt * 32);
#pragma unroll
        for (int op = 0; op < 8; op++) {
            uint bh0, bh1, bh2, bh3, bl0, bl1, bl2, bl3;
            LDSM4(bh0, bh1, bh2, bh3, sb + WG_WH + koff + (uint)op * 16 * 272 + kt * 32);
            LDSM4(bl0, bl1, bl2, bl3, sb + WG_WL + koff + (uint)op * 16 * 272 + kt * 32);
            mma_bf(acc[2*op][0], acc[2*op][1], acc[2*op][2], acc[2*op][3],
                   ah0, ah1, ah2, ah3, bh0, bh1);
            mma_bf(acc[2*op][0], acc[2*op][1], acc[2*op][2], acc[2*op][3],
                   ah0, ah1, ah2, ah3, bl0, bl1);
            mma_bf(acc[2*op][0], acc[2*op][1], acc[2*op][2], acc[2*op][3],
                   al0, al1, al2, al3, bh0, bh1);
            mma_bf(acc[2*op+1][0], acc[2*op+1][1], acc[2*op+1][2], acc[2*op+1][3],
                   ah0, ah1, ah2, ah3, bh2, bh3);
            mma_bf(acc[2*op+1][0], acc[2*op+1][1], acc[2*op+1][2], acc[2*op+1][3],
                   ah0, ah1, ah2, ah3, bl2, bl3);
            mma_bf(acc[2*op+1][0], acc[2*op+1][1], acc[2*op+1][2], acc[2*op+1][3],
                   al0, al1, al2, al3, bh2, bh3);
        }
    }

    float* wy = g_WY + (size_t)(b * NN + n0) * CC + oh * 128;
#pragma unroll
    for (int ot = 0; ot < 16; ot++) {
        int o = ot * 8 + (lane & 3) * 2;
        float b0 = Wb[oh * 128 + o], b1 = Wb[oh * 128 + o + 1];
        *(float2*)(wy + (size_t)r0 * CC + o) = make_float2(acc[ot][0] + b0, acc[ot][1] + b1);
        *(float2*)(wy + (size_t)(r0 + 8) * CC + o) = make_float2(acc[ot][2] + b0, acc[ot][3] + b1);
    }
}

// ---------------- kernel 4a/4b: deterministic BN stats ----------------
__global__ void __launch_bounds__(256) stats1_kernel()
{
    const int blk = blockIdx.x;
    const int t = threadIdx.x;
    float s = 0.f, q = 0.f;
    const float* base = g_WY + (size_t)blk * 128 * CC + t;
    for (int r = 0; r < 128; r++) {
        float v = base[(size_t)r * CC];
        s += v; q += v * v;
    }
    g_psum[blk * CC + t] = s;
    g_psq [blk * CC + t] = q;
}
__global__ void __launch_bounds__(256) stats2_kernel()
{
    const int t = threadIdx.x;
    float s = 0.f, q = 0.f;
    for (int p = 0; p < 128; p++) {
        s += g_psum[p * CC + t];
        q += g_psq [p * CC + t];
    }
    const float invn = 1.0f / (float)(BB * NN);
    float mean = s * invn;
    float var  = q * invn - mean * mean;
    g_mean[t] = mean;
    g_rstd[t] = rsqrtf(var + BN_EPS);
}

// ---------------- kernel 5: BN apply + scale + residual (with transpose) ----------------
__global__ void __launch_bounds__(256) apply_kernel(
    const float* __restrict__ x,
    const float* __restrict__ gamma, const float* __restrict__ beta,
    const float* __restrict__ scale, float* __restrict__ out)
{
    __shared__ float st[64 * 65];
    const int n0 = blockIdx.x * 64;
    const int c0 = blockIdx.y * 64;
    const int b  = blockIdx.z;
    const int tid = threadIdx.x;
    const float s = scale[0];

#pragma unroll
    for (int r = 0; r < 16; r++) {
        int idx = tid + r * 256;
        int nl = idx >> 6, cc = idx & 63;
        st[cc * 65 + nl] = g_WY[((size_t)(b * NN + n0 + nl)) * CC + c0 + cc];
    }
    __syncthreads();
#pragma unroll
    for (int r = 0; r < 16; r++) {
        int idx = tid + r * 256;
        int cc = idx >> 6, nl = idx & 63;
        int c = c0 + cc;
        float wv = st[cc * 65 + nl];
        float v = s * ((wv - g_mean[c]) * g_rstd[c] * gamma[c] + beta[c])
                + x[((size_t)(b * CC + c)) * NN + n0 + nl];
        out[((size_t)(b * CC + c)) * NN + n0 + nl] = v;
    }
}

// ---------------- launcher ----------------
extern "C" void kernel_launch(void* const* d_in, const int* in_sizes, int n_in,
                              void* d_out, int out_size)
{
    const float* x     = (const float*)d_in[0];
    const float* gw    = (const float*)d_in[1];
    const float* gb    = (const float*)d_in[2];
    const float* tw    = (const float*)d_in[3];
    const float* tb    = (const float*)d_in[4];
    const float* pw    = (const float*)d_in[5];
    const float* pb    = (const float*)d_in[6];
    const float* Ww    = (const float*)d_in[7];
    const float* Wb    = (const float*)d_in[8];
    const float* gamma = (const float*)d_in[9];
    const float* beta  = (const float*)d_in[10];
    const float* scale = (const float*)d_in[11];
    float* out = (float*)d_out;

    cudaFuncSetAttribute(proj_kernel,
                         cudaFuncAttributeMaxDynamicSharedMemorySize, PROJ_SMEM);
    cudaFuncSetAttribute(attn_kernel,
                         cudaFuncAttributeMaxDynamicSharedMemorySize, ATTN_SMEM);
    cudaFuncSetAttribute(wgemm_kernel,
                         cudaFuncAttributeMaxDynamicSharedMemorySize, WG_SMEM);

    xcvt_kernel<<<dim3(NN / 64, CC / 64, BB), 256>>>(x);
    wcvt_kernel<<<64, 256>>>(gw, tw, pw, Ww);
    proj_kernel<<<dim3(NN / 128, BB, 3), 256, PROJ_SMEM>>>(gb, tb, pb);
    attn_kernel<<<dim3(NN / 128, BB, 2), 256, ATTN_SMEM>>>();
    combine_kernel<<<BB * NN * CI / 4 / 256, 256>>>();
    wgemm_kernel<<<dim3(NN / 128, 2, BB), 256, WG_SMEM>>>(Wb);
    stats1_kernel<<<128, 256>>>();
    stats2_kernel<<<1, 256>>>();
    apply_kernel<<<dim3(NN / 64, CC / 64, BB), 256>>>(x, gamma, beta, scale, out);
}

// round 11
// speedup vs baseline: 5.7162x; 1.1291x over previous
#include <cuda_runtime.h>

#define BB 4
#define CC 256
#define CI 128
#define NN 4096
#define BN_EPS 1e-5f

typedef unsigned int uint;
typedef unsigned short ushort;

// ---------------- scratch (no allocations allowed) ----------------
__device__ __align__(16) ushort g_Xh[BB * NN * CC];   // x^T hi [b][n][c]
__device__ __align__(16) ushort g_Xl[BB * NN * CC];
__device__ __align__(16) ushort g_PWh[3 * CI * CC];   // proj weights hi (g, theta, phi) [which][o][c]
__device__ __align__(16) ushort g_PWl[3 * CI * CC];
__device__ __align__(16) ushort g_Wwh[CC * CI];       // W conv weight hi [o][d]
__device__ __align__(16) ushort g_Wwl[CC * CI];
__device__ __align__(16) ushort g_Qh[BB * NN * CI];   // theta hi  [b][n][d]
__device__ __align__(16) ushort g_Ql[BB * NN * CI];
__device__ __align__(16) ushort g_Kh[BB * NN * CI];   // phi hi    [b][m][d]
__device__ __align__(16) ushort g_Kl[BB * NN * CI];
__device__ __align__(16) ushort g_Gth[BB * CI * NN];  // g^T hi    [b][d][m]
__device__ __align__(16) ushort g_Yh[BB * NN * CI];   // attention out hi [b][n][d]
__device__ __align__(16) ushort g_Yl[BB * NN * CI];
__device__ __align__(16) float g_WY[BB * NN * CC];    // W conv out [b][n][o]
__device__ __align__(16) float g_psum[128 * CC];
__device__ __align__(16) float g_psq [128 * CC];
__device__ float g_mean[CC];
__device__ float g_rstd[CC];

// ---------------- helpers ----------------
__device__ __forceinline__ ushort bf16rn(float v) {
    uint u = __float_as_uint(v);
    return (ushort)((u + 0x7FFFu + ((u >> 16) & 1u)) >> 16);
}
__device__ __forceinline__ uint smem_u32(const void* p) {
    uint a;
    asm("{ .reg .u64 t; cvta.to.shared.u64 t, %1; cvt.u32.u64 %0, t; }" : "=r"(a) : "l"(p));
    return a;
}
__device__ __forceinline__ void cpa16(uint s, const void* g) {
    asm volatile("cp.async.cg.shared.global [%0], [%1], 16;" :: "r"(s), "l"(g) : "memory");
}
#define CP_COMMIT() asm volatile("cp.async.commit_group;" ::: "memory")
#define CP_WAIT0()  asm volatile("cp.async.wait_group 0;" ::: "memory")
#define CP_WAIT1()  asm volatile("cp.async.wait_group 1;" ::: "memory")

#define LDSM4(r0, r1, r2, r3, addr) \
    asm volatile("ldmatrix.sync.aligned.m8n8.x4.shared.b16 {%0,%1,%2,%3}, [%4];" \
        : "=r"(r0), "=r"(r1), "=r"(r2), "=r"(r3) : "r"(addr))

// pack2(lo, hi): bf16x2 with lo in low half
__device__ __forceinline__ uint pack2(float lo, float hi) {
    uint r;
    asm("cvt.rn.bf16x2.f32 %0, %1, %2;" : "=r"(r) : "f"(hi), "f"(lo));
    return r;
}
__device__ __forceinline__ void mma_bf(float& d0, float& d1, float& d2, float& d3,
                                       uint a0, uint a1, uint a2, uint a3,
                                       uint b0, uint b1) {
    asm volatile("mma.sync.aligned.m16n8k16.row.col.f32.bf16.bf16.f32 "
        "{%0,%1,%2,%3},{%4,%5,%6,%7},{%8,%9},{%0,%1,%2,%3};"
        : "+f"(d0), "+f"(d1), "+f"(d2), "+f"(d3)
        : "r"(a0), "r"(a1), "r"(a2), "r"(a3), "r"(b0), "r"(b1));
}

// ---------------- kernel 0a: transpose + split x -> bf16 hi/lo [b][n][c] ----------------
__global__ void __launch_bounds__(256) xcvt_kernel(const float* __restrict__ x)
{
    __shared__ float st[64 * 65];
    const int n0 = blockIdx.x * 64;
    const int c0 = blockIdx.y * 64;
    const int b  = blockIdx.z;
    const int tid = threadIdx.x;
#pragma unroll
    for (int r = 0; r < 16; r++) {
        int idx = tid + r * 256;
        int cc = idx >> 6, nl = idx & 63;
        st[nl * 65 + cc] = x[((size_t)(b * CC + c0 + cc)) * NN + n0 + nl];
    }
    __syncthreads();
#pragma unroll
    for (int r = 0; r < 16; r++) {
        int idx = tid + r * 256;
        int nl = idx >> 6, cc = idx & 63;
        float v = st[nl * 65 + cc];
        ushort h = bf16rn(v);
        ushort l = bf16rn(v - __uint_as_float(((uint)h) << 16));
        size_t o = ((size_t)(b * NN + n0 + nl)) * CC + c0 + cc;
        g_Xh[o] = h;
        g_Xl[o] = l;
    }
}

// ---------------- kernel 0b: split weights -> bf16 hi/lo ----------------
__global__ void __launch_bounds__(256) wcvt_kernel(
    const float* __restrict__ gw, const float* __restrict__ tw,
    const float* __restrict__ pw, const float* __restrict__ Ww)
{
    const int total = 3 * CI * CC + CC * CI;
    for (int idx = blockIdx.x * 256 + threadIdx.x; idx < total; idx += gridDim.x * 256) {
        float v;
        if (idx < 3 * CI * CC) {
            int which = idx / (CI * CC), r = idx % (CI * CC);
            v = (which == 0 ? gw : which == 1 ? tw : pw)[r];
            ushort h = bf16rn(v);
            g_PWh[idx] = h;
            g_PWl[idx] = bf16rn(v - __uint_as_float(((uint)h) << 16));
        } else {
            int r = idx - 3 * CI * CC;
            v = Ww[r];
            ushort h = bf16rn(v);
            g_Wwh[r] = h;
            g_Wwl[r] = bf16rn(v - __uint_as_float(((uint)h) << 16));
        }
    }
}

// ---------------- kernel 1: mma projections ----------------
#define PJ_XH(buf) ((buf) * 73728)
#define PJ_XL(buf) ((buf) * 73728 + 18432)
#define PJ_WH(buf) ((buf) * 73728 + 36864)
#define PJ_WL(buf) ((buf) * 73728 + 55296)
#define PROJ_SMEM (2 * 73728)

extern __shared__ char sm_p[];

__global__ void __launch_bounds__(256, 1) proj_kernel(
    const float* __restrict__ gb_, const float* __restrict__ tb_,
    const float* __restrict__ pb_)
{
    const int b  = blockIdx.y;
    const int n0 = blockIdx.x * 128;
    const int which = blockIdx.z;              // 0=g->Gt(hi only), 1=theta->Q, 2=phi->K
    const int tid = threadIdx.x;
    const int lane = tid & 31, warp = tid >> 5;
    const uint sb = smem_u32(sm_p);
    const float* bias = (which == 0) ? gb_ : (which == 1) ? tb_ : pb_;

    const char* Xh_g = (const char*)(g_Xh + (size_t)(b * NN + n0) * CC);
    const char* Xl_g = (const char*)(g_Xl + (size_t)(b * NN + n0) * CC);
    const char* Wh_g = (const char*)(g_PWh + which * CI * CC);
    const char* Wl_g = (const char*)(g_PWl + which * CI * CC);

    auto load_chunk = [&](int ch) {
        if (ch < 4) {
            int buf = ch & 1;
            int cb = ch * 128;
#pragma unroll
            for (int it = 0; it < 4; it++) {
                int u = tid + it * 256;
                int row = u >> 3, seg = u & 7;
                cpa16(sb + PJ_XH(buf) + row * 144 + seg * 16, Xh_g + (size_t)row * 512 + cb + seg * 16);
                cpa16(sb + PJ_XL(buf) + row * 144 + seg * 16, Xl_g + (size_t)row * 512 + cb + seg * 16);
                cpa16(sb + PJ_WH(buf) + row * 144 + seg * 16, Wh_g + (size_t)row * 512 + cb + seg * 16);
                cpa16(sb + PJ_WL(buf) + row * 144 + seg * 16, Wl_g + (size_t)row * 512 + cb + seg * 16);
            }
        }
        CP_COMMIT();
    };

    load_chunk(0);
    load_chunk(1);

    const int r0 = warp * 16 + (lane >> 2);
    float acc[16][4];
#pragma unroll
    for (int i = 0; i < 16; i++)
#pragma unroll
        for (int c = 0; c < 4; c++) acc[i][c] = 0.f;

    const uint qoff144 = (uint)(warp * 16 + (lane & 15)) * 144 + ((lane >> 4) << 4);
    const uint koff144 = (uint)((lane & 7) + ((lane >> 4) << 3)) * 144 + (((lane >> 3) & 1) << 4);

    for (int ch = 0; ch < 4; ch++) {
        CP_WAIT1();
        __syncthreads();
        int buf = ch & 1;
#pragma unroll
        for (int kt = 0; kt < 4; kt++) {
            uint ah0, ah1, ah2, ah3, al0, al1, al2, al3;
            LDSM4(ah0, ah1, ah2, ah3, sb + PJ_XH(buf) + qoff144 + kt * 32);
            LDSM4(al0, al1, al2, al3, sb + PJ_XL(buf) + qoff144 + kt * 32);
#pragma unroll
            for (int op = 0; op < 8; op++) {
                uint bh0, bh1, bh2, bh3, bl0, bl1, bl2, bl3;
                LDSM4(bh0, bh1, bh2, bh3, sb + PJ_WH(buf) + koff144 + (uint)op * 16 * 144 + kt * 32);
                LDSM4(bl0, bl1, bl2, bl3, sb + PJ_WL(buf) + koff144 + (uint)op * 16 * 144 + kt * 32);
                mma_bf(acc[2*op][0], acc[2*op][1], acc[2*op][2], acc[2*op][3],
                       ah0, ah1, ah2, ah3, bh0, bh1);
                mma_bf(acc[2*op][0], acc[2*op][1], acc[2*op][2], acc[2*op][3],
                       ah0, ah1, ah2, ah3, bl0, bl1);
                mma_bf(acc[2*op][0], acc[2*op][1], acc[2*op][2], acc[2*op][3],
                       al0, al1, al2, al3, bh0, bh1);
                mma_bf(acc[2*op+1][0], acc[2*op+1][1], acc[2*op+1][2], acc[2*op+1][3],
                       ah0, ah1, ah2, ah3, bh2, bh3);
                mma_bf(acc[2*op+1][0], acc[2*op+1][1], acc[2*op+1][2], acc[2*op+1][3],
                       ah0, ah1, ah2, ah3, bl2, bl3);
                mma_bf(acc[2*op+1][0], acc[2*op+1][1], acc[2*op+1][2], acc[2*op+1][3],
                       al0, al1, al2, al3, bh2, bh3);
            }
        }
        __syncthreads();
        load_chunk(ch + 2);
    }
    CP_WAIT0();

#pragma unroll
    for (int ot = 0; ot < 16; ot++) {
        int o = ot * 8 + (lane & 3) * 2;
        float b0 = bias[o], b1 = bias[o + 1];
        acc[ot][0] += b0; acc[ot][1] += b1;
        acc[ot][2] += b0; acc[ot][3] += b1;
    }

    if (which != 0) {
        uint* dh = (uint*)((which == 1) ? g_Qh : g_Kh) + (size_t)(b * NN + n0) * (CI / 2);
        uint* dl = (uint*)((which == 1) ? g_Ql : g_Kl) + (size_t)(b * NN + n0) * (CI / 2);
#pragma unroll
        for (int ot = 0; ot < 16; ot++) {
            uint i0 = (uint)r0 * 64 + ot * 4 + (lane & 3);
            uint i1 = i0 + 8 * 64;
            uint h0 = pack2(acc[ot][0], acc[ot][1]);
            uint h1 = pack2(acc[ot][2], acc[ot][3]);
            float e0 = acc[ot][0] - __uint_as_float(h0 << 16);
            float e1 = acc[ot][1] - __uint_as_float(h0 & 0xffff0000u);
            float e2 = acc[ot][2] - __uint_as_float(h1 << 16);
            float e3 = acc[ot][3] - __uint_as_float(h1 & 0xffff0000u);
            dh[i0] = h0; dl[i0] = pack2(e0, e1);
            dh[i1] = h1; dl[i1] = pack2(e2, e3);
        }
    } else {
        ushort* st = (ushort*)sm_p;
        __syncthreads();
#pragma unroll
        for (int ot = 0; ot < 16; ot++) {
            int o = ot * 8 + (lane & 3) * 2;
#pragma unroll
            for (int c = 0; c < 4; c++) {
                int oo = o + (c & 1);
                int rr = (c < 2) ? r0 : (r0 + 8);
                st[oo * 136 + rr] = bf16rn(acc[ot][c]);
            }
        }
        __syncthreads();
#pragma unroll
        for (int it = 0; it < 8; it++) {
            int u = tid + it * 256;
            int o = u >> 4, seg = u & 15;
            *(uint4*)((char*)g_Gth + (((size_t)(b * CI + o)) * NN + n0) * 2 + seg * 16)
                = *(const uint4*)((const char*)st + o * 272 + seg * 16);
        }
    }
}

// ---------------- kernel 2: mma.sync flash attention (no split, ldmatrix, 3-stage) ----------------
#define SQH 0
#define SQL 34816
#define SKH(s) (69632 + (s) * 34816)
#define SKL(s) (69632 + (s) * 34816 + 17408)
#define SGH(s) (174080 + (s) * 18432)
#define ATTN_SMEM 229376
#define KTILES 64

extern __shared__ char sm_a[];

__global__ void __launch_bounds__(256, 1) attn_kernel()
{
    const int b  = blockIdx.y;
    const int qt = blockIdx.x;
    const int tid = threadIdx.x;
    const int lane = tid & 31, warp = tid >> 5;
    const uint sb = smem_u32(sm_a);

    const size_t qbase = (size_t)(b * NN + qt * 128) * CI;
    const char* Qh_g = (const char*)(g_Qh + qbase);
    const char* Ql_g = (const char*)(g_Ql + qbase);
    const char* gh_g = (const char*)(g_Gth + (size_t)(b * CI) * NN);

    auto load_stage = [&](int kt, int s) {
        const char* khs = (const char*)(g_Kh + (size_t)(b * NN + kt * 64) * CI);
        const char* kls = (const char*)(g_Kl + (size_t)(b * NN + kt * 64) * CI);
#pragma unroll
        for (int it = 0; it < 4; it++) {
            int u = tid + it * 256;
            int row = u >> 4, ch = u & 15;
            cpa16(sb + SKH(s) + row * 272 + ch * 16, khs + row * 256 + ch * 16);
            cpa16(sb + SKL(s) + row * 272 + ch * 16, kls + row * 256 + ch * 16);
        }
#pragma unroll
        for (int it = 0; it < 4; it++) {
            int u = tid + it * 256;
            int row = u >> 3, ch = u & 7;
            cpa16(sb + SGH(s) + row * 144 + ch * 16, gh_g + (size_t)row * NN * 2 + kt * 128 + ch * 16);
        }
    };

    // prologue: Q + stage0 in group0, stage1 in group1
#pragma unroll
    for (int it = 0; it < 8; it++) {
        int u = tid + it * 256;
        int row = u >> 4, ch = u & 15;
        cpa16(sb + SQH + row * 272 + ch * 16, Qh_g + row * 256 + ch * 16);
        cpa16(sb + SQL + row * 272 + ch * 16, Ql_g + row * 256 + ch * 16);
    }
    load_stage(0, 0);
    CP_COMMIT();
    load_stage(1, 1);
    CP_COMMIT();

    const int r0 = warp * 16 + (lane >> 2);
    float o[16][4];
#pragma unroll
    for (int d = 0; d < 16; d++)
#pragma unroll
        for (int c = 0; c < 4; c++) o[d][c] = 0.f;
    float l0 = 0.f, l1 = 0.f;

    const uint qoff = (uint)(warp * 16 + (lane & 15)) * 272 + ((lane >> 4) << 4);
    const uint koff = (uint)((lane & 7) + ((lane >> 4) << 3)) * 272 + (((lane >> 3) & 1) << 4);
    const uint goff = (uint)((lane & 7) + ((lane >> 4) << 3)) * 144 + (((lane >> 3) & 1) << 4);

    int stage = 0;
    for (int t = 0; t < KTILES; t++) {
        CP_WAIT1();
        __syncthreads();
        int pst = stage + 2 >= 3 ? stage - 1 : stage + 2;
        if (t + 2 < KTILES) load_stage(t + 2, pst);
        CP_COMMIT();

        const uint skh = sb + SKH(stage);
        const uint skl = sb + SKL(stage);
        const uint sgh = sb + SGH(stage);

        float acc[8][4];
#pragma unroll
        for (int nt = 0; nt < 8; nt++)
#pragma unroll
            for (int c = 0; c < 4; c++) acc[nt][c] = 0.f;

#pragma unroll
        for (int kt = 0; kt < 8; kt++) {
            uint ah0, ah1, ah2, ah3, al0, al1, al2, al3;
            LDSM4(ah0, ah1, ah2, ah3, sb + SQH + qoff + kt * 32);
            LDSM4(al0, al1, al2, al3, sb + SQL + qoff + kt * 32);
#pragma unroll
            for (int np = 0; np < 4; np++) {
                uint bh0, bh1, bh2, bh3, bl0, bl1, bl2, bl3;
                LDSM4(bh0, bh1, bh2, bh3, skh + koff + (uint)np * 16 * 272 + kt * 32);
                LDSM4(bl0, bl1, bl2, bl3, skl + koff + (uint)np * 16 * 272 + kt * 32);
                mma_bf(acc[2*np][0], acc[2*np][1], acc[2*np][2], acc[2*np][3],
                       ah0, ah1, ah2, ah3, bh0, bh1);
                mma_bf(acc[2*np][0], acc[2*np][1], acc[2*np][2], acc[2*np][3],
                       ah0, ah1, ah2, ah3, bl0, bl1);
                mma_bf(acc[2*np][0], acc[2*np][1], acc[2*np][2], acc[2*np][3],
                       al0, al1, al2, al3, bh0, bh1);
                mma_bf(acc[2*np+1][0], acc[2*np+1][1], acc[2*np+1][2], acc[2*np+1][3],
                       ah0, ah1, ah2, ah3, bh2, bh3);
                mma_bf(acc[2*np+1][0], acc[2*np+1][1], acc[2*np+1][2], acc[2*np+1][3],
                       ah0, ah1, ah2, ah3, bl2, bl3);
                mma_bf(acc[2*np+1][0], acc[2*np+1][1], acc[2*np+1][2], acc[2*np+1][3],
                       al0, al1, al2, al3, bh2, bh3);
            }
        }

        // softmax: exp, round to bf16; l sums the ROUNDED values so the
        // numerator (bf16 P) and denominator see identical weights.
        uint ph[8][2];
#pragma unroll
        for (int nt = 0; nt < 8; nt++) {
            float p0 = __expf(acc[nt][0]);
            float p1 = __expf(acc[nt][1]);
            float p2 = __expf(acc[nt][2]);
            float p3 = __expf(acc[nt][3]);
            uint h01 = pack2(p0, p1);
            uint h23 = pack2(p2, p3);
            l0 += __uint_as_float(h01 << 16) + __uint_as_float(h01 & 0xffff0000u);
            l1 += __uint_as_float(h23 << 16) + __uint_as_float(h23 & 0xffff0000u);
            ph[nt][0] = h01; ph[nt][1] = h23;
        }

        // O += P_hi * G_hi
#pragma unroll
        for (int kt2 = 0; kt2 < 4; kt2++) {
            uint ah0 = ph[2 * kt2][0], ah1 = ph[2 * kt2][1];
            uint ah2 = ph[2 * kt2 + 1][0], ah3 = ph[2 * kt2 + 1][1];
#pragma unroll
            for (int dp = 0; dp < 8; dp++) {
                uint g0, g1, g2, g3;
                LDSM4(g0, g1, g2, g3, sgh + goff + (uint)dp * 16 * 144 + kt2 * 32);
                mma_bf(o[2*dp][0], o[2*dp][1], o[2*dp][2], o[2*dp][3],
                       ah0, ah1, ah2, ah3, g0, g1);
                mma_bf(o[2*dp+1][0], o[2*dp+1][1], o[2*dp+1][2], o[2*dp+1][3],
                       ah0, ah1, ah2, ah3, g2, g3);
            }
        }

        stage = (stage + 1 == 3) ? 0 : stage + 1;
    }

    // epilogue: quad-reduce l, normalize, emit Y bf16 hi/lo directly
    l0 += __shfl_xor_sync(0xffffffffu, l0, 1);
    l0 += __shfl_xor_sync(0xffffffffu, l0, 2);
    l1 += __shfl_xor_sync(0xffffffffu, l1, 1);
    l1 += __shfl_xor_sync(0xffffffffu, l1, 2);
    const float inv0 = 1.0f / l0, inv1 = 1.0f / l1;

    const uint row0 = (uint)(qt * 128 + r0);
    uint* yh = (uint*)g_Yh + (size_t)b * NN * (CI / 2);
    uint* yl = (uint*)g_Yl + (size_t)b * NN * (CI / 2);
#pragma unroll
    for (int dn = 0; dn < 16; dn++) {
        uint i0 = row0 * 64 + dn * 4 + (lane & 3);
        uint i1 = i0 + 8 * 64;
        float v0 = o[dn][0] * inv0, v1 = o[dn][1] * inv0;
        float v2 = o[dn][2] * inv1, v3 = o[dn][3] * inv1;
        uint h0 = pack2(v0, v1), h1 = pack2(v2, v3);
        float e0 = v0 - __uint_as_float(h0 << 16);
        float e1 = v1 - __uint_as_float(h0 & 0xffff0000u);
        float e2 = v2 - __uint_as_float(h1 << 16);
        float e3 = v3 - __uint_as_float(h1 & 0xffff0000u);
        yh[i0] = h0; yl[i0] = pack2(e0, e1);
        yh[i1] = h1; yl[i1] = pack2(e2, e3);
    }
}

// ---------------- kernel 3: mma wgemm (ldmatrix) ----------------
#define WG_YH 0
#define WG_YL 34816
#define WG_WH 69632
#define WG_WL 104448
#define WG_SMEM 139264

extern __shared__ char sm_w[];

__global__ void __launch_bounds__(256, 1) wgemm_kernel(const float* __restrict__ Wb)
{
    const int b  = blockIdx.z;
    const int oh = blockIdx.y;
    const int n0 = blockIdx.x * 128;
    const int tid = threadIdx.x;
    const int lane = tid & 31, warp = tid >> 5;
    const uint sb = smem_u32(sm_w);

    {
        const char* yh = (const char*)(g_Yh + (size_t)(b * NN + n0) * CI);
        const char* yl = (const char*)(g_Yl + (size_t)(b * NN + n0) * CI);
        const char* wh = (const char*)(g_Wwh + (size_t)(oh * 128) * CI);
        const char* wl = (const char*)(g_Wwl + (size_t)(oh * 128) * CI);
#pragma unroll
        for (int it = 0; it < 8; it++) {
            int u = tid + it * 256;
            int row = u >> 4, ch = u & 15;
            cpa16(sb + WG_YH + row * 272 + ch * 16, yh + (size_t)row * 256 + ch * 16);
            cpa16(sb + WG_YL + row * 272 + ch * 16, yl + (size_t)row * 256 + ch * 16);
            cpa16(sb + WG_WH + row * 272 + ch * 16, wh + (size_t)row * 256 + ch * 16);
            cpa16(sb + WG_WL + row * 272 + ch * 16, wl + (size_t)row * 256 + ch * 16);
        }
    }
    CP_COMMIT();
    CP_WAIT0();
    __syncthreads();

    const int r0 = warp * 16 + (lane >> 2);
    float acc[16][4];
#pragma unroll
    for (int i = 0; i < 16; i++)
#pragma unroll
        for (int c = 0; c < 4; c++) acc[i][c] = 0.f;

    const uint qoff = (uint)(warp * 16 + (lane & 15)) * 272 + ((lane >> 4) << 4);
    const uint koff = (uint)((lane & 7) + ((lane >> 4) << 3)) * 272 + (((lane >> 3) & 1) << 4);

#pragma unroll
    for (int kt = 0; kt < 8; kt++) {
        uint ah0, ah1, ah2, ah3, al0, al1, al2, al3;
        LDSM4(ah0, ah1, ah2, ah3, sb + WG_YH + qoff + kt * 32);
        LDSM4(al0, al1, al2, al3, sb + WG_YL + qoff + kt * 32);
#pragma unroll
        for (int op = 0; op < 8; op++) {
            uint bh0, bh1, bh2, bh3, bl0, bl1, bl2, bl3;
            LDSM4(bh0, bh1, bh2, bh3, sb + WG_WH + koff + (uint)op * 16 * 272 + kt * 32);
            LDSM4(bl0, bl1, bl2, bl3, sb + WG_WL + koff + (uint)op * 16 * 272 + kt * 32);
            mma_bf(acc[2*op][0], acc[2*op][1], acc[2*op][2], acc[2*op][3],
                   ah0, ah1, ah2, ah3, bh0, bh1);
            mma_bf(acc[2*op][0], acc[2*op][1], acc[2*op][2], acc[2*op][3],
                   ah0, ah1, ah2, ah3, bl0, bl1);
            mma_bf(acc[2*op][0], acc[2*op][1], acc[2*op][2], acc[2*op][3],
                   al0, al1, al2, al3, bh0, bh1);
            mma_bf(acc[2*op+1][0], acc[2*op+1][1], acc[2*op+1][2], acc[2*op+1][3],
                   ah0, ah1, ah2, ah3, bh2, bh3);
            mma_bf(acc[2*op+1][0], acc[2*op+1][1], acc[2*op+1][2], acc[2*op+1][3],
                   ah0, ah1, ah2, ah3, bl2, bl3);
            mma_bf(acc[2*op+1][0], acc[2*op+1][1], acc[2*op+1][2], acc[2*op+1][3],
                   al0, al1, al2, al3, bh2, bh3);
        }
    }

    float* wy = g_WY + (size_t)(b * NN + n0) * CC + oh * 128;
#pragma unroll
    for (int ot = 0; ot < 16; ot++) {
        int o = ot * 8 + (lane & 3) * 2;
        float b0 = Wb[oh * 128 + o], b1 = Wb[oh * 128 + o + 1];
        *(float2*)(wy + (size_t)r0 * CC + o) = make_float2(acc[ot][0] + b0, acc[ot][1] + b1);
        *(float2*)(wy + (size_t)(r0 + 8) * CC + o) = make_float2(acc[ot][2] + b0, acc[ot][3] + b1);
    }
}

// ---------------- kernel 4a/4b: deterministic BN stats ----------------
__global__ void __launch_bounds__(256) stats1_kernel()
{
    const int blk = blockIdx.x;
    const int t = threadIdx.x;
    float s = 0.f, q = 0.f;
    const float* base = g_WY + (size_t)blk * 128 * CC + t;
    for (int r = 0; r < 128; r++) {
        float v = base[(size_t)r * CC];
        s += v; q += v * v;
    }
    g_psum[blk * CC + t] = s;
    g_psq [blk * CC + t] = q;
}
__global__ void __launch_bounds__(256) stats2_kernel()
{
    const int t = threadIdx.x;
    float s = 0.f, q = 0.f;
    for (int p = 0; p < 128; p++) {
        s += g_psum[p * CC + t];
        q += g_psq [p * CC + t];
    }
    const float invn = 1.0f / (float)(BB * NN);
    float mean = s * invn;
    float var  = q * invn - mean * mean;
    g_mean[t] = mean;
    g_rstd[t] = rsqrtf(var + BN_EPS);
}

// ---------------- kernel 5: BN apply + scale + residual (with transpose) ----------------
__global__ void __launch_bounds__(256) apply_kernel(
    const float* __restrict__ x,
    const float* __restrict__ gamma, const float* __restrict__ beta,
    const float* __restrict__ scale, float* __restrict__ out)
{
    __shared__ float st[64 * 65];
    const int n0 = blockIdx.x * 64;
    const int c0 = blockIdx.y * 64;
    const int b  = blockIdx.z;
    const int tid = threadIdx.x;
    const float s = scale[0];

#pragma unroll
    for (int r = 0; r < 16; r++) {
        int idx = tid + r * 256;
        int nl = idx >> 6, cc = idx & 63;
        st[cc * 65 + nl] = g_WY[((size_t)(b * NN + n0 + nl)) * CC + c0 + cc];
    }
    __syncthreads();
#pragma unroll
    for (int r = 0; r < 16; r++) {
        int idx = tid + r * 256;
        int cc = idx >> 6, nl = idx & 63;
        int c = c0 + cc;
        float wv = st[cc * 65 + nl];
        float v = s * ((wv - g_mean[c]) * g_rstd[c] * gamma[c] + beta[c])
                + x[((size_t)(b * CC + c)) * NN + n0 + nl];
        out[((size_t)(b * CC + c)) * NN + n0 + nl] = v;
    }
}

// ---------------- launcher ----------------
extern "C" void kernel_launch(void* const* d_in, const int* in_sizes, int n_in,
                              void* d_out, int out_size)
{
    const float* x     = (const float*)d_in[0];
    const float* gw    = (const float*)d_in[1];
    const float* gb    = (const float*)d_in[2];
    const float* tw    = (const float*)d_in[3];
    const float* tb    = (const float*)d_in[4];
    const float* pw    = (const float*)d_in[5];
    const float* pb    = (const float*)d_in[6];
    const float* Ww    = (const float*)d_in[7];
    const float* Wb    = (const float*)d_in[8];
    const float* gamma = (const float*)d_in[9];
    const float* beta  = (const float*)d_in[10];
    const float* scale = (const float*)d_in[11];
    float* out = (float*)d_out;

    cudaFuncSetAttribute(proj_kernel,
                         cudaFuncAttributeMaxDynamicSharedMemorySize, PROJ_SMEM);
    cudaFuncSetAttribute(attn_kernel,
                         cudaFuncAttributeMaxDynamicSharedMemorySize, ATTN_SMEM);
    cudaFuncSetAttribute(wgemm_kernel,
                         cudaFuncAttributeMaxDynamicSharedMemorySize, WG_SMEM);

    xcvt_kernel<<<dim3(NN / 64, CC / 64, BB), 256>>>(x);
    wcvt_kernel<<<64, 256>>>(gw, tw, pw, Ww);
    proj_kernel<<<dim3(NN / 128, BB, 3), 256, PROJ_SMEM>>>(gb, tb, pb);
    attn_kernel<<<dim3(NN / 128, BB), 256, ATTN_SMEM>>>();
    wgemm_kernel<<<dim3(NN / 128, 2, BB), 256, WG_SMEM>>>(Wb);
    stats1_kernel<<<128, 256>>>();
    stats2_kernel<<<1, 256>>>();
    apply_kernel<<<dim3(NN / 64, CC / 64, BB), 256>>>(x, gamma, beta, scale, out);
}